// round 1
// baseline (speedup 1.0000x reference)
#include <cuda_runtime.h>
#include <math.h>

#define NB   4
#define QN   900
#define DIM  256
#define HH   8
#define HD   32
#define PP   4
#define HBB  200
#define WBB  200
#define FFD  512
#define NQ   (NB*QN)        // 3600
#define NZ   (NB*HH)        // 32

// ---------------- device scratch (static, allocation-free) ----------------
__device__ float g_qk [NQ*DIM];
__device__ float g_qh [NQ*DIM];
__device__ float g_kh [NQ*DIM];
__device__ float g_vh [NQ*DIM];
__device__ float g_scores[(size_t)NZ*QN*QN];   // ~104 MB
__device__ float g_att [NQ*DIM];
__device__ float g_out1[NQ*DIM];
__device__ float g_out2[NQ*DIM];
__device__ float g_aug [NQ*DIM];
__device__ float g_offb[NQ*64];
__device__ float g_awl [NQ*32];
__device__ float g_agg [(size_t)NQ*HH*DIM];    // ~29.5 MB
__device__ float g_sumw[NQ*HH];
__device__ float g_ho  [NQ*DIM];
__device__ float g_out3[NQ*DIM];
__device__ float g_out4[NQ*DIM];
__device__ float g_ffn [NQ*FFD];
__device__ float g_out5[NQ*DIM];

// ---------------- elementwise add ----------------
__global__ void add_kernel(const float* __restrict__ A, const float* __restrict__ B,
                           float* __restrict__ C) {
    int i = blockIdx.x * blockDim.x + threadIdx.x;
    C[i] = A[i] + B[i];
}

// ---------------- generic tiled GEMM: C = A(MxK) @ W(KxN) + bias ----------------
// 64x64 tile, BK=16, 256 threads, 4x4 micro-tile. K must be a multiple of 16.
__global__ void gemm_kernel(const float* __restrict__ A, const float* __restrict__ W,
                            const float* __restrict__ bias, float* __restrict__ C,
                            int M, int N, int K, int relu,
                            const float* __restrict__ rowscale) {
    __shared__ float As[16][64];
    __shared__ float Bs[16][64];
    int bm = blockIdx.y * 64, bn = blockIdx.x * 64;
    int tid = threadIdx.x;
    int ty = tid >> 4, tx = tid & 15;
    float acc[4][4] = {};
    int aRow = tid >> 2, aCol = (tid & 3) << 2;
    int bCol = tid & 63, bRow = tid >> 6;
    for (int k0 = 0; k0 < K; k0 += 16) {
        int m = bm + aRow;
        #pragma unroll
        for (int i = 0; i < 4; i++)
            As[aCol + i][aRow] = (m < M) ? A[m * K + k0 + aCol + i] : 0.f;
        int n = bn + bCol;
        #pragma unroll
        for (int i = 0; i < 4; i++)
            Bs[bRow + i * 4][bCol] = (n < N) ? W[(k0 + bRow + i * 4) * N + n] : 0.f;
        __syncthreads();
        #pragma unroll
        for (int kk = 0; kk < 16; kk++) {
            float4 a4 = *(const float4*)&As[kk][ty * 4];
            float4 b4 = *(const float4*)&Bs[kk][tx * 4];
            float a[4] = {a4.x, a4.y, a4.z, a4.w};
            float b[4] = {b4.x, b4.y, b4.z, b4.w};
            #pragma unroll
            for (int i = 0; i < 4; i++)
                #pragma unroll
                for (int j = 0; j < 4; j++) acc[i][j] += a[i] * b[j];
        }
        __syncthreads();
    }
    #pragma unroll
    for (int i = 0; i < 4; i++) {
        int m = bm + ty * 4 + i; if (m >= M) continue;
        float rs = rowscale ? rowscale[m] : 1.f;
        #pragma unroll
        for (int j = 0; j < 4; j++) {
            int n = bn + tx * 4 + j; if (n >= N) continue;
            float v = acc[i][j] + (bias ? bias[n] : 0.f);
            if (relu) v = fmaxf(v, 0.f);
            C[m * N + n] = v * rs;
        }
    }
}

// ---------------- attention scores: S[z,q,k] = scale * qh.kh, masked ----------------
__global__ void scores_kernel(const float* __restrict__ mask) {
    int z = blockIdx.z, b = z >> 3, h = z & 7;
    int bq = blockIdx.y * 64, bk = blockIdx.x * 64;
    __shared__ float Qs[HD][68];
    __shared__ float Ks[HD][68];
    int tid = threadIdx.x;
    int r = tid >> 2, c0 = (tid & 3) * 8;
    #pragma unroll
    for (int i = 0; i < 8; i++) {
        int q = bq + r;
        Qs[c0 + i][r] = (q < QN) ? g_qh[(b * QN + q) * DIM + h * HD + c0 + i] : 0.f;
        int k = bk + r;
        Ks[c0 + i][r] = (k < QN) ? g_kh[(b * QN + k) * DIM + h * HD + c0 + i] : 0.f;
    }
    __syncthreads();
    int ty = tid >> 4, tx = tid & 15;
    float acc[4][4] = {};
    #pragma unroll
    for (int kk = 0; kk < HD; kk++) {
        float4 a4 = *(const float4*)&Qs[kk][ty * 4];
        float4 b4 = *(const float4*)&Ks[kk][tx * 4];
        float a[4] = {a4.x, a4.y, a4.z, a4.w};
        float b[4] = {b4.x, b4.y, b4.z, b4.w};
        #pragma unroll
        for (int i = 0; i < 4; i++)
            #pragma unroll
            for (int j = 0; j < 4; j++) acc[i][j] += a[i] * b[j];
    }
    const float scale = 0.17677669529663687f;  // 1/sqrt(32)
    #pragma unroll
    for (int j = 0; j < 4; j++) {
        int k = bk + tx * 4 + j; if (k >= QN) continue;
        float mv = mask[b * QN + k];
        #pragma unroll
        for (int i = 0; i < 4; i++) {
            int q = bq + ty * 4 + i; if (q >= QN) continue;
            g_scores[((size_t)(z * QN + q)) * QN + k] = (mv > 0.f) ? acc[i][j] * scale : -1e9f;
        }
    }
}

// ---------------- row softmax over 900 keys ----------------
__global__ void softmax_kernel() {
    int row = blockIdx.x;                 // 0..28799  ( (b*8+h)*900 + q )
    float* p = g_scores + (size_t)row * QN;
    int tid = threadIdx.x;
    __shared__ float red[8];
    float v[4];
    float mx = -3e38f;
    #pragma unroll
    for (int i = 0; i < 4; i++) {
        int k = tid + i * 256;
        if (k < QN) { v[i] = p[k]; mx = fmaxf(mx, v[i]); } else v[i] = 0.f;
    }
    for (int o = 16; o; o >>= 1) mx = fmaxf(mx, __shfl_xor_sync(0xffffffffu, mx, o));
    if ((tid & 31) == 0) red[tid >> 5] = mx;
    __syncthreads();
    float bm = red[0];
    #pragma unroll
    for (int i = 1; i < 8; i++) bm = fmaxf(bm, red[i]);
    __syncthreads();
    float sum = 0.f;
    #pragma unroll
    for (int i = 0; i < 4; i++) {
        int k = tid + i * 256;
        if (k < QN) { v[i] = __expf(v[i] - bm); sum += v[i]; }
    }
    for (int o = 16; o; o >>= 1) sum += __shfl_xor_sync(0xffffffffu, sum, o);
    if ((tid & 31) == 0) red[tid >> 5] = sum;
    __syncthreads();
    float ts = 0.f;
    #pragma unroll
    for (int i = 0; i < 8; i++) ts += red[i];
    float inv = 1.f / ts;
    #pragma unroll
    for (int i = 0; i < 4; i++) {
        int k = tid + i * 256;
        if (k < QN) p[k] = v[i] * inv;
    }
}

// ---------------- attn @ V : per (b,h), 900x32 = P(900x900) @ V(900x32) ----------------
__global__ void av_kernel() {
    int z = blockIdx.y, b = z >> 3, h = z & 7;
    int bq = blockIdx.x * 64;
    __shared__ float Ps[64][68];  // [k][q] transposed
    __shared__ float Vs[64][36];  // [k][d]
    int tid = threadIdx.x;        // 128
    int ty = tid >> 3, tx = tid & 7;
    float acc[4][4] = {};
    const size_t srow = (size_t)z * QN;
    for (int k0 = 0; k0 < QN; k0 += 64) {
        #pragma unroll
        for (int t = 0; t < 32; t++) {
            int idx = tid + 128 * t;
            int q = idx >> 6, k = idx & 63;
            float val = 0.f;
            if (bq + q < QN && k0 + k < QN)
                val = g_scores[(srow + bq + q) * QN + k0 + k];
            Ps[k][q] = val;
        }
        #pragma unroll
        for (int t = 0; t < 16; t++) {
            int idx = tid + 128 * t;
            int k = idx >> 5, d = idx & 31;
            Vs[k][d] = (k0 + k < QN) ? g_vh[(b * QN + k0 + k) * DIM + h * HD + d] : 0.f;
        }
        __syncthreads();
        #pragma unroll 16
        for (int kk = 0; kk < 64; kk++) {
            float4 a4 = *(const float4*)&Ps[kk][ty * 4];
            float4 b4 = *(const float4*)&Vs[kk][tx * 4];
            float a[4] = {a4.x, a4.y, a4.z, a4.w};
            float bb[4] = {b4.x, b4.y, b4.z, b4.w};
            #pragma unroll
            for (int i = 0; i < 4; i++)
                #pragma unroll
                for (int j = 0; j < 4; j++) acc[i][j] += a[i] * bb[j];
        }
        __syncthreads();
    }
    #pragma unroll
    for (int i = 0; i < 4; i++) {
        int q = bq + ty * 4 + i; if (q >= QN) continue;
        #pragma unroll
        for (int j = 0; j < 4; j++)
            g_att[(b * QN + q) * DIM + h * HD + tx * 4 + j] = acc[i][j];
    }
}

// ---------------- add + layernorm (256-d rows) ----------------
__global__ void add_ln_kernel(const float* __restrict__ A, const float* __restrict__ B,
                              const float* __restrict__ g, const float* __restrict__ beta,
                              float* __restrict__ out) {
    int row = blockIdx.x, tid = threadIdx.x;
    float x = A[row * DIM + tid] + B[row * DIM + tid];
    __shared__ float red1[8], red2[8];
    float s1 = x, s2 = x * x;
    for (int o = 16; o; o >>= 1) {
        s1 += __shfl_xor_sync(0xffffffffu, s1, o);
        s2 += __shfl_xor_sync(0xffffffffu, s2, o);
    }
    if ((tid & 31) == 0) { red1[tid >> 5] = s1; red2[tid >> 5] = s2; }
    __syncthreads();
    float t1 = 0.f, t2 = 0.f;
    #pragma unroll
    for (int i = 0; i < 8; i++) { t1 += red1[i]; t2 += red2[i]; }
    float mean = t1 * (1.f / DIM);
    float var = t2 * (1.f / DIM) - mean * mean;
    out[row * DIM + tid] = (x - mean) * rsqrtf(var + 1e-5f) * g[tid] + beta[tid];
}

// ---------------- deformable gather: agg[nq,h,:] = sum_{p,c} aw*w*valid * bev[idx,:] ----------------
// Projection is commuted past the (linear) bilinear sampling, so we only
// gather raw bev rows here; the 256x32 per-head projection is a separate GEMM.
__global__ void deform_kernel(const float* __restrict__ bev, const float* __restrict__ ref) {
    int h = blockIdx.x, q = blockIdx.y, n = blockIdx.z;
    int nq = n * QN + q;
    int tid = threadIdx.x;
    float rx = ref[nq * 2 + 0], ry = ref[nq * 2 + 1];
    const float* awl = g_awl + nq * 32 + h * PP;
    float l0 = awl[0], l1 = awl[1], l2 = awl[2], l3 = awl[3];
    float mm = fmaxf(fmaxf(l0, l1), fmaxf(l2, l3));
    float e0 = __expf(l0 - mm), e1 = __expf(l1 - mm), e2 = __expf(l2 - mm), e3 = __expf(l3 - mm);
    float es = 1.f / (e0 + e1 + e2 + e3);
    float aw[PP] = {e0 * es, e1 * es, e2 * es, e3 * es};
    const float* off = g_offb + nq * 64 + h * (PP * 2);
    int idxs[16]; float wts[16]; float sumw = 0.f;
    #pragma unroll
    for (int p = 0; p < PP; p++) {
        float x = rx * (float)WBB + off[p * 2 + 0] - 0.5f;  // OFFSET_SCALE=1
        float y = ry * (float)HBB + off[p * 2 + 1] - 0.5f;
        float x0f = floorf(x), y0f = floorf(y);
        float fx = x - x0f, fy = y - y0f;
        int x0 = (int)x0f, y0 = (int)y0f;
        #pragma unroll
        for (int c = 0; c < 4; c++) {
            int dx = c & 1, dy = c >> 1;
            int xc = x0 + dx, yc = y0 + dy;
            float w = (dx ? fx : 1.f - fx) * (dy ? fy : 1.f - fy);
            bool valid = (xc >= 0) & (xc < WBB) & (yc >= 0) & (yc < HBB);
            int xcc = min(max(xc, 0), WBB - 1);
            int ycc = min(max(yc, 0), HBB - 1);
            float wf = valid ? aw[p] * w : 0.f;
            idxs[p * 4 + c] = ycc * WBB + xcc;
            wts[p * 4 + c] = wf;
            sumw += wf;
        }
    }
    float acc = 0.f;
    const float* bevn = bev + (size_t)n * (HBB * WBB) * DIM;
    #pragma unroll
    for (int s = 0; s < 16; s++) {
        float w = wts[s];
        if (w != 0.f) acc += w * bevn[(size_t)idxs[s] * DIM + tid];  // coalesced over tid
    }
    g_agg[((size_t)nq * HH + h) * DIM + tid] = acc;
    if (tid == 0) g_sumw[nq * HH + h] = sumw;
}

// ---------------- per-head projection: ho[m, h*32+c] = agg[m,h,:] @ Wval[:,h*32+c] + bval*sumw ----------------
__global__ void headgemm_kernel(const float* __restrict__ Wval, const float* __restrict__ bval) {
    int h = blockIdx.y;
    int bm = blockIdx.x * 64;
    __shared__ float As[32][68];  // [k][r]
    __shared__ float Bs[32][36];  // [k][c]
    int tid = threadIdx.x;        // 128
    int ty = tid >> 3, tx = tid & 7;
    float acc[4][4] = {};
    for (int k0 = 0; k0 < DIM; k0 += 32) {
        #pragma unroll
        for (int t = 0; t < 16; t++) {
            int idx = tid + 128 * t;
            int r = idx >> 5, k = idx & 31;
            As[k][r] = (bm + r < NQ) ? g_agg[((size_t)(bm + r) * HH + h) * DIM + k0 + k] : 0.f;
        }
        #pragma unroll
        for (int t = 0; t < 8; t++) {
            int idx = tid + 128 * t;
            int k = idx >> 5, c = idx & 31;
            Bs[k][c] = Wval[(k0 + k) * DIM + h * HD + c];
        }
        __syncthreads();
        #pragma unroll
        for (int kk = 0; kk < 32; kk++) {
            float4 a4 = *(const float4*)&As[kk][ty * 4];
            float4 b4 = *(const float4*)&Bs[kk][tx * 4];
            float a[4] = {a4.x, a4.y, a4.z, a4.w};
            float bb[4] = {b4.x, b4.y, b4.z, b4.w};
            #pragma unroll
            for (int i = 0; i < 4; i++)
                #pragma unroll
                for (int j = 0; j < 4; j++) acc[i][j] += a[i] * bb[j];
        }
        __syncthreads();
    }
    #pragma unroll
    for (int i = 0; i < 4; i++) {
        int m = bm + ty * 4 + i; if (m >= NQ) continue;
        float sw = g_sumw[m * HH + h];
        #pragma unroll
        for (int j = 0; j < 4; j++) {
            int c = tx * 4 + j;
            g_ho[m * DIM + h * HD + c] = acc[i][j] + bval[h * HD + c] * sw;
        }
    }
}

// ---------------- launch ----------------
static float* symaddr(const void* s) {
    void* p = nullptr;
    cudaGetSymbolAddress(&p, s);
    return (float*)p;
}

extern "C" void kernel_launch(void* const* d_in, const int* in_sizes, int n_in,
                              void* d_out, int out_size) {
    const float* queries = (const float*)d_in[0];
    const float* bev     = (const float*)d_in[1];
    const float* refp    = (const float*)d_in[2];
    const float* og      = (const float*)d_in[3];
    const float* mask    = (const float*)d_in[4];
    const float* Wq = (const float*)d_in[5];  const float* bq = (const float*)d_in[6];
    const float* Wk = (const float*)d_in[7];  const float* bk = (const float*)d_in[8];
    const float* Wv = (const float*)d_in[9];  const float* bv = (const float*)d_in[10];
    const float* Wo = (const float*)d_in[11]; const float* bo = (const float*)d_in[12];
    const float* ln1g = (const float*)d_in[13]; const float* ln1b = (const float*)d_in[14];
    const float* Wval = (const float*)d_in[15]; const float* bval = (const float*)d_in[16];
    const float* Woff = (const float*)d_in[17]; const float* boff = (const float*)d_in[18];
    const float* Wattn = (const float*)d_in[19]; const float* battn = (const float*)d_in[20];
    const float* Wdo = (const float*)d_in[21]; const float* bdo = (const float*)d_in[22];
    const float* ln2g = (const float*)d_in[23]; const float* ln2b = (const float*)d_in[24];
    const float* W1 = (const float*)d_in[25]; const float* b1 = (const float*)d_in[26];
    const float* W2 = (const float*)d_in[27]; const float* b2 = (const float*)d_in[28];
    const float* ln3g = (const float*)d_in[29]; const float* ln3b = (const float*)d_in[30];
    float* out = (float*)d_out;

    float* pqk  = symaddr(g_qk);
    float* pqh  = symaddr(g_qh);
    float* pkh  = symaddr(g_kh);
    float* pvh  = symaddr(g_vh);
    float* patt = symaddr(g_att);
    float* pout1 = symaddr(g_out1);
    float* pout2 = symaddr(g_out2);
    float* paug = symaddr(g_aug);
    float* poff = symaddr(g_offb);
    float* pawl = symaddr(g_awl);
    float* pho  = symaddr(g_ho);
    float* pout3 = symaddr(g_out3);
    float* pout4 = symaddr(g_out4);
    float* pffn = symaddr(g_ffn);
    float* pout5 = symaddr(g_out5);

    // 1. q_and_k = queries + og
    add_kernel<<<NQ, 256>>>(queries, og, pqk);
    // 2. QKV projections
    gemm_kernel<<<dim3(4, 57), 256>>>(pqk, Wq, bq, pqh, NQ, DIM, DIM, 0, nullptr);
    gemm_kernel<<<dim3(4, 57), 256>>>(pqk, Wk, bk, pkh, NQ, DIM, DIM, 0, nullptr);
    gemm_kernel<<<dim3(4, 57), 256>>>(queries, Wv, bv, pvh, NQ, DIM, DIM, 0, nullptr);
    // 3. attention scores + softmax + AV
    scores_kernel<<<dim3(15, 15, NZ), 256>>>(mask);
    softmax_kernel<<<NZ * QN, 256>>>();
    av_kernel<<<dim3(15, NZ), 128>>>();
    // 4. output projection + LN1
    gemm_kernel<<<dim3(4, 57), 256>>>(patt, Wo, bo, pout1, NQ, DIM, DIM, 0, nullptr);
    add_ln_kernel<<<NQ, 256>>>(queries, pout1, ln1g, ln1b, pout2);
    // 5. deformable attention (projection commuted past sampling)
    add_kernel<<<NQ, 256>>>(pout2, og, paug);
    gemm_kernel<<<dim3(1, 57), 256>>>(paug, Woff, boff, poff, NQ, 64, DIM, 0, nullptr);
    gemm_kernel<<<dim3(1, 57), 256>>>(paug, Wattn, battn, pawl, NQ, 32, DIM, 0, nullptr);
    deform_kernel<<<dim3(HH, QN, NB), 256>>>(bev, refp);
    headgemm_kernel<<<dim3(57, HH), 128>>>(Wval, bval);
    gemm_kernel<<<dim3(4, 57), 256>>>(pho, Wdo, bdo, pout3, NQ, DIM, DIM, 0, mask);
    add_ln_kernel<<<NQ, 256>>>(pout2, pout3, ln2g, ln2b, pout4);
    // 6. FFN + LN3
    gemm_kernel<<<dim3(8, 57), 256>>>(pout4, W1, b1, pffn, NQ, FFD, DIM, 1, nullptr);
    gemm_kernel<<<dim3(4, 57), 256>>>(pffn, W2, b2, pout5, NQ, DIM, FFD, 0, nullptr);
    add_ln_kernel<<<NQ, 256>>>(pout4, pout5, ln3g, ln3b, out);
}

// round 2
// speedup vs baseline: 1.3916x; 1.3916x over previous
#include <cuda_runtime.h>
#include <math.h>

#define NB   4
#define QN   900
#define DIM  256
#define HH   8
#define HD   32
#define PP   4
#define HBB  200
#define WBB  200
#define FFD  512
#define NQ   (NB*QN)        // 3600
#define NZ   (NB*HH)        // 32

// ---------------- device scratch (static, allocation-free) ----------------
__device__ float g_qk [NQ*DIM];
__device__ float g_qh [NQ*DIM];
__device__ float g_kh [NQ*DIM];
__device__ float g_vh [NQ*DIM];
__device__ float g_att [NQ*DIM];
__device__ float g_out1[NQ*DIM];
__device__ float g_out2[NQ*DIM];
__device__ float g_aug [NQ*DIM];
__device__ float g_offb[NQ*64];
__device__ float g_awl [NQ*32];
__device__ float g_agg [(size_t)NQ*HH*DIM];    // ~29.5 MB
__device__ float g_sumw[NQ*HH];
__device__ float g_ho  [NQ*DIM];
__device__ float g_out3[NQ*DIM];
__device__ float g_out4[NQ*DIM];
__device__ float g_ffn [NQ*FFD];
__device__ float g_out5[NQ*DIM];

// ---------------- elementwise add ----------------
__global__ void add_kernel(const float* __restrict__ A, const float* __restrict__ B,
                           float* __restrict__ C) {
    int i = blockIdx.x * blockDim.x + threadIdx.x;
    C[i] = A[i] + B[i];
}

// ---------------- double-buffered tiled GEMM body: C = A(MxK) @ W(KxN) + bias ----
// 64x64 tile, BK=16, 256 threads, 4x4 micro-tile. K must be a multiple of 16.
__device__ __forceinline__ void gemm_db(const float* __restrict__ A,
                                        const float* __restrict__ W,
                                        const float* __restrict__ bias,
                                        float* __restrict__ C,
                                        int M, int N, int K, int relu,
                                        const float* __restrict__ rowscale,
                                        int bm, int bn) {
    __shared__ float As[2][16][68];
    __shared__ float Bs[2][16][68];
    int tid = threadIdx.x;
    int ty = tid >> 4, tx = tid & 15;
    int aRow = tid >> 2, aCol = (tid & 3) << 2;
    int bCol = tid & 63, bRow = tid >> 6;
    float acc[4][4] = {};

    // prefetch tile 0
    float4 aReg = make_float4(0.f, 0.f, 0.f, 0.f);
    float bReg[4] = {0.f, 0.f, 0.f, 0.f};
    {
        int m = bm + aRow;
        if (m < M) aReg = *(const float4*)&A[(size_t)m * K + aCol];
        int n = bn + bCol;
        if (n < N) {
            #pragma unroll
            for (int i = 0; i < 4; i++) bReg[i] = W[(size_t)(bRow + i * 4) * N + n];
        }
    }
    int buf = 0;
    As[0][aCol + 0][aRow] = aReg.x; As[0][aCol + 1][aRow] = aReg.y;
    As[0][aCol + 2][aRow] = aReg.z; As[0][aCol + 3][aRow] = aReg.w;
    #pragma unroll
    for (int i = 0; i < 4; i++) Bs[0][bRow + i * 4][bCol] = bReg[i];
    __syncthreads();

    for (int k0 = 16;; k0 += 16) {
        bool more = (k0 < K);
        if (more) {
            int m = bm + aRow;
            aReg = make_float4(0.f, 0.f, 0.f, 0.f);
            if (m < M) aReg = *(const float4*)&A[(size_t)m * K + k0 + aCol];
            int n = bn + bCol;
            if (n < N) {
                #pragma unroll
                for (int i = 0; i < 4; i++) bReg[i] = W[(size_t)(k0 + bRow + i * 4) * N + n];
            } else {
                bReg[0] = bReg[1] = bReg[2] = bReg[3] = 0.f;
            }
        }
        #pragma unroll
        for (int kk = 0; kk < 16; kk++) {
            float4 a4 = *(const float4*)&As[buf][kk][ty * 4];
            float4 b4 = *(const float4*)&Bs[buf][kk][tx * 4];
            float a[4] = {a4.x, a4.y, a4.z, a4.w};
            float b[4] = {b4.x, b4.y, b4.z, b4.w};
            #pragma unroll
            for (int i = 0; i < 4; i++)
                #pragma unroll
                for (int j = 0; j < 4; j++) acc[i][j] += a[i] * b[j];
        }
        if (!more) break;
        int nb2 = buf ^ 1;
        As[nb2][aCol + 0][aRow] = aReg.x; As[nb2][aCol + 1][aRow] = aReg.y;
        As[nb2][aCol + 2][aRow] = aReg.z; As[nb2][aCol + 3][aRow] = aReg.w;
        #pragma unroll
        for (int i = 0; i < 4; i++) Bs[nb2][bRow + i * 4][bCol] = bReg[i];
        __syncthreads();
        buf = nb2;
    }

    #pragma unroll
    for (int i = 0; i < 4; i++) {
        int m = bm + ty * 4 + i; if (m >= M) continue;
        float rs = rowscale ? rowscale[m] : 1.f;
        #pragma unroll
        for (int j = 0; j < 4; j++) {
            int n = bn + tx * 4 + j; if (n >= N) continue;
            float v = acc[i][j] + (bias ? bias[n] : 0.f);
            if (relu) v = fmaxf(v, 0.f);
            C[(size_t)m * N + n] = v * rs;
        }
    }
}

__global__ void gemm_kernel(const float* __restrict__ A, const float* __restrict__ W,
                            const float* __restrict__ bias, float* __restrict__ C,
                            int M, int N, int K, int relu,
                            const float* __restrict__ rowscale) {
    gemm_db(A, W, bias, C, M, N, K, relu, rowscale, blockIdx.y * 64, blockIdx.x * 64);
}

// merged QKV projection: z=0 -> qh, z=1 -> kh, z=2 -> vh
__global__ void qkv_kernel(const float* __restrict__ queries,
                           const float* __restrict__ Wq, const float* __restrict__ bq,
                           const float* __restrict__ Wk, const float* __restrict__ bk,
                           const float* __restrict__ Wv, const float* __restrict__ bv) {
    int z = blockIdx.z;
    const float* A = (z == 2) ? queries : g_qk;
    const float* W = (z == 0) ? Wq : (z == 1) ? Wk : Wv;
    const float* bias = (z == 0) ? bq : (z == 1) ? bk : bv;
    float* C = (z == 0) ? g_qh : (z == 1) ? g_kh : g_vh;
    gemm_db(A, W, bias, C, NQ, DIM, DIM, 0, nullptr, blockIdx.y * 64, blockIdx.x * 64);
}

// ---------------- flash attention: per (z, q-tile 64), online softmax ----------------
__global__ void flash_kernel(const float* __restrict__ mask) {
    int z = blockIdx.y, b = z >> 3, h = z & 7;
    int q0 = blockIdx.x * 64;
    __shared__ float Qs[32][68];
    __shared__ float Ks[32][68];
    __shared__ float Vs[64][36];
    __shared__ float PsT[64][68];
    __shared__ float Ms[64];
    int tid = threadIdx.x;
    int ty = tid >> 4, tx = tid & 15;

    // load Q tile (transposed: Qs[d][q])
    {
        int q = tid >> 2, d0 = (tid & 3) * 8;
        int gq = q0 + q;
        float4 v0 = make_float4(0.f, 0.f, 0.f, 0.f), v1 = v0;
        if (gq < QN) {
            const float* p = &g_qh[(size_t)(b * QN + gq) * DIM + h * HD + d0];
            v0 = *(const float4*)p; v1 = *(const float4*)(p + 4);
        }
        Qs[d0 + 0][q] = v0.x; Qs[d0 + 1][q] = v0.y; Qs[d0 + 2][q] = v0.z; Qs[d0 + 3][q] = v0.w;
        Qs[d0 + 4][q] = v1.x; Qs[d0 + 5][q] = v1.y; Qs[d0 + 6][q] = v1.z; Qs[d0 + 7][q] = v1.w;
    }

    float m_i[4], l_i[4], o[4][2];
    #pragma unroll
    for (int i = 0; i < 4; i++) {
        m_i[i] = -3.0e38f; l_i[i] = 0.f; o[i][0] = 0.f; o[i][1] = 0.f;
    }
    const float scale = 0.17677669529663687f;  // 1/sqrt(32)

    for (int k0 = 0; k0 < QN; k0 += 64) {
        // load K (transposed), V (direct), mask
        {
            int k = tid >> 2, d0 = (tid & 3) * 8;
            int gk = k0 + k;
            float4 v0 = make_float4(0.f, 0.f, 0.f, 0.f), v1 = v0, w0 = v0, w1 = v0;
            if (gk < QN) {
                const float* pk = &g_kh[(size_t)(b * QN + gk) * DIM + h * HD + d0];
                v0 = *(const float4*)pk; v1 = *(const float4*)(pk + 4);
                const float* pv = &g_vh[(size_t)(b * QN + gk) * DIM + h * HD + d0];
                w0 = *(const float4*)pv; w1 = *(const float4*)(pv + 4);
            }
            Ks[d0 + 0][k] = v0.x; Ks[d0 + 1][k] = v0.y; Ks[d0 + 2][k] = v0.z; Ks[d0 + 3][k] = v0.w;
            Ks[d0 + 4][k] = v1.x; Ks[d0 + 5][k] = v1.y; Ks[d0 + 6][k] = v1.z; Ks[d0 + 7][k] = v1.w;
            *(float4*)&Vs[k][d0] = w0;
            *(float4*)&Vs[k][d0 + 4] = w1;
            if (tid < 64) Ms[tid] = (k0 + tid < QN) ? mask[b * QN + k0 + tid] : 0.f;
        }
        __syncthreads();

        // S = Q @ K^T (64x64), each thread 4x4
        float s[4][4] = {};
        #pragma unroll
        for (int d = 0; d < 32; d++) {
            float4 a4 = *(const float4*)&Qs[d][ty * 4];
            float4 b4 = *(const float4*)&Ks[d][tx * 4];
            float a[4] = {a4.x, a4.y, a4.z, a4.w};
            float bb[4] = {b4.x, b4.y, b4.z, b4.w};
            #pragma unroll
            for (int i = 0; i < 4; i++)
                #pragma unroll
                for (int j = 0; j < 4; j++) s[i][j] += a[i] * bb[j];
        }

        // scale + mask + pad, per-row max (reduce across the 16 tx lanes)
        float rm[4];
        #pragma unroll
        for (int i = 0; i < 4; i++) {
            float r = -3.0e38f;
            #pragma unroll
            for (int j = 0; j < 4; j++) {
                int gk = k0 + tx * 4 + j;
                float val;
                if (gk >= QN) val = -1.0e30f;
                else if (Ms[tx * 4 + j] > 0.f) val = s[i][j] * scale;
                else val = -1.0e9f;
                s[i][j] = val;
                r = fmaxf(r, val);
            }
            #pragma unroll
            for (int off = 1; off < 16; off <<= 1)
                r = fmaxf(r, __shfl_xor_sync(0xffffffffu, r, off));
            rm[i] = r;
        }

        // online softmax update
        #pragma unroll
        for (int i = 0; i < 4; i++) {
            float mn = fmaxf(m_i[i], rm[i]);
            float f = __expf(m_i[i] - mn);
            float rs = 0.f;
            #pragma unroll
            for (int j = 0; j < 4; j++) {
                float p = __expf(s[i][j] - mn);
                s[i][j] = p;
                rs += p;
            }
            #pragma unroll
            for (int off = 1; off < 16; off <<= 1)
                rs += __shfl_xor_sync(0xffffffffu, rs, off);
            l_i[i] = l_i[i] * f + rs;
            m_i[i] = mn;
            o[i][0] *= f; o[i][1] *= f;
        }

        // store P transposed: PsT[k][q]
        #pragma unroll
        for (int i = 0; i < 4; i++)
            #pragma unroll
            for (int j = 0; j < 4; j++)
                PsT[tx * 4 + j][ty * 4 + i] = s[i][j];
        __syncthreads();

        // O += P @ V : thread covers rows ty*4..+3, cols tx*2..+1
        #pragma unroll 8
        for (int k = 0; k < 64; k++) {
            float4 a4 = *(const float4*)&PsT[k][ty * 4];
            float2 b2 = *(const float2*)&Vs[k][tx * 2];
            o[0][0] += a4.x * b2.x; o[0][1] += a4.x * b2.y;
            o[1][0] += a4.y * b2.x; o[1][1] += a4.y * b2.y;
            o[2][0] += a4.z * b2.x; o[2][1] += a4.z * b2.y;
            o[3][0] += a4.w * b2.x; o[3][1] += a4.w * b2.y;
        }
        __syncthreads();
    }

    #pragma unroll
    for (int i = 0; i < 4; i++) {
        int q = q0 + ty * 4 + i;
        if (q < QN) {
            float inv = 1.f / l_i[i];
            float* p = &g_att[(size_t)(b * QN + q) * DIM + h * HD + tx * 2];
            p[0] = o[i][0] * inv;
            p[1] = o[i][1] * inv;
        }
    }
}

// ---------------- add + layernorm (256-d rows) ----------------
__global__ void add_ln_kernel(const float* __restrict__ A, const float* __restrict__ B,
                              const float* __restrict__ g, const float* __restrict__ beta,
                              float* __restrict__ out) {
    int row = blockIdx.x, tid = threadIdx.x;
    float x = A[row * DIM + tid] + B[row * DIM + tid];
    __shared__ float red1[8], red2[8];
    float s1 = x, s2 = x * x;
    for (int o = 16; o; o >>= 1) {
        s1 += __shfl_xor_sync(0xffffffffu, s1, o);
        s2 += __shfl_xor_sync(0xffffffffu, s2, o);
    }
    if ((tid & 31) == 0) { red1[tid >> 5] = s1; red2[tid >> 5] = s2; }
    __syncthreads();
    float t1 = 0.f, t2 = 0.f;
    #pragma unroll
    for (int i = 0; i < 8; i++) { t1 += red1[i]; t2 += red2[i]; }
    float mean = t1 * (1.f / DIM);
    float var = t2 * (1.f / DIM) - mean * mean;
    out[row * DIM + tid] = (x - mean) * rsqrtf(var + 1e-5f) * g[tid] + beta[tid];
}

// ---------------- deformable gather, all 8 heads per block ----------------
__global__ void deform_kernel(const float* __restrict__ bev, const float* __restrict__ ref) {
    int q = blockIdx.x, n = blockIdx.y;
    int nq = n * QN + q;
    __shared__ int sidx[128];
    __shared__ float swt[128];
    int tid = threadIdx.x;
    if (tid < 128) {
        int h = tid >> 4, s = tid & 15, p = s >> 2, c = s & 3;
        const float* awl = g_awl + nq * 32 + h * 4;
        float l0 = awl[0], l1 = awl[1], l2 = awl[2], l3 = awl[3];
        float mm = fmaxf(fmaxf(l0, l1), fmaxf(l2, l3));
        float e0 = __expf(l0 - mm), e1 = __expf(l1 - mm);
        float e2 = __expf(l2 - mm), e3 = __expf(l3 - mm);
        float es = 1.f / (e0 + e1 + e2 + e3);
        float awp = (p == 0 ? e0 : p == 1 ? e1 : p == 2 ? e2 : e3) * es;
        const float* off = g_offb + nq * 64 + h * 8;
        float x = ref[nq * 2 + 0] * (float)WBB + off[p * 2 + 0] - 0.5f;
        float y = ref[nq * 2 + 1] * (float)HBB + off[p * 2 + 1] - 0.5f;
        float x0f = floorf(x), y0f = floorf(y);
        float fx = x - x0f, fy = y - y0f;
        int dx = c & 1, dy = c >> 1;
        int xc = (int)x0f + dx, yc = (int)y0f + dy;
        float w = (dx ? fx : 1.f - fx) * (dy ? fy : 1.f - fy);
        bool valid = (xc >= 0) && (xc < WBB) && (yc >= 0) && (yc < HBB);
        float wf = valid ? awp * w : 0.f;
        int xcc = min(max(xc, 0), WBB - 1);
        int ycc = min(max(yc, 0), HBB - 1);
        sidx[tid] = ycc * WBB + xcc;
        swt[tid] = wf;
        float sw = wf;
        #pragma unroll
        for (int o = 1; o < 16; o <<= 1) sw += __shfl_xor_sync(0xffffffffu, sw, o);
        if (s == 0) g_sumw[nq * 8 + h] = sw;
    }
    __syncthreads();
    const float* bevn = bev + (size_t)n * (HBB * WBB) * DIM;
    #pragma unroll
    for (int h = 0; h < 8; h++) {
        float a = 0.f;
        #pragma unroll
        for (int s = 0; s < 16; s++) {
            float w = swt[h * 16 + s];
            if (w != 0.f) a += w * bevn[(size_t)sidx[h * 16 + s] * DIM + tid];
        }
        g_agg[((size_t)nq * HH + h) * DIM + tid] = a;
    }
}

// ---------------- per-head projection: ho[m, h*32+c] = agg[m,h,:] @ Wval[:,h*32+c] + bval*sumw
__global__ void headgemm_kernel(const float* __restrict__ Wval, const float* __restrict__ bval) {
    int h = blockIdx.y;
    int bm = blockIdx.x * 64;
    __shared__ float As[32][68];  // [k][r]
    __shared__ float Bs[32][36];  // [k][c]
    int tid = threadIdx.x;        // 128
    int ty = tid >> 3, tx = tid & 7;
    float acc[4][4] = {};
    for (int k0 = 0; k0 < DIM; k0 += 32) {
        #pragma unroll
        for (int t = 0; t < 16; t++) {
            int idx = tid + 128 * t;
            int r = idx >> 5, k = idx & 31;
            As[k][r] = (bm + r < NQ) ? g_agg[((size_t)(bm + r) * HH + h) * DIM + k0 + k] : 0.f;
        }
        #pragma unroll
        for (int t = 0; t < 8; t++) {
            int idx = tid + 128 * t;
            int k = idx >> 5, c = idx & 31;
            Bs[k][c] = Wval[(k0 + k) * DIM + h * HD + c];
        }
        __syncthreads();
        #pragma unroll
        for (int kk = 0; kk < 32; kk++) {
            float4 a4 = *(const float4*)&As[kk][ty * 4];
            float4 b4 = *(const float4*)&Bs[kk][tx * 4];
            float a[4] = {a4.x, a4.y, a4.z, a4.w};
            float bb[4] = {b4.x, b4.y, b4.z, b4.w};
            #pragma unroll
            for (int i = 0; i < 4; i++)
                #pragma unroll
                for (int j = 0; j < 4; j++) acc[i][j] += a[i] * bb[j];
        }
        __syncthreads();
    }
    #pragma unroll
    for (int i = 0; i < 4; i++) {
        int m = bm + ty * 4 + i; if (m >= NQ) continue;
        float sw = g_sumw[m * HH + h];
        #pragma unroll
        for (int j = 0; j < 4; j++) {
            int c = tx * 4 + j;
            g_ho[m * DIM + h * HD + c] = acc[i][j] + bval[h * HD + c] * sw;
        }
    }
}

// ---------------- launch ----------------
static float* symaddr(const void* s) {
    void* p = nullptr;
    cudaGetSymbolAddress(&p, s);
    return (float*)p;
}

extern "C" void kernel_launch(void* const* d_in, const int* in_sizes, int n_in,
                              void* d_out, int out_size) {
    const float* queries = (const float*)d_in[0];
    const float* bev     = (const float*)d_in[1];
    const float* refp    = (const float*)d_in[2];
    const float* og      = (const float*)d_in[3];
    const float* mask    = (const float*)d_in[4];
    const float* Wq = (const float*)d_in[5];  const float* bq = (const float*)d_in[6];
    const float* Wk = (const float*)d_in[7];  const float* bk = (const float*)d_in[8];
    const float* Wv = (const float*)d_in[9];  const float* bv = (const float*)d_in[10];
    const float* Wo = (const float*)d_in[11]; const float* bo = (const float*)d_in[12];
    const float* ln1g = (const float*)d_in[13]; const float* ln1b = (const float*)d_in[14];
    const float* Wval = (const float*)d_in[15]; const float* bval = (const float*)d_in[16];
    const float* Woff = (const float*)d_in[17]; const float* boff = (const float*)d_in[18];
    const float* Wattn = (const float*)d_in[19]; const float* battn = (const float*)d_in[20];
    const float* Wdo = (const float*)d_in[21]; const float* bdo = (const float*)d_in[22];
    const float* ln2g = (const float*)d_in[23]; const float* ln2b = (const float*)d_in[24];
    const float* W1 = (const float*)d_in[25]; const float* b1 = (const float*)d_in[26];
    const float* W2 = (const float*)d_in[27]; const float* b2 = (const float*)d_in[28];
    const float* ln3g = (const float*)d_in[29]; const float* ln3b = (const float*)d_in[30];
    float* out = (float*)d_out;

    float* pqk  = symaddr(g_qk);
    float* patt = symaddr(g_att);
    float* pout1 = symaddr(g_out1);
    float* pout2 = symaddr(g_out2);
    float* paug = symaddr(g_aug);
    float* poff = symaddr(g_offb);
    float* pawl = symaddr(g_awl);
    float* pho  = symaddr(g_ho);
    float* pout3 = symaddr(g_out3);
    float* pout4 = symaddr(g_out4);
    float* pffn = symaddr(g_ffn);
    float* pout5 = symaddr(g_out5);

    // 1. q_and_k = queries + og
    add_kernel<<<NQ, 256>>>(queries, og, pqk);
    // 2. fused QKV projections (one launch, 684 blocks)
    qkv_kernel<<<dim3(4, 57, 3), 256>>>(queries, Wq, bq, Wk, bk, Wv, bv);
    // 3. flash attention (scores+softmax+AV fused, no 104MB scratch)
    flash_kernel<<<dim3(15, NZ), 256>>>(mask);
    // 4. output projection + LN1
    gemm_kernel<<<dim3(4, 57), 256>>>(patt, Wo, bo, pout1, NQ, DIM, DIM, 0, nullptr);
    add_ln_kernel<<<NQ, 256>>>(queries, pout1, ln1g, ln1b, pout2);
    // 5. deformable attention (projection commuted past sampling)
    add_kernel<<<NQ, 256>>>(pout2, og, paug);
    gemm_kernel<<<dim3(1, 57), 256>>>(paug, Woff, boff, poff, NQ, 64, DIM, 0, nullptr);
    gemm_kernel<<<dim3(1, 57), 256>>>(paug, Wattn, battn, pawl, NQ, 32, DIM, 0, nullptr);
    deform_kernel<<<dim3(QN, NB), 256>>>(bev, refp);
    headgemm_kernel<<<dim3(57, HH), 128>>>(Wval, bval);
    gemm_kernel<<<dim3(4, 57), 256>>>(pho, Wdo, bdo, pout3, NQ, DIM, DIM, 0, mask);
    add_ln_kernel<<<NQ, 256>>>(pout2, pout3, ln2g, ln2b, pout4);
    // 6. FFN + LN3
    gemm_kernel<<<dim3(8, 57), 256>>>(pout4, W1, b1, pffn, NQ, FFD, DIM, 1, nullptr);
    gemm_kernel<<<dim3(4, 57), 256>>>(pffn, W2, b2, pout5, NQ, DIM, FFD, 0, nullptr);
    add_ln_kernel<<<NQ, 256>>>(pout4, pout5, ln3g, ln3b, out);
}

// round 5
// speedup vs baseline: 1.4953x; 1.0745x over previous
#include <cuda_runtime.h>
#include <math.h>

#define NB   4
#define QN   900
#define DIM  256
#define HH   8
#define HD   32
#define PP   4
#define HBB  200
#define WBB  200
#define FFD  512
#define NQ   (NB*QN)        // 3600
#define NZ   (NB*HH)        // 32

// ---------------- device scratch (static, allocation-free) ----------------
__device__ float g_qk [NQ*DIM];
__device__ float g_qh [NQ*DIM];
__device__ float g_kh [NQ*DIM];
__device__ float g_vh [NQ*DIM];
__device__ float g_att [NQ*DIM];
__device__ float g_out1[NQ*DIM];
__device__ float g_out2[NQ*DIM];
__device__ float g_aug [NQ*DIM];
__device__ float g_offb[NQ*64];
__device__ float g_awl [NQ*32];
__device__ float g_agg [(size_t)NQ*HH*DIM];    // ~29.5 MB
__device__ float g_sumw[NQ*HH];
__device__ float g_ho  [NQ*DIM];
__device__ float g_out3[NQ*DIM];
__device__ float g_out4[NQ*DIM];
__device__ float g_ffn [NQ*FFD];
__device__ float g_out5[NQ*DIM];

// ---------------- elementwise add ----------------
__global__ void add_kernel(const float* __restrict__ A, const float* __restrict__ B,
                           float* __restrict__ C) {
    int i = blockIdx.x * blockDim.x + threadIdx.x;
    C[i] = A[i] + B[i];
}

// ---------------- GEMM v3: 64x64 tile, BK=16, 128 threads, 8x4 micro ----------------
// C = A(MxK) @ W(KxN) + bias, optional relu, optional per-row scale.
// K multiple of 16, N multiple of 4.
__device__ __forceinline__ void gemm_v3(const float* __restrict__ A,
                                        const float* __restrict__ W,
                                        const float* __restrict__ bias,
                                        float* __restrict__ C,
                                        int M, int N, int K, int relu,
                                        const float* __restrict__ rowscale,
                                        int bm, int bn) {
    __shared__ float As[2][16][68];
    __shared__ float Bs[2][16][68];
    int tid = threadIdx.x;          // 128
    int ty = tid >> 4, tx = tid & 15;
    int am = tid & 63;              // A row within tile
    int ak = (tid >> 6) << 3;       // 0 or 8
    int br = tid >> 4;              // 0..7 (handles rows br, br+8)
    int bn4 = (tid & 15) << 2;
    float acc[8][4] = {};

    int m_a = bm + am;
    int n_b = bn + bn4;
    bool avalid = m_a < M;
    bool bvalid = n_b < N;
    const float* Arow = A + (size_t)m_a * K + ak;

    float4 a0 = make_float4(0.f,0.f,0.f,0.f), a1 = a0, b0 = a0, b1 = a0;
    if (avalid) { a0 = *(const float4*)(Arow); a1 = *(const float4*)(Arow + 4); }
    if (bvalid) {
        b0 = *(const float4*)&W[(size_t)br * N + n_b];
        b1 = *(const float4*)&W[(size_t)(br + 8) * N + n_b];
    }
    int buf = 0;
    {
        float av[8] = {a0.x,a0.y,a0.z,a0.w,a1.x,a1.y,a1.z,a1.w};
        #pragma unroll
        for (int i = 0; i < 8; i++) As[0][ak + i][am] = av[i];
        *(float4*)&Bs[0][br][bn4] = b0;
        *(float4*)&Bs[0][br + 8][bn4] = b1;
    }
    __syncthreads();

    for (int k0 = 16;; k0 += 16) {
        bool more = (k0 < K);
        if (more) {
            a0 = make_float4(0.f,0.f,0.f,0.f); a1 = a0; b0 = a0; b1 = a0;
            if (avalid) { a0 = *(const float4*)(Arow + k0); a1 = *(const float4*)(Arow + k0 + 4); }
            if (bvalid) {
                b0 = *(const float4*)&W[(size_t)(k0 + br) * N + n_b];
                b1 = *(const float4*)&W[(size_t)(k0 + br + 8) * N + n_b];
            }
        }
        #pragma unroll
        for (int kk = 0; kk < 16; kk++) {
            float4 x0 = *(const float4*)&As[buf][kk][ty * 8];
            float4 x1 = *(const float4*)&As[buf][kk][ty * 8 + 4];
            float4 y  = *(const float4*)&Bs[buf][kk][tx * 4];
            float a[8] = {x0.x,x0.y,x0.z,x0.w,x1.x,x1.y,x1.z,x1.w};
            float b[4] = {y.x,y.y,y.z,y.w};
            #pragma unroll
            for (int i = 0; i < 8; i++)
                #pragma unroll
                for (int j = 0; j < 4; j++) acc[i][j] += a[i] * b[j];
        }
        if (!more) break;
        buf ^= 1;
        {
            float av[8] = {a0.x,a0.y,a0.z,a0.w,a1.x,a1.y,a1.z,a1.w};
            #pragma unroll
            for (int i = 0; i < 8; i++) As[buf][ak + i][am] = av[i];
            *(float4*)&Bs[buf][br][bn4] = b0;
            *(float4*)&Bs[buf][br + 8][bn4] = b1;
        }
        __syncthreads();
    }

    int n = bn + tx * 4;
    if (n < N) {
        float4 bb = make_float4(0.f,0.f,0.f,0.f);
        if (bias) bb = *(const float4*)&bias[n];
        #pragma unroll
        for (int i = 0; i < 8; i++) {
            int m = bm + ty * 8 + i;
            if (m >= M) continue;
            float rs = rowscale ? rowscale[m] : 1.f;
            float4 o;
            o.x = acc[i][0] + bb.x; o.y = acc[i][1] + bb.y;
            o.z = acc[i][2] + bb.z; o.w = acc[i][3] + bb.w;
            if (relu) {
                o.x = fmaxf(o.x, 0.f); o.y = fmaxf(o.y, 0.f);
                o.z = fmaxf(o.z, 0.f); o.w = fmaxf(o.w, 0.f);
            }
            o.x *= rs; o.y *= rs; o.z *= rs; o.w *= rs;
            *(float4*)&C[(size_t)m * N + n] = o;
        }
    }
}

__global__ void gemm_kernel(const float* __restrict__ A, const float* __restrict__ W,
                            const float* __restrict__ bias, float* __restrict__ C,
                            int M, int N, int K, int relu,
                            const float* __restrict__ rowscale) {
    gemm_v3(A, W, bias, C, M, N, K, relu, rowscale, blockIdx.y * 64, blockIdx.x * 64);
}

// merged QKV projection: z=0 -> qh, z=1 -> kh, z=2 -> vh
__global__ void qkv_kernel(const float* __restrict__ queries,
                           const float* __restrict__ Wq, const float* __restrict__ bq,
                           const float* __restrict__ Wk, const float* __restrict__ bk,
                           const float* __restrict__ Wv, const float* __restrict__ bv) {
    int z = blockIdx.z;
    const float* A = (z == 2) ? queries : g_qk;
    const float* W = (z == 0) ? Wq : (z == 1) ? Wk : Wv;
    const float* bias = (z == 0) ? bq : (z == 1) ? bk : bv;
    float* C = (z == 0) ? g_qh : (z == 1) ? g_kh : g_vh;
    gemm_v3(A, W, bias, C, NQ, DIM, DIM, 0, nullptr, blockIdx.y * 64, blockIdx.x * 64);
}

// merged offset + attention-logit projections: z=0 -> offb (N=64), z=1 -> awl (N=32)
__global__ void offattn_kernel(const float* __restrict__ Woff, const float* __restrict__ boff,
                               const float* __restrict__ Wattn, const float* __restrict__ battn) {
    if (blockIdx.z == 0)
        gemm_v3(g_aug, Woff, boff, g_offb, NQ, 64, DIM, 0, nullptr, blockIdx.y * 64, 0);
    else
        gemm_v3(g_aug, Wattn, battn, g_awl, NQ, 32, DIM, 0, nullptr, blockIdx.y * 64, 0);
}

// ---------------- flash attention with K/V register prefetch ----------------
__global__ void flash_kernel(const float* __restrict__ mask) {
    int z = blockIdx.y, b = z >> 3, h = z & 7;
    int q0 = blockIdx.x * 64;
    __shared__ float Qs[32][68];
    __shared__ float Ks[32][68];
    __shared__ float Vs[64][36];
    __shared__ float PsT[64][68];
    __shared__ float Ms[64];
    int tid = threadIdx.x;
    int ty = tid >> 4, tx = tid & 15;
    int lk = tid >> 2, ld = (tid & 3) * 8;

    // load Q tile (transposed: Qs[d][q])
    {
        int gq = q0 + lk;
        float4 v0 = make_float4(0.f,0.f,0.f,0.f), v1 = v0;
        if (gq < QN) {
            const float* p = &g_qh[(size_t)(b * QN + gq) * DIM + h * HD + ld];
            v0 = *(const float4*)p; v1 = *(const float4*)(p + 4);
        }
        Qs[ld + 0][lk] = v0.x; Qs[ld + 1][lk] = v0.y; Qs[ld + 2][lk] = v0.z; Qs[ld + 3][lk] = v0.w;
        Qs[ld + 4][lk] = v1.x; Qs[ld + 5][lk] = v1.y; Qs[ld + 6][lk] = v1.z; Qs[ld + 7][lk] = v1.w;
    }

    float4 pk0, pk1, pv0, pv1;
    float pm = 0.f;
    auto LOADT = [&](int k0) {
        int gk = k0 + lk;
        pk0 = make_float4(0.f,0.f,0.f,0.f); pk1 = pk0; pv0 = pk0; pv1 = pk0;
        if (gk < QN) {
            const float* pk = &g_kh[(size_t)(b * QN + gk) * DIM + h * HD + ld];
            pk0 = *(const float4*)pk; pk1 = *(const float4*)(pk + 4);
            const float* pv = &g_vh[(size_t)(b * QN + gk) * DIM + h * HD + ld];
            pv0 = *(const float4*)pv; pv1 = *(const float4*)(pv + 4);
        }
        if (tid < 64) pm = (k0 + tid < QN) ? mask[b * QN + k0 + tid] : 0.f;
    };
    auto STORET = [&]() {
        Ks[ld + 0][lk] = pk0.x; Ks[ld + 1][lk] = pk0.y; Ks[ld + 2][lk] = pk0.z; Ks[ld + 3][lk] = pk0.w;
        Ks[ld + 4][lk] = pk1.x; Ks[ld + 5][lk] = pk1.y; Ks[ld + 6][lk] = pk1.z; Ks[ld + 7][lk] = pk1.w;
        *(float4*)&Vs[lk][ld] = pv0;
        *(float4*)&Vs[lk][ld + 4] = pv1;
        if (tid < 64) Ms[tid] = pm;
    };

    float m_i[4], l_i[4], o[4][2];
    #pragma unroll
    for (int i = 0; i < 4; i++) { m_i[i] = -3.0e38f; l_i[i] = 0.f; o[i][0] = 0.f; o[i][1] = 0.f; }
    const float scale = 0.17677669529663687f;  // 1/sqrt(32)

    LOADT(0); STORET(); __syncthreads();
    const int NT = (QN + 63) / 64;  // 15
    for (int t = 0; t < NT; t++) {
        int k0 = t * 64;
        bool more = (t + 1) < NT;
        if (more) LOADT(k0 + 64);   // overlaps with compute below

        // S = Q @ K^T (64x64), 4x4 per thread
        float s[4][4] = {};
        #pragma unroll
        for (int d = 0; d < 32; d++) {
            float4 a4 = *(const float4*)&Qs[d][ty * 4];
            float4 b4 = *(const float4*)&Ks[d][tx * 4];
            float a[4] = {a4.x, a4.y, a4.z, a4.w};
            float bb[4] = {b4.x, b4.y, b4.z, b4.w};
            #pragma unroll
            for (int i = 0; i < 4; i++)
                #pragma unroll
                for (int j = 0; j < 4; j++) s[i][j] += a[i] * bb[j];
        }

        // scale + mask + pad, per-row max (16 tx lanes)
        float rm[4];
        #pragma unroll
        for (int i = 0; i < 4; i++) {
            float r = -3.0e38f;
            #pragma unroll
            for (int j = 0; j < 4; j++) {
                int gk = k0 + tx * 4 + j;
                float val;
                if (gk >= QN) val = -1.0e30f;
                else if (Ms[tx * 4 + j] > 0.f) val = s[i][j] * scale;
                else val = -1.0e9f;
                s[i][j] = val;
                r = fmaxf(r, val);
            }
            #pragma unroll
            for (int off = 1; off < 16; off <<= 1)
                r = fmaxf(r, __shfl_xor_sync(0xffffffffu, r, off));
            rm[i] = r;
        }

        // online softmax update
        #pragma unroll
        for (int i = 0; i < 4; i++) {
            float mn = fmaxf(m_i[i], rm[i]);
            float f = __expf(m_i[i] - mn);
            float rs = 0.f;
            #pragma unroll
            for (int j = 0; j < 4; j++) {
                float p = __expf(s[i][j] - mn);
                s[i][j] = p;
                rs += p;
            }
            #pragma unroll
            for (int off = 1; off < 16; off <<= 1)
                rs += __shfl_xor_sync(0xffffffffu, rs, off);
            l_i[i] = l_i[i] * f + rs;
            m_i[i] = mn;
            o[i][0] *= f; o[i][1] *= f;
        }

        // store P transposed: PsT[k][q]
        #pragma unroll
        for (int i = 0; i < 4; i++)
            #pragma unroll
            for (int j = 0; j < 4; j++)
                PsT[tx * 4 + j][ty * 4 + i] = s[i][j];
        __syncthreads();

        // O += P @ V : rows ty*4..+3, cols tx*2..+1
        #pragma unroll 8
        for (int k = 0; k < 64; k++) {
            float4 a4 = *(const float4*)&PsT[k][ty * 4];
            float2 b2 = *(const float2*)&Vs[k][tx * 2];
            o[0][0] += a4.x * b2.x; o[0][1] += a4.x * b2.y;
            o[1][0] += a4.y * b2.x; o[1][1] += a4.y * b2.y;
            o[2][0] += a4.z * b2.x; o[2][1] += a4.z * b2.y;
            o[3][0] += a4.w * b2.x; o[3][1] += a4.w * b2.y;
        }
        __syncthreads();
        if (more) { STORET(); __syncthreads(); }
    }

    #pragma unroll
    for (int i = 0; i < 4; i++) {
        int q = q0 + ty * 4 + i;
        if (q < QN) {
            float inv = 1.f / l_i[i];
            float* p = &g_att[(size_t)(b * QN + q) * DIM + h * HD + tx * 2];
            p[0] = o[i][0] * inv;
            p[1] = o[i][1] * inv;
        }
    }
}

// ---------------- add + layernorm (256-d rows) ----------------
__global__ void add_ln_kernel(const float* __restrict__ A, const float* __restrict__ B,
                              const float* __restrict__ g, const float* __restrict__ beta,
                              float* __restrict__ out) {
    int row = blockIdx.x, tid = threadIdx.x;
    float x = A[row * DIM + tid] + B[row * DIM + tid];
    __shared__ float red1[8], red2[8];
    float s1 = x, s2 = x * x;
    for (int o = 16; o; o >>= 1) {
        s1 += __shfl_xor_sync(0xffffffffu, s1, o);
        s2 += __shfl_xor_sync(0xffffffffu, s2, o);
    }
    if ((tid & 31) == 0) { red1[tid >> 5] = s1; red2[tid >> 5] = s2; }
    __syncthreads();
    float t1 = 0.f, t2 = 0.f;
    #pragma unroll
    for (int i = 0; i < 8; i++) { t1 += red1[i]; t2 += red2[i]; }
    float mean = t1 * (1.f / DIM);
    float var = t2 * (1.f / DIM) - mean * mean;
    out[row * DIM + tid] = (x - mean) * rsqrtf(var + 1e-5f) * g[tid] + beta[tid];
}

// ---------------- deformable gather (float4, 2 heads per 64-lane group) ----------------
__global__ void deform_kernel(const float* __restrict__ bev, const float* __restrict__ ref) {
    int q = blockIdx.x, n = blockIdx.y;
    int nq = n * QN + q;
    __shared__ int sidx[128];
    __shared__ float swt[128];
    int tid = threadIdx.x;  // 256
    if (tid < 128) {
        int h = tid >> 4, s = tid & 15, p = s >> 2, c = s & 3;
        const float* awl = g_awl + nq * 32 + h * 4;
        float l0 = awl[0], l1 = awl[1], l2 = awl[2], l3 = awl[3];
        float mm = fmaxf(fmaxf(l0, l1), fmaxf(l2, l3));
        float e0 = __expf(l0 - mm), e1 = __expf(l1 - mm);
        float e2 = __expf(l2 - mm), e3 = __expf(l3 - mm);
        float es = 1.f / (e0 + e1 + e2 + e3);
        float awp = (p == 0 ? e0 : p == 1 ? e1 : p == 2 ? e2 : e3) * es;
        const float* off = g_offb + nq * 64 + h * 8;
        float x = ref[nq * 2 + 0] * (float)WBB + off[p * 2 + 0] - 0.5f;
        float y = ref[nq * 2 + 1] * (float)HBB + off[p * 2 + 1] - 0.5f;
        float x0f = floorf(x), y0f = floorf(y);
        float fx = x - x0f, fy = y - y0f;
        int dx = c & 1, dy = c >> 1;
        int xc = (int)x0f + dx, yc = (int)y0f + dy;
        float w = (dx ? fx : 1.f - fx) * (dy ? fy : 1.f - fy);
        bool valid = (xc >= 0) && (xc < WBB) && (yc >= 0) && (yc < HBB);
        float wf = valid ? awp * w : 0.f;
        int xcc = min(max(xc, 0), WBB - 1);
        int ycc = min(max(yc, 0), HBB - 1);
        sidx[tid] = ycc * WBB + xcc;
        swt[tid] = wf;
        float sw = wf;
        #pragma unroll
        for (int o = 1; o < 16; o <<= 1) sw += __shfl_xor_sync(0xffffffffu, sw, o);
        if (s == 0) g_sumw[nq * 8 + h] = sw;
    }
    __syncthreads();
    int sg = tid >> 6;            // 0..3 -> heads 2sg, 2sg+1
    int c4 = (tid & 63) << 2;     // channel base
    const float* bevn = bev + (size_t)n * (HBB * WBB) * DIM;
    #pragma unroll
    for (int hh2 = 0; hh2 < 2; hh2++) {
        int h = sg * 2 + hh2;
        float4 a = make_float4(0.f, 0.f, 0.f, 0.f);
        #pragma unroll
        for (int s = 0; s < 16; s++) {
            float w = swt[h * 16 + s];
            if (w != 0.f) {
                float4 gv = *(const float4*)&bevn[(size_t)sidx[h * 16 + s] * DIM + c4];
                a.x += w * gv.x; a.y += w * gv.y; a.z += w * gv.z; a.w += w * gv.w;
            }
        }
        *(float4*)&g_agg[((size_t)nq * HH + h) * DIM + c4] = a;
    }
}

// ---------------- per-head projection v2: 128x32 tile, 128 threads, 8x4 micro ----------------
__global__ void headgemm_kernel(const float* __restrict__ Wval, const float* __restrict__ bval) {
    int h = blockIdx.y;
    int bm = blockIdx.x * 128;
    __shared__ float As[2][16][132];
    __shared__ float Bs[2][16][36];
    int tid = threadIdx.x;  // 128
    int ty = tid >> 3, tx = tid & 7;
    float acc[8][4] = {};

    int m_a = bm + tid;
    bool avalid = m_a < NQ;
    const float* Arow = g_agg + ((size_t)m_a * HH + h) * DIM;
    int brr = tid >> 3;          // 0..15
    int bn4 = (tid & 7) * 4;
    const float* Wh = Wval + h * HD;

    float4 a0, a1, a2, a3, b0;
    auto LOADA = [&](int k0) {
        a0 = make_float4(0.f,0.f,0.f,0.f); a1 = a0; a2 = a0; a3 = a0;
        if (avalid) {
            a0 = *(const float4*)&Arow[k0];     a1 = *(const float4*)&Arow[k0 + 4];
            a2 = *(const float4*)&Arow[k0 + 8]; a3 = *(const float4*)&Arow[k0 + 12];
        }
    };
    auto LOADB = [&](int k0) {
        b0 = *(const float4*)&Wh[(size_t)(k0 + brr) * DIM + bn4];
    };
    auto STORE = [&](int buf) {
        float av[16] = {a0.x,a0.y,a0.z,a0.w,a1.x,a1.y,a1.z,a1.w,
                        a2.x,a2.y,a2.z,a2.w,a3.x,a3.y,a3.z,a3.w};
        #pragma unroll
        for (int i = 0; i < 16; i++) As[buf][i][tid] = av[i];
        *(float4*)&Bs[buf][brr][bn4] = b0;
    };

    LOADA(0); LOADB(0); STORE(0);
    __syncthreads();
    int buf = 0;
    for (int k0 = 16;; k0 += 16) {
        bool more = (k0 < DIM);
        if (more) { LOADA(k0); LOADB(k0); }
        #pragma unroll
        for (int kk = 0; kk < 16; kk++) {
            float4 x0 = *(const float4*)&As[buf][kk][ty * 8];
            float4 x1 = *(const float4*)&As[buf][kk][ty * 8 + 4];
            float4 y  = *(const float4*)&Bs[buf][kk][tx * 4];
            float a[8] = {x0.x,x0.y,x0.z,x0.w,x1.x,x1.y,x1.z,x1.w};
            float b[4] = {y.x,y.y,y.z,y.w};
            #pragma unroll
            for (int i = 0; i < 8; i++)
                #pragma unroll
                for (int j = 0; j < 4; j++) acc[i][j] += a[i] * b[j];
        }
        if (!more) break;
        buf ^= 1;
        STORE(buf);
        __syncthreads();
    }

    float4 bb = *(const float4*)&bval[h * HD + tx * 4];
    #pragma unroll
    for (int i = 0; i < 8; i++) {
        int m = bm + ty * 8 + i;
        if (m >= NQ) continue;
        float sw = g_sumw[m * HH + h];
        float4 o;
        o.x = acc[i][0] + bb.x * sw; o.y = acc[i][1] + bb.y * sw;
        o.z = acc[i][2] + bb.z * sw; o.w = acc[i][3] + bb.w * sw;
        *(float4*)&g_ho[(size_t)m * DIM + h * HD + tx * 4] = o;
    }
}

// ---------------- launch ----------------
static float* symaddr(const void* s) {
    void* p = nullptr;
    cudaGetSymbolAddress(&p, s);
    return (float*)p;
}

extern "C" void kernel_launch(void* const* d_in, const int* in_sizes, int n_in,
                              void* d_out, int out_size) {
    const float* queries = (const float*)d_in[0];
    const float* bev     = (const float*)d_in[1];
    const float* refp    = (const float*)d_in[2];
    const float* og      = (const float*)d_in[3];
    const float* mask    = (const float*)d_in[4];
    const float* Wq = (const float*)d_in[5];  const float* bq = (const float*)d_in[6];
    const float* Wk = (const float*)d_in[7];  const float* bk = (const float*)d_in[8];
    const float* Wv = (const float*)d_in[9];  const float* bv = (const float*)d_in[10];
    const float* Wo = (const float*)d_in[11]; const float* bo = (const float*)d_in[12];
    const float* ln1g = (const float*)d_in[13]; const float* ln1b = (const float*)d_in[14];
    const float* Wval = (const float*)d_in[15]; const float* bval = (const float*)d_in[16];
    const float* Woff = (const float*)d_in[17]; const float* boff = (const float*)d_in[18];
    const float* Wattn = (const float*)d_in[19]; const float* battn = (const float*)d_in[20];
    const float* Wdo = (const float*)d_in[21]; const float* bdo = (const float*)d_in[22];
    const float* ln2g = (const float*)d_in[23]; const float* ln2b = (const float*)d_in[24];
    const float* W1 = (const float*)d_in[25]; const float* b1 = (const float*)d_in[26];
    const float* W2 = (const float*)d_in[27]; const float* b2 = (const float*)d_in[28];
    const float* ln3g = (const float*)d_in[29]; const float* ln3b = (const float*)d_in[30];
    float* out = (float*)d_out;

    float* pqk  = symaddr(g_qk);
    float* patt = symaddr(g_att);
    float* pout1 = symaddr(g_out1);
    float* pout2 = symaddr(g_out2);
    float* paug = symaddr(g_aug);
    float* pho  = symaddr(g_ho);
    float* pout3 = symaddr(g_out3);
    float* pout4 = symaddr(g_out4);
    float* pffn = symaddr(g_ffn);
    float* pout5 = symaddr(g_out5);

    // 1. q_and_k = queries + og
    add_kernel<<<NQ, 256>>>(queries, og, pqk);
    // 2. fused QKV projections
    qkv_kernel<<<dim3(4, 57, 3), 128>>>(queries, Wq, bq, Wk, bk, Wv, bv);
    // 3. flash attention
    flash_kernel<<<dim3(15, NZ), 256>>>(mask);
    // 4. output projection + LN1
    gemm_kernel<<<dim3(4, 57), 128>>>(patt, Wo, bo, pout1, NQ, DIM, DIM, 0, nullptr);
    add_ln_kernel<<<NQ, 256>>>(queries, pout1, ln1g, ln1b, pout2);
    // 5. deformable attention (projection commuted past sampling)
    add_kernel<<<NQ, 256>>>(pout2, og, paug);
    offattn_kernel<<<dim3(1, 57, 2), 128>>>(Woff, boff, Wattn, battn);
    deform_kernel<<<dim3(QN, NB), 256>>>(bev, refp);
    headgemm_kernel<<<dim3(29, HH), 128>>>(Wval, bval);
    gemm_kernel<<<dim3(4, 57), 128>>>(pho, Wdo, bdo, pout3, NQ, DIM, DIM, 0, mask);
    add_ln_kernel<<<NQ, 256>>>(pout2, pout3, ln2g, ln2b, pout4);
    // 6. FFN + LN3
    gemm_kernel<<<dim3(8, 57), 128>>>(pout4, W1, b1, pffn, NQ, FFD, DIM, 1, nullptr);
    gemm_kernel<<<dim3(4, 57), 128>>>(pffn, W2, b2, pout5, NQ, DIM, FFD, 0, nullptr);
    add_ln_kernel<<<NQ, 256>>>(pout4, pout5, ln3g, ln3b, out);
}

// round 6
// speedup vs baseline: 1.7664x; 1.1813x over previous
#include <cuda_runtime.h>
#include <math.h>

#define NB   4
#define QN   900
#define DIM  256
#define HH   8
#define HD   32
#define PP   4
#define HBB  200
#define WBB  200
#define FFD  512
#define NQ   (NB*QN)        // 3600
#define NZ   (NB*HH)        // 32

// ---------------- device scratch (static, allocation-free) ----------------
__device__ float g_qk [NQ*DIM];
__device__ float g_qh [NQ*DIM];
__device__ float g_kh [NQ*DIM];
__device__ float g_vh [NQ*DIM];
__device__ float g_att [NQ*DIM];
__device__ float g_out1[NQ*DIM];
__device__ float g_out2[NQ*DIM];
__device__ float g_aug [NQ*DIM];
__device__ float g_offb[NQ*64];
__device__ float g_awl [NQ*32];
__device__ float g_agg [(size_t)NQ*HH*DIM];    // ~29.5 MB
__device__ float g_sumw[NQ*HH];
__device__ float g_ho  [NQ*DIM];
__device__ float g_out3[NQ*DIM];
__device__ float g_out4[NQ*DIM];
__device__ float g_ffn [NQ*FFD];
__device__ float g_out5[NQ*DIM];

// ---------------- elementwise add ----------------
__global__ void add_kernel(const float* __restrict__ A, const float* __restrict__ B,
                           float* __restrict__ C) {
    int i = blockIdx.x * blockDim.x + threadIdx.x;
    C[i] = A[i] + B[i];
}

// ================= tf32 tensor-core GEMM =================
// C = A(MxK) @ W(KxN) + bias [, relu][, rowscale]
// tile 64x64, BK=16, 128 threads = 4 warps in 2x2, warp tile 32x32.
// Requires: K % 16 == 0, N % 64 == 0, grid.x == N/64, A rows 16B-aligned.
__device__ __forceinline__ unsigned f2tf(float x) {
    unsigned r;
    asm("cvt.rna.tf32.f32 %0, %1;" : "=r"(r) : "f"(x));
    return r;
}
__device__ __forceinline__ void mma_tf32(float4& d,
                                         unsigned a0, unsigned a1, unsigned a2, unsigned a3,
                                         unsigned b0, unsigned b1) {
    asm volatile("mma.sync.aligned.m16n8k8.row.col.f32.tf32.tf32.f32 "
                 "{%0,%1,%2,%3}, {%4,%5,%6,%7}, {%8,%9}, {%0,%1,%2,%3};"
                 : "+f"(d.x), "+f"(d.y), "+f"(d.z), "+f"(d.w)
                 : "r"(a0), "r"(a1), "r"(a2), "r"(a3), "r"(b0), "r"(b1));
}

#define ASTR 20
#define BSTR 72

__device__ __forceinline__ void gemm_tf32(const float* __restrict__ A,
                                          const float* __restrict__ W,
                                          const float* __restrict__ bias,
                                          float* __restrict__ C,
                                          int M, int N, int K, int relu,
                                          const float* __restrict__ rowscale,
                                          int bm, int bn) {
    __shared__ unsigned As[2][64 * ASTR];
    __shared__ unsigned Bs[2][16 * BSTR];
    int tid = threadIdx.x;              // 128
    int warp = tid >> 5, lane = tid & 31;
    int wm = (warp & 1) * 32;
    int wn = (warp >> 1) * 32;
    int fr = lane >> 2, fc = lane & 3;  // fragment row/col ids
    float4 acc[2][4];
    #pragma unroll
    for (int i = 0; i < 2; i++)
        #pragma unroll
        for (int j = 0; j < 4; j++) acc[i][j] = make_float4(0.f, 0.f, 0.f, 0.f);

    // global load mapping
    int am = tid >> 1;                  // 0..63
    int ak = (tid & 1) * 8;             // 0 or 8
    bool avalid = (bm + am) < M;
    const float* Aptr = A + (size_t)(bm + am) * K + ak;
    int bk = tid >> 3;                  // 0..15
    int bnc = (tid & 7) * 8;
    const float* Wptr = W + (size_t)bk * N + bn + bnc;

    float4 xa0, xa1, yb0, yb1;
    auto LDG = [&](int k0) {
        xa0 = make_float4(0.f, 0.f, 0.f, 0.f); xa1 = xa0;
        if (avalid) { xa0 = *(const float4*)(Aptr + k0); xa1 = *(const float4*)(Aptr + k0 + 4); }
        yb0 = *(const float4*)(Wptr + (size_t)k0 * N);
        yb1 = *(const float4*)(Wptr + (size_t)k0 * N + 4);
    };
    auto STS = [&](int buf) {
        uint4 u0 = make_uint4(f2tf(xa0.x), f2tf(xa0.y), f2tf(xa0.z), f2tf(xa0.w));
        uint4 u1 = make_uint4(f2tf(xa1.x), f2tf(xa1.y), f2tf(xa1.z), f2tf(xa1.w));
        *(uint4*)&As[buf][am * ASTR + ak] = u0;
        *(uint4*)&As[buf][am * ASTR + ak + 4] = u1;
        uint4 v0 = make_uint4(f2tf(yb0.x), f2tf(yb0.y), f2tf(yb0.z), f2tf(yb0.w));
        uint4 v1 = make_uint4(f2tf(yb1.x), f2tf(yb1.y), f2tf(yb1.z), f2tf(yb1.w));
        *(uint4*)&Bs[buf][bk * BSTR + bnc] = v0;
        *(uint4*)&Bs[buf][bk * BSTR + bnc + 4] = v1;
    };

    LDG(0); STS(0);
    __syncthreads();
    int buf = 0;
    for (int k0 = 16;; k0 += 16) {
        bool more = (k0 < K);
        if (more) LDG(k0);
        #pragma unroll
        for (int ks = 0; ks < 16; ks += 8) {
            unsigned af[2][4];
            #pragma unroll
            for (int mi = 0; mi < 2; mi++) {
                const unsigned* ab = &As[buf][(wm + mi * 16) * ASTR + ks];
                af[mi][0] = ab[fr * ASTR + fc];
                af[mi][1] = ab[(fr + 8) * ASTR + fc];
                af[mi][2] = ab[fr * ASTR + fc + 4];
                af[mi][3] = ab[(fr + 8) * ASTR + fc + 4];
            }
            unsigned bf[4][2];
            #pragma unroll
            for (int ni = 0; ni < 4; ni++) {
                const unsigned* bb = &Bs[buf][ks * BSTR + wn + ni * 8 + fr];
                bf[ni][0] = bb[fc * BSTR];
                bf[ni][1] = bb[(fc + 4) * BSTR];
            }
            #pragma unroll
            for (int mi = 0; mi < 2; mi++)
                #pragma unroll
                for (int ni = 0; ni < 4; ni++)
                    mma_tf32(acc[mi][ni], af[mi][0], af[mi][1], af[mi][2], af[mi][3],
                             bf[ni][0], bf[ni][1]);
        }
        if (!more) break;
        buf ^= 1;
        STS(buf);
        __syncthreads();
    }

    // epilogue: each acc tile holds rows {r, r+8}, cols {2c, 2c+1}
    int c2 = fc * 2;
    #pragma unroll
    for (int ni = 0; ni < 4; ni++) {
        int n = bn + wn + ni * 8 + c2;
        float b0 = 0.f, b1 = 0.f;
        if (bias) { b0 = bias[n]; b1 = bias[n + 1]; }
        #pragma unroll
        for (int mi = 0; mi < 2; mi++) {
            float4 d = acc[mi][ni];
            int m0 = bm + wm + mi * 16 + fr;
            int m1 = m0 + 8;
            if (m0 < M) {
                float rs = rowscale ? rowscale[m0] : 1.f;
                float o0 = d.x + b0, o1 = d.y + b1;
                if (relu) { o0 = fmaxf(o0, 0.f); o1 = fmaxf(o1, 0.f); }
                *(float2*)&C[(size_t)m0 * N + n] = make_float2(o0 * rs, o1 * rs);
            }
            if (m1 < M) {
                float rs = rowscale ? rowscale[m1] : 1.f;
                float o0 = d.z + b0, o1 = d.w + b1;
                if (relu) { o0 = fmaxf(o0, 0.f); o1 = fmaxf(o1, 0.f); }
                *(float2*)&C[(size_t)m1 * N + n] = make_float2(o0 * rs, o1 * rs);
            }
        }
    }
}

__global__ void gemm_tf32_kernel(const float* __restrict__ A, const float* __restrict__ W,
                                 const float* __restrict__ bias, float* __restrict__ C,
                                 int M, int N, int K, int relu,
                                 const float* __restrict__ rowscale) {
    gemm_tf32(A, W, bias, C, M, N, K, relu, rowscale, blockIdx.y * 64, blockIdx.x * 64);
}

// merged QKV projection: z=0 -> qh, z=1 -> kh, z=2 -> vh (tensor cores)
__global__ void qkv_kernel(const float* __restrict__ queries,
                           const float* __restrict__ Wq, const float* __restrict__ bq,
                           const float* __restrict__ Wk, const float* __restrict__ bk,
                           const float* __restrict__ Wv, const float* __restrict__ bv) {
    int z = blockIdx.z;
    const float* A = (z == 2) ? queries : g_qk;
    const float* W = (z == 0) ? Wq : (z == 1) ? Wk : Wv;
    const float* bias = (z == 0) ? bq : (z == 1) ? bk : bv;
    float* C = (z == 0) ? g_qh : (z == 1) ? g_kh : g_vh;
    gemm_tf32(A, W, bias, C, NQ, DIM, DIM, 0, nullptr, blockIdx.y * 64, blockIdx.x * 64);
}

// ---------------- SIMT GEMM (kept for small-N projections) ----------------
__device__ __forceinline__ void gemm_v3(const float* __restrict__ A,
                                        const float* __restrict__ W,
                                        const float* __restrict__ bias,
                                        float* __restrict__ C,
                                        int M, int N, int K, int relu,
                                        const float* __restrict__ rowscale,
                                        int bm, int bn) {
    __shared__ float As[2][16][68];
    __shared__ float Bs[2][16][68];
    int tid = threadIdx.x;          // 128
    int ty = tid >> 4, tx = tid & 15;
    int am = tid & 63;
    int ak = (tid >> 6) << 3;
    int br = tid >> 4;
    int bn4 = (tid & 15) << 2;
    float acc[8][4] = {};

    int m_a = bm + am;
    int n_b = bn + bn4;
    bool avalid = m_a < M;
    bool bvalid = n_b < N;
    const float* Arow = A + (size_t)m_a * K + ak;

    float4 a0 = make_float4(0.f,0.f,0.f,0.f), a1 = a0, b0 = a0, b1 = a0;
    if (avalid) { a0 = *(const float4*)(Arow); a1 = *(const float4*)(Arow + 4); }
    if (bvalid) {
        b0 = *(const float4*)&W[(size_t)br * N + n_b];
        b1 = *(const float4*)&W[(size_t)(br + 8) * N + n_b];
    }
    int buf = 0;
    {
        float av[8] = {a0.x,a0.y,a0.z,a0.w,a1.x,a1.y,a1.z,a1.w};
        #pragma unroll
        for (int i = 0; i < 8; i++) As[0][ak + i][am] = av[i];
        *(float4*)&Bs[0][br][bn4] = b0;
        *(float4*)&Bs[0][br + 8][bn4] = b1;
    }
    __syncthreads();

    for (int k0 = 16;; k0 += 16) {
        bool more = (k0 < K);
        if (more) {
            a0 = make_float4(0.f,0.f,0.f,0.f); a1 = a0; b0 = a0; b1 = a0;
            if (avalid) { a0 = *(const float4*)(Arow + k0); a1 = *(const float4*)(Arow + k0 + 4); }
            if (bvalid) {
                b0 = *(const float4*)&W[(size_t)(k0 + br) * N + n_b];
                b1 = *(const float4*)&W[(size_t)(k0 + br + 8) * N + n_b];
            }
        }
        #pragma unroll
        for (int kk = 0; kk < 16; kk++) {
            float4 x0 = *(const float4*)&As[buf][kk][ty * 8];
            float4 x1 = *(const float4*)&As[buf][kk][ty * 8 + 4];
            float4 y  = *(const float4*)&Bs[buf][kk][tx * 4];
            float a[8] = {x0.x,x0.y,x0.z,x0.w,x1.x,x1.y,x1.z,x1.w};
            float b[4] = {y.x,y.y,y.z,y.w};
            #pragma unroll
            for (int i = 0; i < 8; i++)
                #pragma unroll
                for (int j = 0; j < 4; j++) acc[i][j] += a[i] * b[j];
        }
        if (!more) break;
        buf ^= 1;
        {
            float av[8] = {a0.x,a0.y,a0.z,a0.w,a1.x,a1.y,a1.z,a1.w};
            #pragma unroll
            for (int i = 0; i < 8; i++) As[buf][ak + i][am] = av[i];
            *(float4*)&Bs[buf][br][bn4] = b0;
            *(float4*)&Bs[buf][br + 8][bn4] = b1;
        }
        __syncthreads();
    }

    int n = bn + tx * 4;
    if (n < N) {
        float4 bb = make_float4(0.f,0.f,0.f,0.f);
        if (bias) bb = *(const float4*)&bias[n];
        #pragma unroll
        for (int i = 0; i < 8; i++) {
            int m = bm + ty * 8 + i;
            if (m >= M) continue;
            float rs = rowscale ? rowscale[m] : 1.f;
            float4 o;
            o.x = acc[i][0] + bb.x; o.y = acc[i][1] + bb.y;
            o.z = acc[i][2] + bb.z; o.w = acc[i][3] + bb.w;
            if (relu) {
                o.x = fmaxf(o.x, 0.f); o.y = fmaxf(o.y, 0.f);
                o.z = fmaxf(o.z, 0.f); o.w = fmaxf(o.w, 0.f);
            }
            o.x *= rs; o.y *= rs; o.z *= rs; o.w *= rs;
            *(float4*)&C[(size_t)m * N + n] = o;
        }
    }
}

// merged offset + attention-logit projections: z=0 -> offb (N=64), z=1 -> awl (N=32)
__global__ void offattn_kernel(const float* __restrict__ Woff, const float* __restrict__ boff,
                               const float* __restrict__ Wattn, const float* __restrict__ battn) {
    if (blockIdx.z == 0)
        gemm_v3(g_aug, Woff, boff, g_offb, NQ, 64, DIM, 0, nullptr, blockIdx.y * 64, 0);
    else
        gemm_v3(g_aug, Wattn, battn, g_awl, NQ, 32, DIM, 0, nullptr, blockIdx.y * 64, 0);
}

// ---------------- flash attention with K/V register prefetch ----------------
__global__ void flash_kernel(const float* __restrict__ mask) {
    int z = blockIdx.y, b = z >> 3, h = z & 7;
    int q0 = blockIdx.x * 64;
    __shared__ float Qs[32][68];
    __shared__ float Ks[32][68];
    __shared__ float Vs[64][36];
    __shared__ float PsT[64][68];
    __shared__ float Ms[64];
    int tid = threadIdx.x;
    int ty = tid >> 4, tx = tid & 15;
    int lk = tid >> 2, ld = (tid & 3) * 8;

    {
        int gq = q0 + lk;
        float4 v0 = make_float4(0.f,0.f,0.f,0.f), v1 = v0;
        if (gq < QN) {
            const float* p = &g_qh[(size_t)(b * QN + gq) * DIM + h * HD + ld];
            v0 = *(const float4*)p; v1 = *(const float4*)(p + 4);
        }
        Qs[ld + 0][lk] = v0.x; Qs[ld + 1][lk] = v0.y; Qs[ld + 2][lk] = v0.z; Qs[ld + 3][lk] = v0.w;
        Qs[ld + 4][lk] = v1.x; Qs[ld + 5][lk] = v1.y; Qs[ld + 6][lk] = v1.z; Qs[ld + 7][lk] = v1.w;
    }

    float4 pk0, pk1, pv0, pv1;
    float pm = 0.f;
    auto LOADT = [&](int k0) {
        int gk = k0 + lk;
        pk0 = make_float4(0.f,0.f,0.f,0.f); pk1 = pk0; pv0 = pk0; pv1 = pk0;
        if (gk < QN) {
            const float* pk = &g_kh[(size_t)(b * QN + gk) * DIM + h * HD + ld];
            pk0 = *(const float4*)pk; pk1 = *(const float4*)(pk + 4);
            const float* pv = &g_vh[(size_t)(b * QN + gk) * DIM + h * HD + ld];
            pv0 = *(const float4*)pv; pv1 = *(const float4*)(pv + 4);
        }
        if (tid < 64) pm = (k0 + tid < QN) ? mask[b * QN + k0 + tid] : 0.f;
    };
    auto STORET = [&]() {
        Ks[ld + 0][lk] = pk0.x; Ks[ld + 1][lk] = pk0.y; Ks[ld + 2][lk] = pk0.z; Ks[ld + 3][lk] = pk0.w;
        Ks[ld + 4][lk] = pk1.x; Ks[ld + 5][lk] = pk1.y; Ks[ld + 6][lk] = pk1.z; Ks[ld + 7][lk] = pk1.w;
        *(float4*)&Vs[lk][ld] = pv0;
        *(float4*)&Vs[lk][ld + 4] = pv1;
        if (tid < 64) Ms[tid] = pm;
    };

    float m_i[4], l_i[4], o[4][2];
    #pragma unroll
    for (int i = 0; i < 4; i++) { m_i[i] = -3.0e38f; l_i[i] = 0.f; o[i][0] = 0.f; o[i][1] = 0.f; }
    const float scale = 0.17677669529663687f;  // 1/sqrt(32)

    LOADT(0); STORET(); __syncthreads();
    const int NT = (QN + 63) / 64;  // 15
    for (int t = 0; t < NT; t++) {
        int k0 = t * 64;
        bool more = (t + 1) < NT;
        if (more) LOADT(k0 + 64);

        float s[4][4] = {};
        #pragma unroll
        for (int d = 0; d < 32; d++) {
            float4 a4 = *(const float4*)&Qs[d][ty * 4];
            float4 b4 = *(const float4*)&Ks[d][tx * 4];
            float a[4] = {a4.x, a4.y, a4.z, a4.w};
            float bb[4] = {b4.x, b4.y, b4.z, b4.w};
            #pragma unroll
            for (int i = 0; i < 4; i++)
                #pragma unroll
                for (int j = 0; j < 4; j++) s[i][j] += a[i] * bb[j];
        }

        float rm[4];
        #pragma unroll
        for (int i = 0; i < 4; i++) {
            float r = -3.0e38f;
            #pragma unroll
            for (int j = 0; j < 4; j++) {
                int gk = k0 + tx * 4 + j;
                float val;
                if (gk >= QN) val = -1.0e30f;
                else if (Ms[tx * 4 + j] > 0.f) val = s[i][j] * scale;
                else val = -1.0e9f;
                s[i][j] = val;
                r = fmaxf(r, val);
            }
            #pragma unroll
            for (int off = 1; off < 16; off <<= 1)
                r = fmaxf(r, __shfl_xor_sync(0xffffffffu, r, off));
            rm[i] = r;
        }

        #pragma unroll
        for (int i = 0; i < 4; i++) {
            float mn = fmaxf(m_i[i], rm[i]);
            float f = __expf(m_i[i] - mn);
            float rs = 0.f;
            #pragma unroll
            for (int j = 0; j < 4; j++) {
                float p = __expf(s[i][j] - mn);
                s[i][j] = p;
                rs += p;
            }
            #pragma unroll
            for (int off = 1; off < 16; off <<= 1)
                rs += __shfl_xor_sync(0xffffffffu, rs, off);
            l_i[i] = l_i[i] * f + rs;
            m_i[i] = mn;
            o[i][0] *= f; o[i][1] *= f;
        }

        #pragma unroll
        for (int i = 0; i < 4; i++)
            #pragma unroll
            for (int j = 0; j < 4; j++)
                PsT[tx * 4 + j][ty * 4 + i] = s[i][j];
        __syncthreads();

        #pragma unroll 8
        for (int k = 0; k < 64; k++) {
            float4 a4 = *(const float4*)&PsT[k][ty * 4];
            float2 b2 = *(const float2*)&Vs[k][tx * 2];
            o[0][0] += a4.x * b2.x; o[0][1] += a4.x * b2.y;
            o[1][0] += a4.y * b2.x; o[1][1] += a4.y * b2.y;
            o[2][0] += a4.z * b2.x; o[2][1] += a4.z * b2.y;
            o[3][0] += a4.w * b2.x; o[3][1] += a4.w * b2.y;
        }
        __syncthreads();
        if (more) { STORET(); __syncthreads(); }
    }

    #pragma unroll
    for (int i = 0; i < 4; i++) {
        int q = q0 + ty * 4 + i;
        if (q < QN) {
            float inv = 1.f / l_i[i];
            float* p = &g_att[(size_t)(b * QN + q) * DIM + h * HD + tx * 2];
            p[0] = o[i][0] * inv;
            p[1] = o[i][1] * inv;
        }
    }
}

// ---------------- add + layernorm (256-d rows) ----------------
__global__ void add_ln_kernel(const float* __restrict__ A, const float* __restrict__ B,
                              const float* __restrict__ g, const float* __restrict__ beta,
                              float* __restrict__ out) {
    int row = blockIdx.x, tid = threadIdx.x;
    float x = A[row * DIM + tid] + B[row * DIM + tid];
    __shared__ float red1[8], red2[8];
    float s1 = x, s2 = x * x;
    for (int o = 16; o; o >>= 1) {
        s1 += __shfl_xor_sync(0xffffffffu, s1, o);
        s2 += __shfl_xor_sync(0xffffffffu, s2, o);
    }
    if ((tid & 31) == 0) { red1[tid >> 5] = s1; red2[tid >> 5] = s2; }
    __syncthreads();
    float t1 = 0.f, t2 = 0.f;
    #pragma unroll
    for (int i = 0; i < 8; i++) { t1 += red1[i]; t2 += red2[i]; }
    float mean = t1 * (1.f / DIM);
    float var = t2 * (1.f / DIM) - mean * mean;
    out[row * DIM + tid] = (x - mean) * rsqrtf(var + 1e-5f) * g[tid] + beta[tid];
}

// ---------------- deformable gather (float4, 2 heads per 64-lane group) ----------------
__global__ void deform_kernel(const float* __restrict__ bev, const float* __restrict__ ref) {
    int q = blockIdx.x, n = blockIdx.y;
    int nq = n * QN + q;
    __shared__ int sidx[128];
    __shared__ float swt[128];
    int tid = threadIdx.x;  // 256
    if (tid < 128) {
        int h = tid >> 4, s = tid & 15, p = s >> 2, c = s & 3;
        const float* awl = g_awl + nq * 32 + h * 4;
        float l0 = awl[0], l1 = awl[1], l2 = awl[2], l3 = awl[3];
        float mm = fmaxf(fmaxf(l0, l1), fmaxf(l2, l3));
        float e0 = __expf(l0 - mm), e1 = __expf(l1 - mm);
        float e2 = __expf(l2 - mm), e3 = __expf(l3 - mm);
        float es = 1.f / (e0 + e1 + e2 + e3);
        float awp = (p == 0 ? e0 : p == 1 ? e1 : p == 2 ? e2 : e3) * es;
        const float* off = g_offb + nq * 64 + h * 8;
        float x = ref[nq * 2 + 0] * (float)WBB + off[p * 2 + 0] - 0.5f;
        float y = ref[nq * 2 + 1] * (float)HBB + off[p * 2 + 1] - 0.5f;
        float x0f = floorf(x), y0f = floorf(y);
        float fx = x - x0f, fy = y - y0f;
        int dx = c & 1, dy = c >> 1;
        int xc = (int)x0f + dx, yc = (int)y0f + dy;
        float w = (dx ? fx : 1.f - fx) * (dy ? fy : 1.f - fy);
        bool valid = (xc >= 0) && (xc < WBB) && (yc >= 0) && (yc < HBB);
        float wf = valid ? awp * w : 0.f;
        int xcc = min(max(xc, 0), WBB - 1);
        int ycc = min(max(yc, 0), HBB - 1);
        sidx[tid] = ycc * WBB + xcc;
        swt[tid] = wf;
        float sw = wf;
        #pragma unroll
        for (int o = 1; o < 16; o <<= 1) sw += __shfl_xor_sync(0xffffffffu, sw, o);
        if (s == 0) g_sumw[nq * 8 + h] = sw;
    }
    __syncthreads();
    int sg = tid >> 6;            // 0..3 -> heads 2sg, 2sg+1
    int c4 = (tid & 63) << 2;     // channel base
    const float* bevn = bev + (size_t)n * (HBB * WBB) * DIM;
    #pragma unroll
    for (int hh2 = 0; hh2 < 2; hh2++) {
        int h = sg * 2 + hh2;
        float4 a = make_float4(0.f, 0.f, 0.f, 0.f);
        #pragma unroll
        for (int s = 0; s < 16; s++) {
            float w = swt[h * 16 + s];
            if (w != 0.f) {
                float4 gv = *(const float4*)&bevn[(size_t)sidx[h * 16 + s] * DIM + c4];
                a.x += w * gv.x; a.y += w * gv.y; a.z += w * gv.z; a.w += w * gv.w;
            }
        }
        *(float4*)&g_agg[((size_t)nq * HH + h) * DIM + c4] = a;
    }
}

// ---------------- per-head projection: 128x32 tile, 128 threads, 8x4 micro ----------------
__global__ void headgemm_kernel(const float* __restrict__ Wval, const float* __restrict__ bval) {
    int h = blockIdx.y;
    int bm = blockIdx.x * 128;
    __shared__ float As[2][16][132];
    __shared__ float Bs[2][16][36];
    int tid = threadIdx.x;  // 128
    int ty = tid >> 3, tx = tid & 7;
    float acc[8][4] = {};

    int m_a = bm + tid;
    bool avalid = m_a < NQ;
    const float* Arow = g_agg + ((size_t)m_a * HH + h) * DIM;
    int brr = tid >> 3;
    int bn4 = (tid & 7) * 4;
    const float* Wh = Wval + h * HD;

    float4 a0, a1, a2, a3, b0;
    auto LOADA = [&](int k0) {
        a0 = make_float4(0.f,0.f,0.f,0.f); a1 = a0; a2 = a0; a3 = a0;
        if (avalid) {
            a0 = *(const float4*)&Arow[k0];     a1 = *(const float4*)&Arow[k0 + 4];
            a2 = *(const float4*)&Arow[k0 + 8]; a3 = *(const float4*)&Arow[k0 + 12];
        }
    };
    auto LOADB = [&](int k0) {
        b0 = *(const float4*)&Wh[(size_t)(k0 + brr) * DIM + bn4];
    };
    auto STORE = [&](int buf) {
        float av[16] = {a0.x,a0.y,a0.z,a0.w,a1.x,a1.y,a1.z,a1.w,
                        a2.x,a2.y,a2.z,a2.w,a3.x,a3.y,a3.z,a3.w};
        #pragma unroll
        for (int i = 0; i < 16; i++) As[buf][i][tid] = av[i];
        *(float4*)&Bs[buf][brr][bn4] = b0;
    };

    LOADA(0); LOADB(0); STORE(0);
    __syncthreads();
    int buf = 0;
    for (int k0 = 16;; k0 += 16) {
        bool more = (k0 < DIM);
        if (more) { LOADA(k0); LOADB(k0); }
        #pragma unroll
        for (int kk = 0; kk < 16; kk++) {
            float4 x0 = *(const float4*)&As[buf][kk][ty * 8];
            float4 x1 = *(const float4*)&As[buf][kk][ty * 8 + 4];
            float4 y  = *(const float4*)&Bs[buf][kk][tx * 4];
            float a[8] = {x0.x,x0.y,x0.z,x0.w,x1.x,x1.y,x1.z,x1.w};
            float b[4] = {y.x,y.y,y.z,y.w};
            #pragma unroll
            for (int i = 0; i < 8; i++)
                #pragma unroll
                for (int j = 0; j < 4; j++) acc[i][j] += a[i] * b[j];
        }
        if (!more) break;
        buf ^= 1;
        STORE(buf);
        __syncthreads();
    }

    float4 bb = *(const float4*)&bval[h * HD + tx * 4];
    #pragma unroll
    for (int i = 0; i < 8; i++) {
        int m = bm + ty * 8 + i;
        if (m >= NQ) continue;
        float sw = g_sumw[m * HH + h];
        float4 o;
        o.x = acc[i][0] + bb.x * sw; o.y = acc[i][1] + bb.y * sw;
        o.z = acc[i][2] + bb.z * sw; o.w = acc[i][3] + bb.w * sw;
        *(float4*)&g_ho[(size_t)m * DIM + h * HD + tx * 4] = o;
    }
}

// ---------------- launch ----------------
static float* symaddr(const void* s) {
    void* p = nullptr;
    cudaGetSymbolAddress(&p, s);
    return (float*)p;
}

extern "C" void kernel_launch(void* const* d_in, const int* in_sizes, int n_in,
                              void* d_out, int out_size) {
    const float* queries = (const float*)d_in[0];
    const float* bev     = (const float*)d_in[1];
    const float* refp    = (const float*)d_in[2];
    const float* og      = (const float*)d_in[3];
    const float* mask    = (const float*)d_in[4];
    const float* Wq = (const float*)d_in[5];  const float* bq = (const float*)d_in[6];
    const float* Wk = (const float*)d_in[7];  const float* bk = (const float*)d_in[8];
    const float* Wv = (const float*)d_in[9];  const float* bv = (const float*)d_in[10];
    const float* Wo = (const float*)d_in[11]; const float* bo = (const float*)d_in[12];
    const float* ln1g = (const float*)d_in[13]; const float* ln1b = (const float*)d_in[14];
    const float* Wval = (const float*)d_in[15]; const float* bval = (const float*)d_in[16];
    const float* Woff = (const float*)d_in[17]; const float* boff = (const float*)d_in[18];
    const float* Wattn = (const float*)d_in[19]; const float* battn = (const float*)d_in[20];
    const float* Wdo = (const float*)d_in[21]; const float* bdo = (const float*)d_in[22];
    const float* ln2g = (const float*)d_in[23]; const float* ln2b = (const float*)d_in[24];
    const float* W1 = (const float*)d_in[25]; const float* b1 = (const float*)d_in[26];
    const float* W2 = (const float*)d_in[27]; const float* b2 = (const float*)d_in[28];
    const float* ln3g = (const float*)d_in[29]; const float* ln3b = (const float*)d_in[30];
    float* out = (float*)d_out;

    float* pqk  = symaddr(g_qk);
    float* patt = symaddr(g_att);
    float* pout1 = symaddr(g_out1);
    float* pout2 = symaddr(g_out2);
    float* paug = symaddr(g_aug);
    float* pho  = symaddr(g_ho);
    float* pout3 = symaddr(g_out3);
    float* pout4 = symaddr(g_out4);
    float* pffn = symaddr(g_ffn);
    float* pout5 = symaddr(g_out5);

    // 1. q_and_k = queries + og
    add_kernel<<<NQ, 256>>>(queries, og, pqk);
    // 2. fused QKV projections (tf32 tensor cores)
    qkv_kernel<<<dim3(4, 57, 3), 128>>>(queries, Wq, bq, Wk, bk, Wv, bv);
    // 3. flash attention
    flash_kernel<<<dim3(15, NZ), 256>>>(mask);
    // 4. output projection + LN1
    gemm_tf32_kernel<<<dim3(4, 57), 128>>>(patt, Wo, bo, pout1, NQ, DIM, DIM, 0, nullptr);
    add_ln_kernel<<<NQ, 256>>>(queries, pout1, ln1g, ln1b, pout2);
    // 5. deformable attention (projection commuted past sampling)
    add_kernel<<<NQ, 256>>>(pout2, og, paug);
    offattn_kernel<<<dim3(1, 57, 2), 128>>>(Woff, boff, Wattn, battn);
    deform_kernel<<<dim3(QN, NB), 256>>>(bev, refp);
    headgemm_kernel<<<dim3(29, HH), 128>>>(Wval, bval);
    gemm_tf32_kernel<<<dim3(4, 57), 128>>>(pho, Wdo, bdo, pout3, NQ, DIM, DIM, 0, mask);
    add_ln_kernel<<<NQ, 256>>>(pout2, pout3, ln2g, ln2b, pout4);
    // 6. FFN + LN3 (tf32 tensor cores)
    gemm_tf32_kernel<<<dim3(8, 57), 128>>>(pout4, W1, b1, pffn, NQ, FFD, DIM, 1, nullptr);
    gemm_tf32_kernel<<<dim3(4, 57), 128>>>(pffn, W2, b2, pout5, NQ, DIM, FFD, 0, nullptr);
    add_ln_kernel<<<NQ, 256>>>(pout4, pout5, ln3g, ln3b, out);
}

// round 7
// speedup vs baseline: 2.6948x; 1.5256x over previous
#include <cuda_runtime.h>
#include <math.h>

#define NB   4
#define QN   900
#define DIM  256
#define HH   8
#define HD   32
#define PP   4
#define HBB  200
#define WBB  200
#define FFD  512
#define NQ   (NB*QN)        // 3600
#define NZ   (NB*HH)        // 32

// ---------------- device scratch (static, allocation-free) ----------------
__device__ float g_qk [NQ*DIM];
__device__ float g_qh [NQ*DIM];
__device__ float g_kh [NQ*DIM];
__device__ float g_vh [NQ*DIM];
__device__ float g_att [NQ*DIM];
__device__ float g_out1[NQ*DIM];
__device__ float g_out2[NQ*DIM];
__device__ float g_aug [NQ*DIM];
__device__ float g_offb[NQ*64];
__device__ float g_awl [NQ*32];
__device__ float g_agg [(size_t)NQ*HH*DIM];    // ~29.5 MB
__device__ float g_sumw[NQ*HH];
__device__ float g_ho  [NQ*DIM];
__device__ float g_out3[NQ*DIM];
__device__ float g_out4[NQ*DIM];
__device__ float g_ffn [NQ*FFD];
__device__ float g_out5[NQ*DIM];

// ---------------- elementwise add ----------------
__global__ void add_kernel(const float* __restrict__ A, const float* __restrict__ B,
                           float* __restrict__ C) {
    int i = blockIdx.x * blockDim.x + threadIdx.x;
    C[i] = A[i] + B[i];
}

// ================= tf32 mma primitives =================
__device__ __forceinline__ unsigned f2tf(float x) {
    unsigned r;
    asm("cvt.rna.tf32.f32 %0, %1;" : "=r"(r) : "f"(x));
    return r;
}
__device__ __forceinline__ void mma_tf32(float4& d,
                                         unsigned a0, unsigned a1, unsigned a2, unsigned a3,
                                         unsigned b0, unsigned b1) {
    asm volatile("mma.sync.aligned.m16n8k8.row.col.f32.tf32.tf32.f32 "
                 "{%0,%1,%2,%3}, {%4,%5,%6,%7}, {%8,%9}, {%0,%1,%2,%3};"
                 : "+f"(d.x), "+f"(d.y), "+f"(d.z), "+f"(d.w)
                 : "r"(a0), "r"(a1), "r"(a2), "r"(a3), "r"(b0), "r"(b1));
}

#define ASTR 20
#define BSTR 72

// ================= tf32 tensor-core GEMM (64x64 tile, 4 warps 2x2) =================
__device__ __forceinline__ void gemm_tf32(const float* __restrict__ A,
                                          const float* __restrict__ W,
                                          const float* __restrict__ bias,
                                          float* __restrict__ C,
                                          int M, int N, int K, int relu,
                                          const float* __restrict__ rowscale,
                                          int bm, int bn) {
    __shared__ unsigned As[2][64 * ASTR];
    __shared__ unsigned Bs[2][16 * BSTR];
    int tid = threadIdx.x;              // 128
    int warp = tid >> 5, lane = tid & 31;
    int wm = (warp & 1) * 32;
    int wn = (warp >> 1) * 32;
    int fr = lane >> 2, fc = lane & 3;
    float4 acc[2][4];
    #pragma unroll
    for (int i = 0; i < 2; i++)
        #pragma unroll
        for (int j = 0; j < 4; j++) acc[i][j] = make_float4(0.f, 0.f, 0.f, 0.f);

    int am = tid >> 1;
    int ak = (tid & 1) * 8;
    bool avalid = (bm + am) < M;
    const float* Aptr = A + (size_t)(bm + am) * K + ak;
    int bk = tid >> 3;
    int bnc = (tid & 7) * 8;
    const float* Wptr = W + (size_t)bk * N + bn + bnc;

    float4 xa0, xa1, yb0, yb1;
    auto LDG = [&](int k0) {
        xa0 = make_float4(0.f, 0.f, 0.f, 0.f); xa1 = xa0;
        if (avalid) { xa0 = *(const float4*)(Aptr + k0); xa1 = *(const float4*)(Aptr + k0 + 4); }
        yb0 = *(const float4*)(Wptr + (size_t)k0 * N);
        yb1 = *(const float4*)(Wptr + (size_t)k0 * N + 4);
    };
    auto STS = [&](int buf) {
        uint4 u0 = make_uint4(f2tf(xa0.x), f2tf(xa0.y), f2tf(xa0.z), f2tf(xa0.w));
        uint4 u1 = make_uint4(f2tf(xa1.x), f2tf(xa1.y), f2tf(xa1.z), f2tf(xa1.w));
        *(uint4*)&As[buf][am * ASTR + ak] = u0;
        *(uint4*)&As[buf][am * ASTR + ak + 4] = u1;
        uint4 v0 = make_uint4(f2tf(yb0.x), f2tf(yb0.y), f2tf(yb0.z), f2tf(yb0.w));
        uint4 v1 = make_uint4(f2tf(yb1.x), f2tf(yb1.y), f2tf(yb1.z), f2tf(yb1.w));
        *(uint4*)&Bs[buf][bk * BSTR + bnc] = v0;
        *(uint4*)&Bs[buf][bk * BSTR + bnc + 4] = v1;
    };

    LDG(0); STS(0);
    __syncthreads();
    int buf = 0;
    for (int k0 = 16;; k0 += 16) {
        bool more = (k0 < K);
        if (more) LDG(k0);
        #pragma unroll
        for (int ks = 0; ks < 16; ks += 8) {
            unsigned af[2][4];
            #pragma unroll
            for (int mi = 0; mi < 2; mi++) {
                const unsigned* ab = &As[buf][(wm + mi * 16) * ASTR + ks];
                af[mi][0] = ab[fr * ASTR + fc];
                af[mi][1] = ab[(fr + 8) * ASTR + fc];
                af[mi][2] = ab[fr * ASTR + fc + 4];
                af[mi][3] = ab[(fr + 8) * ASTR + fc + 4];
            }
            unsigned bf[4][2];
            #pragma unroll
            for (int ni = 0; ni < 4; ni++) {
                const unsigned* bb = &Bs[buf][ks * BSTR + wn + ni * 8 + fr];
                bf[ni][0] = bb[fc * BSTR];
                bf[ni][1] = bb[(fc + 4) * BSTR];
            }
            #pragma unroll
            for (int mi = 0; mi < 2; mi++)
                #pragma unroll
                for (int ni = 0; ni < 4; ni++)
                    mma_tf32(acc[mi][ni], af[mi][0], af[mi][1], af[mi][2], af[mi][3],
                             bf[ni][0], bf[ni][1]);
        }
        if (!more) break;
        buf ^= 1;
        STS(buf);
        __syncthreads();
    }

    int c2 = fc * 2;
    #pragma unroll
    for (int ni = 0; ni < 4; ni++) {
        int n = bn + wn + ni * 8 + c2;
        float b0 = 0.f, b1 = 0.f;
        if (bias) { b0 = bias[n]; b1 = bias[n + 1]; }
        #pragma unroll
        for (int mi = 0; mi < 2; mi++) {
            float4 d = acc[mi][ni];
            int m0 = bm + wm + mi * 16 + fr;
            int m1 = m0 + 8;
            if (m0 < M) {
                float rs = rowscale ? rowscale[m0] : 1.f;
                float o0 = d.x + b0, o1 = d.y + b1;
                if (relu) { o0 = fmaxf(o0, 0.f); o1 = fmaxf(o1, 0.f); }
                *(float2*)&C[(size_t)m0 * N + n] = make_float2(o0 * rs, o1 * rs);
            }
            if (m1 < M) {
                float rs = rowscale ? rowscale[m1] : 1.f;
                float o0 = d.z + b0, o1 = d.w + b1;
                if (relu) { o0 = fmaxf(o0, 0.f); o1 = fmaxf(o1, 0.f); }
                *(float2*)&C[(size_t)m1 * N + n] = make_float2(o0 * rs, o1 * rs);
            }
        }
    }
}

__global__ void gemm_tf32_kernel(const float* __restrict__ A, const float* __restrict__ W,
                                 const float* __restrict__ bias, float* __restrict__ C,
                                 int M, int N, int K, int relu,
                                 const float* __restrict__ rowscale) {
    gemm_tf32(A, W, bias, C, M, N, K, relu, rowscale, blockIdx.y * 64, blockIdx.x * 64);
}

__global__ void qkv_kernel(const float* __restrict__ queries,
                           const float* __restrict__ Wq, const float* __restrict__ bq,
                           const float* __restrict__ Wk, const float* __restrict__ bk,
                           const float* __restrict__ Wv, const float* __restrict__ bv) {
    int z = blockIdx.z;
    const float* A = (z == 2) ? queries : g_qk;
    const float* W = (z == 0) ? Wq : (z == 1) ? Wk : Wv;
    const float* bias = (z == 0) ? bq : (z == 1) ? bk : bv;
    float* C = (z == 0) ? g_qh : (z == 1) ? g_kh : g_vh;
    gemm_tf32(A, W, bias, C, NQ, DIM, DIM, 0, nullptr, blockIdx.y * 64, blockIdx.x * 64);
}

// ---------------- SIMT GEMM (small-N projections) ----------------
__device__ __forceinline__ void gemm_v3(const float* __restrict__ A,
                                        const float* __restrict__ W,
                                        const float* __restrict__ bias,
                                        float* __restrict__ C,
                                        int M, int N, int K, int relu,
                                        const float* __restrict__ rowscale,
                                        int bm, int bn) {
    __shared__ float As[2][16][68];
    __shared__ float Bs[2][16][68];
    int tid = threadIdx.x;          // 128
    int ty = tid >> 4, tx = tid & 15;
    int am = tid & 63;
    int ak = (tid >> 6) << 3;
    int br = tid >> 4;
    int bn4 = (tid & 15) << 2;
    float acc[8][4] = {};

    int m_a = bm + am;
    int n_b = bn + bn4;
    bool avalid = m_a < M;
    bool bvalid = n_b < N;
    const float* Arow = A + (size_t)m_a * K + ak;

    float4 a0 = make_float4(0.f,0.f,0.f,0.f), a1 = a0, b0 = a0, b1 = a0;
    if (avalid) { a0 = *(const float4*)(Arow); a1 = *(const float4*)(Arow + 4); }
    if (bvalid) {
        b0 = *(const float4*)&W[(size_t)br * N + n_b];
        b1 = *(const float4*)&W[(size_t)(br + 8) * N + n_b];
    }
    int buf = 0;
    {
        float av[8] = {a0.x,a0.y,a0.z,a0.w,a1.x,a1.y,a1.z,a1.w};
        #pragma unroll
        for (int i = 0; i < 8; i++) As[0][ak + i][am] = av[i];
        *(float4*)&Bs[0][br][bn4] = b0;
        *(float4*)&Bs[0][br + 8][bn4] = b1;
    }
    __syncthreads();

    for (int k0 = 16;; k0 += 16) {
        bool more = (k0 < K);
        if (more) {
            a0 = make_float4(0.f,0.f,0.f,0.f); a1 = a0; b0 = a0; b1 = a0;
            if (avalid) { a0 = *(const float4*)(Arow + k0); a1 = *(const float4*)(Arow + k0 + 4); }
            if (bvalid) {
                b0 = *(const float4*)&W[(size_t)(k0 + br) * N + n_b];
                b1 = *(const float4*)&W[(size_t)(k0 + br + 8) * N + n_b];
            }
        }
        #pragma unroll
        for (int kk = 0; kk < 16; kk++) {
            float4 x0 = *(const float4*)&As[buf][kk][ty * 8];
            float4 x1 = *(const float4*)&As[buf][kk][ty * 8 + 4];
            float4 y  = *(const float4*)&Bs[buf][kk][tx * 4];
            float a[8] = {x0.x,x0.y,x0.z,x0.w,x1.x,x1.y,x1.z,x1.w};
            float b[4] = {y.x,y.y,y.z,y.w};
            #pragma unroll
            for (int i = 0; i < 8; i++)
                #pragma unroll
                for (int j = 0; j < 4; j++) acc[i][j] += a[i] * b[j];
        }
        if (!more) break;
        buf ^= 1;
        {
            float av[8] = {a0.x,a0.y,a0.z,a0.w,a1.x,a1.y,a1.z,a1.w};
            #pragma unroll
            for (int i = 0; i < 8; i++) As[buf][ak + i][am] = av[i];
            *(float4*)&Bs[buf][br][bn4] = b0;
            *(float4*)&Bs[buf][br + 8][bn4] = b1;
        }
        __syncthreads();
    }

    int n = bn + tx * 4;
    if (n < N) {
        float4 bb = make_float4(0.f,0.f,0.f,0.f);
        if (bias) bb = *(const float4*)&bias[n];
        #pragma unroll
        for (int i = 0; i < 8; i++) {
            int m = bm + ty * 8 + i;
            if (m >= M) continue;
            float rs = rowscale ? rowscale[m] : 1.f;
            float4 o;
            o.x = acc[i][0] + bb.x; o.y = acc[i][1] + bb.y;
            o.z = acc[i][2] + bb.z; o.w = acc[i][3] + bb.w;
            if (relu) {
                o.x = fmaxf(o.x, 0.f); o.y = fmaxf(o.y, 0.f);
                o.z = fmaxf(o.z, 0.f); o.w = fmaxf(o.w, 0.f);
            }
            o.x *= rs; o.y *= rs; o.z *= rs; o.w *= rs;
            *(float4*)&C[(size_t)m * N + n] = o;
        }
    }
}

__global__ void offattn_kernel(const float* __restrict__ Woff, const float* __restrict__ boff,
                               const float* __restrict__ Wattn, const float* __restrict__ battn) {
    if (blockIdx.z == 0)
        gemm_v3(g_aug, Woff, boff, g_offb, NQ, 64, DIM, 0, nullptr, blockIdx.y * 64, 0);
    else
        gemm_v3(g_aug, Wattn, battn, g_awl, NQ, 32, DIM, 0, nullptr, blockIdx.y * 64, 0);
}

// ================= flash attention on tensor cores =================
// 128 threads = 4 warps, each warp owns 16 q rows; 64-key tiles.
__global__ void flash_kernel(const float* __restrict__ mask) {
    int z = blockIdx.y, b = z >> 3, h = z & 7;
    int q0 = blockIdx.x * 64;
    __shared__ float    Qs[64 * 36];
    __shared__ unsigned Ks[64 * 36];    // [key][d] tf32
    __shared__ unsigned VsT[32 * 68];   // [d][key] tf32
    __shared__ float    Ms[64];
    int tid = threadIdx.x;
    int warp = tid >> 5, lane = tid & 31;
    int fr = lane >> 2, fc = lane & 3;
    const float scale = 0.17677669529663687f;  // 1/sqrt(32)

    // stage Q tile (fp32, zero-padded)
    {
        int row = tid >> 1, d0 = (tid & 1) * 16;
        int gq = q0 + row;
        float4 v[4];
        #pragma unroll
        for (int i = 0; i < 4; i++) v[i] = make_float4(0.f, 0.f, 0.f, 0.f);
        if (gq < QN) {
            const float* p = &g_qh[(size_t)(b * QN + gq) * DIM + h * HD + d0];
            #pragma unroll
            for (int i = 0; i < 4; i++) v[i] = *(const float4*)(p + i * 4);
        }
        #pragma unroll
        for (int i = 0; i < 4; i++) *(float4*)&Qs[row * 36 + d0 + i * 4] = v[i];
    }
    __syncthreads();

    // Q fragments -> registers (tf32), 4 k-steps
    unsigned aq[4][4];
    {
        int r0 = warp * 16 + fr;
        #pragma unroll
        for (int ks = 0; ks < 4; ks++) {
            aq[ks][0] = f2tf(Qs[r0 * 36 + ks * 8 + fc]);
            aq[ks][1] = f2tf(Qs[(r0 + 8) * 36 + ks * 8 + fc]);
            aq[ks][2] = f2tf(Qs[r0 * 36 + ks * 8 + fc + 4]);
            aq[ks][3] = f2tf(Qs[(r0 + 8) * 36 + ks * 8 + fc + 4]);
        }
    }

    // K/V register prefetch
    int lk = tid >> 1, ld = (tid & 1) * 16;
    float4 pk[4], pv[4];
    float pm = 0.f;
    auto LOADT = [&](int k0) {
        int gk = k0 + lk;
        #pragma unroll
        for (int i = 0; i < 4; i++) { pk[i] = make_float4(0.f,0.f,0.f,0.f); pv[i] = pk[i]; }
        if (gk < QN) {
            const float* kp = &g_kh[(size_t)(b * QN + gk) * DIM + h * HD + ld];
            const float* vp = &g_vh[(size_t)(b * QN + gk) * DIM + h * HD + ld];
            #pragma unroll
            for (int i = 0; i < 4; i++) { pk[i] = *(const float4*)(kp + i * 4); pv[i] = *(const float4*)(vp + i * 4); }
        }
        if (tid < 64) pm = (k0 + tid < QN) ? mask[b * QN + k0 + tid] : 0.f;
    };
    auto STORET = [&]() {
        #pragma unroll
        for (int i = 0; i < 4; i++) {
            uint4 u = make_uint4(f2tf(pk[i].x), f2tf(pk[i].y), f2tf(pk[i].z), f2tf(pk[i].w));
            *(uint4*)&Ks[lk * 36 + ld + i * 4] = u;
        }
        #pragma unroll
        for (int i = 0; i < 4; i++) {
            VsT[(ld + i * 4 + 0) * 68 + lk] = f2tf(pv[i].x);
            VsT[(ld + i * 4 + 1) * 68 + lk] = f2tf(pv[i].y);
            VsT[(ld + i * 4 + 2) * 68 + lk] = f2tf(pv[i].z);
            VsT[(ld + i * 4 + 3) * 68 + lk] = f2tf(pv[i].w);
        }
        if (tid < 64) Ms[tid] = pm;
    };

    float m0 = -3.0e38f, m1 = -3.0e38f, l0 = 0.f, l1 = 0.f;
    float4 o[4];
    #pragma unroll
    for (int i = 0; i < 4; i++) o[i] = make_float4(0.f, 0.f, 0.f, 0.f);

    LOADT(0); STORET(); __syncthreads();
    const int NT = (QN + 63) / 64;  // 15
    for (int t = 0; t < NT; t++) {
        int k0 = t * 64;
        bool more = (t + 1) < NT;
        if (more) LOADT(k0 + 64);

        // S = Q @ K^T : 8 n-tiles x 4 k-steps
        float4 s[8];
        #pragma unroll
        for (int nt = 0; nt < 8; nt++) s[nt] = make_float4(0.f, 0.f, 0.f, 0.f);
        #pragma unroll
        for (int ks = 0; ks < 4; ks++) {
            #pragma unroll
            for (int nt = 0; nt < 8; nt++) {
                unsigned b0 = Ks[(nt * 8 + fr) * 36 + ks * 8 + fc];
                unsigned b1 = Ks[(nt * 8 + fr) * 36 + ks * 8 + fc + 4];
                mma_tf32(s[nt], aq[ks][0], aq[ks][1], aq[ks][2], aq[ks][3], b0, b1);
            }
        }

        // scale + mask + row max (rows fr, fr+8; quad-lane reduce)
        float rm0 = -3.0e38f, rm1 = -3.0e38f;
        #pragma unroll
        for (int nt = 0; nt < 8; nt++) {
            int kx = k0 + nt * 8 + 2 * fc;
            float mx = Ms[nt * 8 + 2 * fc], my = Ms[nt * 8 + 2 * fc + 1];
            float4 v = s[nt];
            v.x = (kx     < QN) ? (mx > 0.f ? v.x * scale : -1e9f) : -1e30f;
            v.y = (kx + 1 < QN) ? (my > 0.f ? v.y * scale : -1e9f) : -1e30f;
            v.z = (kx     < QN) ? (mx > 0.f ? v.z * scale : -1e9f) : -1e30f;
            v.w = (kx + 1 < QN) ? (my > 0.f ? v.w * scale : -1e9f) : -1e30f;
            s[nt] = v;
            rm0 = fmaxf(rm0, fmaxf(v.x, v.y));
            rm1 = fmaxf(rm1, fmaxf(v.z, v.w));
        }
        rm0 = fmaxf(rm0, __shfl_xor_sync(0xffffffffu, rm0, 1));
        rm0 = fmaxf(rm0, __shfl_xor_sync(0xffffffffu, rm0, 2));
        rm1 = fmaxf(rm1, __shfl_xor_sync(0xffffffffu, rm1, 1));
        rm1 = fmaxf(rm1, __shfl_xor_sync(0xffffffffu, rm1, 2));

        float mn0 = fmaxf(m0, rm0), mn1 = fmaxf(m1, rm1);
        float f0 = __expf(m0 - mn0), f1 = __expf(m1 - mn1);
        m0 = mn0; m1 = mn1;
        #pragma unroll
        for (int i = 0; i < 4; i++) { o[i].x *= f0; o[i].y *= f0; o[i].z *= f1; o[i].w *= f1; }

        float rs0 = 0.f, rs1 = 0.f;
        #pragma unroll
        for (int nt = 0; nt < 8; nt++) {
            float4 v = s[nt];
            v.x = __expf(v.x - mn0); v.y = __expf(v.y - mn0);
            v.z = __expf(v.z - mn1); v.w = __expf(v.w - mn1);
            s[nt] = v;
            rs0 += v.x + v.y; rs1 += v.z + v.w;
        }
        rs0 += __shfl_xor_sync(0xffffffffu, rs0, 1);
        rs0 += __shfl_xor_sync(0xffffffffu, rs0, 2);
        rs1 += __shfl_xor_sync(0xffffffffu, rs1, 1);
        rs1 += __shfl_xor_sync(0xffffffffu, rs1, 2);
        l0 = l0 * f0 + rs0;
        l1 = l1 * f1 + rs1;

        // O += P @ V : convert C-frag -> A-frag via shfl, then mma
        int srcA = (lane & ~3) | (fc >> 1);
        int srcB = srcA | 2;
        bool odd = (fc & 1);
        #pragma unroll
        for (int ks = 0; ks < 8; ks++) {
            float4 c = s[ks];
            float y0 = __shfl_sync(0xffffffffu, c.x, srcA);
            float y1 = __shfl_sync(0xffffffffu, c.y, srcA);
            float z0 = __shfl_sync(0xffffffffu, c.x, srcB);
            float z1 = __shfl_sync(0xffffffffu, c.y, srcB);
            float y2 = __shfl_sync(0xffffffffu, c.z, srcA);
            float y3 = __shfl_sync(0xffffffffu, c.w, srcA);
            float z2 = __shfl_sync(0xffffffffu, c.z, srcB);
            float z3 = __shfl_sync(0xffffffffu, c.w, srcB);
            unsigned a0 = f2tf(odd ? y1 : y0);
            unsigned a1 = f2tf(odd ? y3 : y2);
            unsigned a2 = f2tf(odd ? z1 : z0);
            unsigned a3 = f2tf(odd ? z3 : z2);
            #pragma unroll
            for (int dt = 0; dt < 4; dt++) {
                unsigned b0 = VsT[(dt * 8 + fr) * 68 + ks * 8 + fc];
                unsigned b1 = VsT[(dt * 8 + fr) * 68 + ks * 8 + fc + 4];
                mma_tf32(o[dt], a0, a1, a2, a3, b0, b1);
            }
        }
        __syncthreads();
        if (more) { STORET(); __syncthreads(); }
    }

    // epilogue
    float inv0 = 1.f / l0, inv1 = 1.f / l1;
    int qr0 = q0 + warp * 16 + fr;
    int qr1 = qr0 + 8;
    #pragma unroll
    for (int dt = 0; dt < 4; dt++) {
        int d = h * HD + dt * 8 + 2 * fc;
        if (qr0 < QN)
            *(float2*)&g_att[(size_t)(b * QN + qr0) * DIM + d] = make_float2(o[dt].x * inv0, o[dt].y * inv0);
        if (qr1 < QN)
            *(float2*)&g_att[(size_t)(b * QN + qr1) * DIM + d] = make_float2(o[dt].z * inv1, o[dt].w * inv1);
    }
}

// ---------------- add + layernorm (256-d rows) ----------------
__global__ void add_ln_kernel(const float* __restrict__ A, const float* __restrict__ B,
                              const float* __restrict__ g, const float* __restrict__ beta,
                              float* __restrict__ out) {
    int row = blockIdx.x, tid = threadIdx.x;
    float x = A[row * DIM + tid] + B[row * DIM + tid];
    __shared__ float red1[8], red2[8];
    float s1 = x, s2 = x * x;
    for (int o = 16; o; o >>= 1) {
        s1 += __shfl_xor_sync(0xffffffffu, s1, o);
        s2 += __shfl_xor_sync(0xffffffffu, s2, o);
    }
    if ((tid & 31) == 0) { red1[tid >> 5] = s1; red2[tid >> 5] = s2; }
    __syncthreads();
    float t1 = 0.f, t2 = 0.f;
    #pragma unroll
    for (int i = 0; i < 8; i++) { t1 += red1[i]; t2 += red2[i]; }
    float mean = t1 * (1.f / DIM);
    float var = t2 * (1.f / DIM) - mean * mean;
    out[row * DIM + tid] = (x - mean) * rsqrtf(var + 1e-5f) * g[tid] + beta[tid];
}

// ---------------- deformable gather (float4, 2 heads per 64-lane group) ----------------
__global__ void deform_kernel(const float* __restrict__ bev, const float* __restrict__ ref) {
    int q = blockIdx.x, n = blockIdx.y;
    int nq = n * QN + q;
    __shared__ int sidx[128];
    __shared__ float swt[128];
    int tid = threadIdx.x;  // 256
    if (tid < 128) {
        int h = tid >> 4, s = tid & 15, p = s >> 2, c = s & 3;
        const float* awl = g_awl + nq * 32 + h * 4;
        float l0 = awl[0], l1 = awl[1], l2 = awl[2], l3 = awl[3];
        float mm = fmaxf(fmaxf(l0, l1), fmaxf(l2, l3));
        float e0 = __expf(l0 - mm), e1 = __expf(l1 - mm);
        float e2 = __expf(l2 - mm), e3 = __expf(l3 - mm);
        float es = 1.f / (e0 + e1 + e2 + e3);
        float awp = (p == 0 ? e0 : p == 1 ? e1 : p == 2 ? e2 : e3) * es;
        const float* off = g_offb + nq * 64 + h * 8;
        float x = ref[nq * 2 + 0] * (float)WBB + off[p * 2 + 0] - 0.5f;
        float y = ref[nq * 2 + 1] * (float)HBB + off[p * 2 + 1] - 0.5f;
        float x0f = floorf(x), y0f = floorf(y);
        float fx = x - x0f, fy = y - y0f;
        int dx = c & 1, dy = c >> 1;
        int xc = (int)x0f + dx, yc = (int)y0f + dy;
        float w = (dx ? fx : 1.f - fx) * (dy ? fy : 1.f - fy);
        bool valid = (xc >= 0) && (xc < WBB) && (yc >= 0) && (yc < HBB);
        float wf = valid ? awp * w : 0.f;
        int xcc = min(max(xc, 0), WBB - 1);
        int ycc = min(max(yc, 0), HBB - 1);
        sidx[tid] = ycc * WBB + xcc;
        swt[tid] = wf;
        float sw = wf;
        #pragma unroll
        for (int o = 1; o < 16; o <<= 1) sw += __shfl_xor_sync(0xffffffffu, sw, o);
        if (s == 0) g_sumw[nq * 8 + h] = sw;
    }
    __syncthreads();
    int sg = tid >> 6;
    int c4 = (tid & 63) << 2;
    const float* bevn = bev + (size_t)n * (HBB * WBB) * DIM;
    #pragma unroll
    for (int hh2 = 0; hh2 < 2; hh2++) {
        int h = sg * 2 + hh2;
        float4 a = make_float4(0.f, 0.f, 0.f, 0.f);
        #pragma unroll
        for (int s = 0; s < 16; s++) {
            float w = swt[h * 16 + s];
            if (w != 0.f) {
                float4 gv = *(const float4*)&bevn[(size_t)sidx[h * 16 + s] * DIM + c4];
                a.x += w * gv.x; a.y += w * gv.y; a.z += w * gv.z; a.w += w * gv.w;
            }
        }
        *(float4*)&g_agg[((size_t)nq * HH + h) * DIM + c4] = a;
    }
}

// ================= per-head projection on tensor cores =================
// 64m x 32n tile, 4 warps stacked in m (16 rows each), K=256.
__global__ void headgemm_kernel(const float* __restrict__ Wval, const float* __restrict__ bval) {
    int h = blockIdx.y;
    int bm = blockIdx.x * 64;
    __shared__ unsigned As[2][64 * ASTR];
    __shared__ unsigned Bs[2][16 * 36];
    int tid = threadIdx.x;          // 128
    int warp = tid >> 5, lane = tid & 31;
    int fr = lane >> 2, fc = lane & 3;
    float4 acc[4];
    #pragma unroll
    for (int i = 0; i < 4; i++) acc[i] = make_float4(0.f, 0.f, 0.f, 0.f);

    int am = tid >> 1;
    int ak = (tid & 1) * 8;
    bool avalid = (bm + am) < NQ;
    const float* Aptr = g_agg + ((size_t)(bm + am) * HH + h) * DIM + ak;
    int bk = tid >> 3;              // 0..15
    int bn4 = (tid & 7) * 4;
    const float* Wptr = Wval + (size_t)bk * DIM + h * HD + bn4;

    float4 xa0, xa1, yb;
    auto LDG = [&](int k0) {
        xa0 = make_float4(0.f, 0.f, 0.f, 0.f); xa1 = xa0;
        if (avalid) { xa0 = *(const float4*)(Aptr + k0); xa1 = *(const float4*)(Aptr + k0 + 4); }
        yb = *(const float4*)(Wptr + (size_t)k0 * DIM);
    };
    auto STS = [&](int buf) {
        uint4 u0 = make_uint4(f2tf(xa0.x), f2tf(xa0.y), f2tf(xa0.z), f2tf(xa0.w));
        uint4 u1 = make_uint4(f2tf(xa1.x), f2tf(xa1.y), f2tf(xa1.z), f2tf(xa1.w));
        *(uint4*)&As[buf][am * ASTR + ak] = u0;
        *(uint4*)&As[buf][am * ASTR + ak + 4] = u1;
        uint4 v = make_uint4(f2tf(yb.x), f2tf(yb.y), f2tf(yb.z), f2tf(yb.w));
        *(uint4*)&Bs[buf][bk * 36 + bn4] = v;
    };

    LDG(0); STS(0);
    __syncthreads();
    int buf = 0;
    for (int k0 = 16;; k0 += 16) {
        bool more = (k0 < DIM);
        if (more) LDG(k0);
        #pragma unroll
        for (int ks = 0; ks < 16; ks += 8) {
            const unsigned* ab = &As[buf][(warp * 16) * ASTR + ks];
            unsigned a0 = ab[fr * ASTR + fc];
            unsigned a1 = ab[(fr + 8) * ASTR + fc];
            unsigned a2 = ab[fr * ASTR + fc + 4];
            unsigned a3 = ab[(fr + 8) * ASTR + fc + 4];
            #pragma unroll
            for (int nt = 0; nt < 4; nt++) {
                unsigned b0 = Bs[buf][(ks + fc) * 36 + nt * 8 + fr];
                unsigned b1 = Bs[buf][(ks + fc + 4) * 36 + nt * 8 + fr];
                mma_tf32(acc[nt], a0, a1, a2, a3, b0, b1);
            }
        }
        if (!more) break;
        buf ^= 1;
        STS(buf);
        __syncthreads();
    }

    int m0 = bm + warp * 16 + fr;
    int m1 = m0 + 8;
    #pragma unroll
    for (int nt = 0; nt < 4; nt++) {
        int c = nt * 8 + 2 * fc;
        float bv0 = bval[h * HD + c], bv1 = bval[h * HD + c + 1];
        if (m0 < NQ) {
            float sw = g_sumw[m0 * HH + h];
            *(float2*)&g_ho[(size_t)m0 * DIM + h * HD + c] =
                make_float2(acc[nt].x + bv0 * sw, acc[nt].y + bv1 * sw);
        }
        if (m1 < NQ) {
            float sw = g_sumw[m1 * HH + h];
            *(float2*)&g_ho[(size_t)m1 * DIM + h * HD + c] =
                make_float2(acc[nt].z + bv0 * sw, acc[nt].w + bv1 * sw);
        }
    }
}

// ---------------- launch ----------------
static float* symaddr(const void* s) {
    void* p = nullptr;
    cudaGetSymbolAddress(&p, s);
    return (float*)p;
}

extern "C" void kernel_launch(void* const* d_in, const int* in_sizes, int n_in,
                              void* d_out, int out_size) {
    const float* queries = (const float*)d_in[0];
    const float* bev     = (const float*)d_in[1];
    const float* refp    = (const float*)d_in[2];
    const float* og      = (const float*)d_in[3];
    const float* mask    = (const float*)d_in[4];
    const float* Wq = (const float*)d_in[5];  const float* bq = (const float*)d_in[6];
    const float* Wk = (const float*)d_in[7];  const float* bk = (const float*)d_in[8];
    const float* Wv = (const float*)d_in[9];  const float* bv = (const float*)d_in[10];
    const float* Wo = (const float*)d_in[11]; const float* bo = (const float*)d_in[12];
    const float* ln1g = (const float*)d_in[13]; const float* ln1b = (const float*)d_in[14];
    const float* Wval = (const float*)d_in[15]; const float* bval = (const float*)d_in[16];
    const float* Woff = (const float*)d_in[17]; const float* boff = (const float*)d_in[18];
    const float* Wattn = (const float*)d_in[19]; const float* battn = (const float*)d_in[20];
    const float* Wdo = (const float*)d_in[21]; const float* bdo = (const float*)d_in[22];
    const float* ln2g = (const float*)d_in[23]; const float* ln2b = (const float*)d_in[24];
    const float* W1 = (const float*)d_in[25]; const float* b1 = (const float*)d_in[26];
    const float* W2 = (const float*)d_in[27]; const float* b2 = (const float*)d_in[28];
    const float* ln3g = (const float*)d_in[29]; const float* ln3b = (const float*)d_in[30];
    float* out = (float*)d_out;

    float* pqk  = symaddr(g_qk);
    float* patt = symaddr(g_att);
    float* pout1 = symaddr(g_out1);
    float* pout2 = symaddr(g_out2);
    float* paug = symaddr(g_aug);
    float* pho  = symaddr(g_ho);
    float* pout3 = symaddr(g_out3);
    float* pout4 = symaddr(g_out4);
    float* pffn = symaddr(g_ffn);
    float* pout5 = symaddr(g_out5);

    // 1. q_and_k = queries + og
    add_kernel<<<NQ, 256>>>(queries, og, pqk);
    // 2. fused QKV projections (tf32)
    qkv_kernel<<<dim3(4, 57, 3), 128>>>(queries, Wq, bq, Wk, bk, Wv, bv);
    // 3. flash attention (tf32 tensor cores)
    flash_kernel<<<dim3(15, NZ), 128>>>(mask);
    // 4. output projection + LN1
    gemm_tf32_kernel<<<dim3(4, 57), 128>>>(patt, Wo, bo, pout1, NQ, DIM, DIM, 0, nullptr);
    add_ln_kernel<<<NQ, 256>>>(queries, pout1, ln1g, ln1b, pout2);
    // 5. deformable attention (projection commuted past sampling)
    add_kernel<<<NQ, 256>>>(pout2, og, paug);
    offattn_kernel<<<dim3(1, 57, 2), 128>>>(Woff, boff, Wattn, battn);
    deform_kernel<<<dim3(QN, NB), 256>>>(bev, refp);
    headgemm_kernel<<<dim3(57, HH), 128>>>(Wval, bval);
    gemm_tf32_kernel<<<dim3(4, 57), 128>>>(pho, Wdo, bdo, pout3, NQ, DIM, DIM, 0, mask);
    add_ln_kernel<<<NQ, 256>>>(pout2, pout3, ln2g, ln2b, pout4);
    // 6. FFN + LN3 (tf32)
    gemm_tf32_kernel<<<dim3(8, 57), 128>>>(pout4, W1, b1, pffn, NQ, FFD, DIM, 1, nullptr);
    gemm_tf32_kernel<<<dim3(4, 57), 128>>>(pffn, W2, b2, pout5, NQ, DIM, FFD, 0, nullptr);
    add_ln_kernel<<<NQ, 256>>>(pout4, pout5, ln3g, ln3b, out);
}

// round 8
// speedup vs baseline: 2.8591x; 1.0610x over previous
#include <cuda_runtime.h>
#include <math.h>

#define NB   4
#define QN   900
#define DIM  256
#define HH   8
#define HD   32
#define PP   4
#define HBB  200
#define WBB  200
#define FFD  512
#define NQ   (NB*QN)        // 3600
#define NZ   (NB*HH)        // 32

// ---------------- device scratch (static, allocation-free) ----------------
__device__ float g_qh [NQ*DIM];
__device__ float g_kh [NQ*DIM];
__device__ float g_vh [NQ*DIM];
__device__ float g_att [NQ*DIM];
__device__ float g_out1[NQ*DIM];
__device__ float g_out2[NQ*DIM];
__device__ float g_offb[NQ*64];
__device__ float g_awl [NQ*32];
__device__ float g_agg [(size_t)NQ*HH*DIM];    // ~29.5 MB
__device__ float g_sumw[NQ*HH];
__device__ float g_ho  [NQ*DIM];
__device__ float g_out3[NQ*DIM];
__device__ float g_out4[NQ*DIM];
__device__ float g_ffn [NQ*FFD];
__device__ float g_out5[NQ*DIM];

// ================= tf32 mma primitives =================
__device__ __forceinline__ unsigned f2tf(float x) {
    unsigned r;
    asm("cvt.rna.tf32.f32 %0, %1;" : "=r"(r) : "f"(x));
    return r;
}
__device__ __forceinline__ void mma_tf32(float4& d,
                                         unsigned a0, unsigned a1, unsigned a2, unsigned a3,
                                         unsigned b0, unsigned b1) {
    asm volatile("mma.sync.aligned.m16n8k8.row.col.f32.tf32.tf32.f32 "
                 "{%0,%1,%2,%3}, {%4,%5,%6,%7}, {%8,%9}, {%0,%1,%2,%3};"
                 : "+f"(d.x), "+f"(d.y), "+f"(d.z), "+f"(d.w)
                 : "r"(a0), "r"(a1), "r"(a2), "r"(a3), "r"(b0), "r"(b1));
}

#define ASTR 20
#define BSTR 72

// ================= tf32 GEMM v4: 128x64 tile, 256 threads (8 warps 4x2) ==========
// C = (A [+ A2]) @ W + bias [, relu][, rowscale]; K%16==0, N%64==0 within tile.
__device__ __forceinline__ void gemm_tf32_128(const float* __restrict__ A,
                                              const float* __restrict__ A2,
                                              const float* __restrict__ W,
                                              const float* __restrict__ bias,
                                              float* __restrict__ C,
                                              int M, int N, int K, int relu,
                                              const float* __restrict__ rowscale,
                                              int bm, int bn) {
    __shared__ unsigned As[2][128 * ASTR];
    __shared__ unsigned Bs[2][16 * BSTR];
    int tid = threadIdx.x;              // 256
    int warp = tid >> 5, lane = tid & 31;
    int wm = (warp & 3) * 32;
    int wn = (warp >> 2) * 32;
    int fr = lane >> 2, fc = lane & 3;
    float4 acc[2][4];
    #pragma unroll
    for (int i = 0; i < 2; i++)
        #pragma unroll
        for (int j = 0; j < 4; j++) acc[i][j] = make_float4(0.f, 0.f, 0.f, 0.f);

    int am = tid >> 1;                  // 0..127
    int ak = (tid & 1) * 8;
    bool avalid = (bm + am) < M;
    const float* Aptr  = A + (size_t)(bm + am) * K + ak;
    const float* A2ptr = A2 ? A2 + (size_t)(bm + am) * K + ak : (const float*)0;
    int bk = tid >> 4;                  // 0..15
    int bnc = (tid & 15) * 4;
    const float* Wptr = W + (size_t)bk * N + bn + bnc;

    float4 xa0, xa1, yb;
    auto LDG = [&](int k0) {
        xa0 = make_float4(0.f, 0.f, 0.f, 0.f); xa1 = xa0;
        if (avalid) {
            xa0 = *(const float4*)(Aptr + k0);
            xa1 = *(const float4*)(Aptr + k0 + 4);
            if (A2ptr) {
                float4 u0 = *(const float4*)(A2ptr + k0);
                float4 u1 = *(const float4*)(A2ptr + k0 + 4);
                xa0.x += u0.x; xa0.y += u0.y; xa0.z += u0.z; xa0.w += u0.w;
                xa1.x += u1.x; xa1.y += u1.y; xa1.z += u1.z; xa1.w += u1.w;
            }
        }
        yb = *(const float4*)(Wptr + (size_t)k0 * N);
    };
    auto STS = [&](int buf) {
        uint4 u0 = make_uint4(f2tf(xa0.x), f2tf(xa0.y), f2tf(xa0.z), f2tf(xa0.w));
        uint4 u1 = make_uint4(f2tf(xa1.x), f2tf(xa1.y), f2tf(xa1.z), f2tf(xa1.w));
        *(uint4*)&As[buf][am * ASTR + ak] = u0;
        *(uint4*)&As[buf][am * ASTR + ak + 4] = u1;
        uint4 v = make_uint4(f2tf(yb.x), f2tf(yb.y), f2tf(yb.z), f2tf(yb.w));
        *(uint4*)&Bs[buf][bk * BSTR + bnc] = v;
    };

    LDG(0); STS(0);
    __syncthreads();
    int buf = 0;
    for (int k0 = 16;; k0 += 16) {
        bool more = (k0 < K);
        if (more) LDG(k0);
        #pragma unroll
        for (int ks = 0; ks < 16; ks += 8) {
            unsigned af[2][4];
            #pragma unroll
            for (int mi = 0; mi < 2; mi++) {
                const unsigned* ab = &As[buf][(wm + mi * 16) * ASTR + ks];
                af[mi][0] = ab[fr * ASTR + fc];
                af[mi][1] = ab[(fr + 8) * ASTR + fc];
                af[mi][2] = ab[fr * ASTR + fc + 4];
                af[mi][3] = ab[(fr + 8) * ASTR + fc + 4];
            }
            unsigned bf[4][2];
            #pragma unroll
            for (int ni = 0; ni < 4; ni++) {
                const unsigned* bb = &Bs[buf][ks * BSTR + wn + ni * 8 + fr];
                bf[ni][0] = bb[fc * BSTR];
                bf[ni][1] = bb[(fc + 4) * BSTR];
            }
            #pragma unroll
            for (int mi = 0; mi < 2; mi++)
                #pragma unroll
                for (int ni = 0; ni < 4; ni++)
                    mma_tf32(acc[mi][ni], af[mi][0], af[mi][1], af[mi][2], af[mi][3],
                             bf[ni][0], bf[ni][1]);
        }
        if (!more) break;
        buf ^= 1;
        STS(buf);
        __syncthreads();
    }

    int c2 = fc * 2;
    #pragma unroll
    for (int ni = 0; ni < 4; ni++) {
        int n = bn + wn + ni * 8 + c2;
        float b0 = 0.f, b1 = 0.f;
        if (bias) { b0 = bias[n]; b1 = bias[n + 1]; }
        #pragma unroll
        for (int mi = 0; mi < 2; mi++) {
            float4 d = acc[mi][ni];
            int m0 = bm + wm + mi * 16 + fr;
            int m1 = m0 + 8;
            if (m0 < M) {
                float rs = rowscale ? rowscale[m0] : 1.f;
                float o0 = d.x + b0, o1 = d.y + b1;
                if (relu) { o0 = fmaxf(o0, 0.f); o1 = fmaxf(o1, 0.f); }
                *(float2*)&C[(size_t)m0 * N + n] = make_float2(o0 * rs, o1 * rs);
            }
            if (m1 < M) {
                float rs = rowscale ? rowscale[m1] : 1.f;
                float o0 = d.z + b0, o1 = d.w + b1;
                if (relu) { o0 = fmaxf(o0, 0.f); o1 = fmaxf(o1, 0.f); }
                *(float2*)&C[(size_t)m1 * N + n] = make_float2(o0 * rs, o1 * rs);
            }
        }
    }
}

__global__ void gemm_tf32_kernel(const float* __restrict__ A, const float* __restrict__ W,
                                 const float* __restrict__ bias, float* __restrict__ C,
                                 int M, int N, int K, int relu,
                                 const float* __restrict__ rowscale) {
    gemm_tf32_128(A, nullptr, W, bias, C, M, N, K, relu, rowscale,
                  blockIdx.y * 128, blockIdx.x * 64);
}

// merged QKV projection with fused residual add: z=0 -> qh, z=1 -> kh (A=queries+og),
// z=2 -> vh (A=queries)
__global__ void qkv_kernel(const float* __restrict__ queries, const float* __restrict__ og,
                           const float* __restrict__ Wq, const float* __restrict__ bq,
                           const float* __restrict__ Wk, const float* __restrict__ bk,
                           const float* __restrict__ Wv, const float* __restrict__ bv) {
    int z = blockIdx.z;
    const float* A2 = (z == 2) ? nullptr : og;
    const float* W = (z == 0) ? Wq : (z == 1) ? Wk : Wv;
    const float* bias = (z == 0) ? bq : (z == 1) ? bk : bv;
    float* C = (z == 0) ? g_qh : (z == 1) ? g_kh : g_vh;
    gemm_tf32_128(queries, A2, W, bias, C, NQ, DIM, DIM, 0, nullptr,
                  blockIdx.y * 128, blockIdx.x * 64);
}

// ---------------- SIMT GEMM with optional fused A2 add (small-N projections) -------
__device__ __forceinline__ void gemm_v3(const float* __restrict__ A,
                                        const float* __restrict__ A2,
                                        const float* __restrict__ W,
                                        const float* __restrict__ bias,
                                        float* __restrict__ C,
                                        int M, int N, int K, int relu,
                                        int bm, int bn) {
    __shared__ float As[2][16][68];
    __shared__ float Bs[2][16][68];
    int tid = threadIdx.x;          // 128
    int ty = tid >> 4, tx = tid & 15;
    int am = tid & 63;
    int ak = (tid >> 6) << 3;
    int br = tid >> 4;
    int bn4 = (tid & 15) << 2;
    float acc[8][4] = {};

    int m_a = bm + am;
    int n_b = bn + bn4;
    bool avalid = m_a < M;
    bool bvalid = n_b < N;
    const float* Arow = A + (size_t)m_a * K + ak;
    const float* A2row = A2 ? A2 + (size_t)m_a * K + ak : (const float*)0;

    float4 a0, a1, b0, b1;
    auto LDGS = [&](int k0) {
        a0 = make_float4(0.f,0.f,0.f,0.f); a1 = a0; b0 = a0; b1 = a0;
        if (avalid) {
            a0 = *(const float4*)(Arow + k0);
            a1 = *(const float4*)(Arow + k0 + 4);
            if (A2row) {
                float4 u0 = *(const float4*)(A2row + k0);
                float4 u1 = *(const float4*)(A2row + k0 + 4);
                a0.x += u0.x; a0.y += u0.y; a0.z += u0.z; a0.w += u0.w;
                a1.x += u1.x; a1.y += u1.y; a1.z += u1.z; a1.w += u1.w;
            }
        }
        if (bvalid) {
            b0 = *(const float4*)&W[(size_t)(k0 + br) * N + n_b];
            b1 = *(const float4*)&W[(size_t)(k0 + br + 8) * N + n_b];
        }
    };
    auto STSS = [&](int buf) {
        float av[8] = {a0.x,a0.y,a0.z,a0.w,a1.x,a1.y,a1.z,a1.w};
        #pragma unroll
        for (int i = 0; i < 8; i++) As[buf][ak + i][am] = av[i];
        *(float4*)&Bs[buf][br][bn4] = b0;
        *(float4*)&Bs[buf][br + 8][bn4] = b1;
    };

    LDGS(0); STSS(0);
    __syncthreads();
    int buf = 0;
    for (int k0 = 16;; k0 += 16) {
        bool more = (k0 < K);
        if (more) LDGS(k0);
        #pragma unroll
        for (int kk = 0; kk < 16; kk++) {
            float4 x0 = *(const float4*)&As[buf][kk][ty * 8];
            float4 x1 = *(const float4*)&As[buf][kk][ty * 8 + 4];
            float4 y  = *(const float4*)&Bs[buf][kk][tx * 4];
            float a[8] = {x0.x,x0.y,x0.z,x0.w,x1.x,x1.y,x1.z,x1.w};
            float b[4] = {y.x,y.y,y.z,y.w};
            #pragma unroll
            for (int i = 0; i < 8; i++)
                #pragma unroll
                for (int j = 0; j < 4; j++) acc[i][j] += a[i] * b[j];
        }
        if (!more) break;
        buf ^= 1;
        STSS(buf);
        __syncthreads();
    }

    int n = bn + tx * 4;
    if (n < N) {
        float4 bb = make_float4(0.f,0.f,0.f,0.f);
        if (bias) bb = *(const float4*)&bias[n];
        #pragma unroll
        for (int i = 0; i < 8; i++) {
            int m = bm + ty * 8 + i;
            if (m >= M) continue;
            float4 o;
            o.x = acc[i][0] + bb.x; o.y = acc[i][1] + bb.y;
            o.z = acc[i][2] + bb.z; o.w = acc[i][3] + bb.w;
            if (relu) {
                o.x = fmaxf(o.x, 0.f); o.y = fmaxf(o.y, 0.f);
                o.z = fmaxf(o.z, 0.f); o.w = fmaxf(o.w, 0.f);
            }
            *(float4*)&C[(size_t)m * N + n] = o;
        }
    }
}

// merged offset + attention-logit projections with fused aug = out2 + og
__global__ void offattn_kernel(const float* __restrict__ og,
                               const float* __restrict__ Woff, const float* __restrict__ boff,
                               const float* __restrict__ Wattn, const float* __restrict__ battn) {
    if (blockIdx.z == 0)
        gemm_v3(g_out2, og, Woff, boff, g_offb, NQ, 64, DIM, 0, blockIdx.y * 64, 0);
    else
        gemm_v3(g_out2, og, Wattn, battn, g_awl, NQ, 32, DIM, 0, blockIdx.y * 64, 0);
}

// ================= flash attention on tensor cores (q-tile 128, 256 thr) ==========
__global__ void flash_kernel(const float* __restrict__ mask) {
    int z = blockIdx.y, b = z >> 3, h = z & 7;
    int q0 = blockIdx.x * 128;
    __shared__ float    Qs[128 * 36];
    __shared__ unsigned Ks[64 * 36];    // [key][d] tf32
    __shared__ unsigned VsT[32 * 68];   // [d][key] tf32
    __shared__ float    Ms[64];
    int tid = threadIdx.x;              // 256
    int warp = tid >> 5, lane = tid & 31;
    int fr = lane >> 2, fc = lane & 3;
    const float scale = 0.17677669529663687f;  // 1/sqrt(32)

    // stage Q tile (fp32, zero-padded): 128 rows x 32 d
    {
        int row = tid >> 1, d0 = (tid & 1) * 16;
        int gq = q0 + row;
        float4 v[4];
        #pragma unroll
        for (int i = 0; i < 4; i++) v[i] = make_float4(0.f, 0.f, 0.f, 0.f);
        if (gq < QN) {
            const float* p = &g_qh[(size_t)(b * QN + gq) * DIM + h * HD + d0];
            #pragma unroll
            for (int i = 0; i < 4; i++) v[i] = *(const float4*)(p + i * 4);
        }
        #pragma unroll
        for (int i = 0; i < 4; i++) *(float4*)&Qs[row * 36 + d0 + i * 4] = v[i];
    }
    __syncthreads();

    // Q fragments -> registers (tf32), 4 k-steps; warp owns rows warp*16..+15
    unsigned aq[4][4];
    {
        int r0 = warp * 16 + fr;
        #pragma unroll
        for (int ks = 0; ks < 4; ks++) {
            aq[ks][0] = f2tf(Qs[r0 * 36 + ks * 8 + fc]);
            aq[ks][1] = f2tf(Qs[(r0 + 8) * 36 + ks * 8 + fc]);
            aq[ks][2] = f2tf(Qs[r0 * 36 + ks * 8 + fc + 4]);
            aq[ks][3] = f2tf(Qs[(r0 + 8) * 36 + ks * 8 + fc + 4]);
        }
    }

    // K/V register prefetch: 256 threads, 64 keys x 32 d, 8 floats each
    int lk = tid >> 2, ld = (tid & 3) * 8;
    float4 pk0, pk1, pv0, pv1;
    float pm = 0.f;
    auto LOADT = [&](int k0) {
        int gk = k0 + lk;
        pk0 = make_float4(0.f,0.f,0.f,0.f); pk1 = pk0; pv0 = pk0; pv1 = pk0;
        if (gk < QN) {
            const float* kp = &g_kh[(size_t)(b * QN + gk) * DIM + h * HD + ld];
            const float* vp = &g_vh[(size_t)(b * QN + gk) * DIM + h * HD + ld];
            pk0 = *(const float4*)kp; pk1 = *(const float4*)(kp + 4);
            pv0 = *(const float4*)vp; pv1 = *(const float4*)(vp + 4);
        }
        if (tid < 64) pm = (k0 + tid < QN) ? mask[b * QN + k0 + tid] : 0.f;
    };
    auto STORET = [&]() {
        uint4 u0 = make_uint4(f2tf(pk0.x), f2tf(pk0.y), f2tf(pk0.z), f2tf(pk0.w));
        uint4 u1 = make_uint4(f2tf(pk1.x), f2tf(pk1.y), f2tf(pk1.z), f2tf(pk1.w));
        *(uint4*)&Ks[lk * 36 + ld] = u0;
        *(uint4*)&Ks[lk * 36 + ld + 4] = u1;
        VsT[(ld + 0) * 68 + lk] = f2tf(pv0.x);
        VsT[(ld + 1) * 68 + lk] = f2tf(pv0.y);
        VsT[(ld + 2) * 68 + lk] = f2tf(pv0.z);
        VsT[(ld + 3) * 68 + lk] = f2tf(pv0.w);
        VsT[(ld + 4) * 68 + lk] = f2tf(pv1.x);
        VsT[(ld + 5) * 68 + lk] = f2tf(pv1.y);
        VsT[(ld + 6) * 68 + lk] = f2tf(pv1.z);
        VsT[(ld + 7) * 68 + lk] = f2tf(pv1.w);
        if (tid < 64) Ms[tid] = pm;
    };

    float m0 = -3.0e38f, m1 = -3.0e38f, l0 = 0.f, l1 = 0.f;
    float4 o[4];
    #pragma unroll
    for (int i = 0; i < 4; i++) o[i] = make_float4(0.f, 0.f, 0.f, 0.f);

    LOADT(0); STORET(); __syncthreads();
    const int NT = (QN + 63) / 64;  // 15
    for (int t = 0; t < NT; t++) {
        int k0 = t * 64;
        bool more = (t + 1) < NT;
        if (more) LOADT(k0 + 64);

        // S = Q @ K^T : 8 n-tiles x 4 k-steps
        float4 s[8];
        #pragma unroll
        for (int nt = 0; nt < 8; nt++) s[nt] = make_float4(0.f, 0.f, 0.f, 0.f);
        #pragma unroll
        for (int ks = 0; ks < 4; ks++) {
            #pragma unroll
            for (int nt = 0; nt < 8; nt++) {
                unsigned b0 = Ks[(nt * 8 + fr) * 36 + ks * 8 + fc];
                unsigned b1 = Ks[(nt * 8 + fr) * 36 + ks * 8 + fc + 4];
                mma_tf32(s[nt], aq[ks][0], aq[ks][1], aq[ks][2], aq[ks][3], b0, b1);
            }
        }

        // scale + mask + row max (rows fr, fr+8; quad-lane reduce)
        float rm0 = -3.0e38f, rm1 = -3.0e38f;
        #pragma unroll
        for (int nt = 0; nt < 8; nt++) {
            int kx = k0 + nt * 8 + 2 * fc;
            float mx = Ms[nt * 8 + 2 * fc], my = Ms[nt * 8 + 2 * fc + 1];
            float4 v = s[nt];
            v.x = (kx     < QN) ? (mx > 0.f ? v.x * scale : -1e9f) : -1e30f;
            v.y = (kx + 1 < QN) ? (my > 0.f ? v.y * scale : -1e9f) : -1e30f;
            v.z = (kx     < QN) ? (mx > 0.f ? v.z * scale : -1e9f) : -1e30f;
            v.w = (kx + 1 < QN) ? (my > 0.f ? v.w * scale : -1e9f) : -1e30f;
            s[nt] = v;
            rm0 = fmaxf(rm0, fmaxf(v.x, v.y));
            rm1 = fmaxf(rm1, fmaxf(v.z, v.w));
        }
        rm0 = fmaxf(rm0, __shfl_xor_sync(0xffffffffu, rm0, 1));
        rm0 = fmaxf(rm0, __shfl_xor_sync(0xffffffffu, rm0, 2));
        rm1 = fmaxf(rm1, __shfl_xor_sync(0xffffffffu, rm1, 1));
        rm1 = fmaxf(rm1, __shfl_xor_sync(0xffffffffu, rm1, 2));

        float mn0 = fmaxf(m0, rm0), mn1 = fmaxf(m1, rm1);
        float f0 = __expf(m0 - mn0), f1 = __expf(m1 - mn1);
        m0 = mn0; m1 = mn1;
        #pragma unroll
        for (int i = 0; i < 4; i++) { o[i].x *= f0; o[i].y *= f0; o[i].z *= f1; o[i].w *= f1; }

        float rs0 = 0.f, rs1 = 0.f;
        #pragma unroll
        for (int nt = 0; nt < 8; nt++) {
            float4 v = s[nt];
            v.x = __expf(v.x - mn0); v.y = __expf(v.y - mn0);
            v.z = __expf(v.z - mn1); v.w = __expf(v.w - mn1);
            s[nt] = v;
            rs0 += v.x + v.y; rs1 += v.z + v.w;
        }
        rs0 += __shfl_xor_sync(0xffffffffu, rs0, 1);
        rs0 += __shfl_xor_sync(0xffffffffu, rs0, 2);
        rs1 += __shfl_xor_sync(0xffffffffu, rs1, 1);
        rs1 += __shfl_xor_sync(0xffffffffu, rs1, 2);
        l0 = l0 * f0 + rs0;
        l1 = l1 * f1 + rs1;

        // O += P @ V : convert C-frag -> A-frag via shfl, then mma
        int srcA = (lane & ~3) | (fc >> 1);
        int srcB = srcA | 2;
        bool odd = (fc & 1);
        #pragma unroll
        for (int ks = 0; ks < 8; ks++) {
            float4 c = s[ks];
            float y0 = __shfl_sync(0xffffffffu, c.x, srcA);
            float y1 = __shfl_sync(0xffffffffu, c.y, srcA);
            float z0 = __shfl_sync(0xffffffffu, c.x, srcB);
            float z1 = __shfl_sync(0xffffffffu, c.y, srcB);
            float y2 = __shfl_sync(0xffffffffu, c.z, srcA);
            float y3 = __shfl_sync(0xffffffffu, c.w, srcA);
            float z2 = __shfl_sync(0xffffffffu, c.z, srcB);
            float z3 = __shfl_sync(0xffffffffu, c.w, srcB);
            unsigned a0 = f2tf(odd ? y1 : y0);
            unsigned a1 = f2tf(odd ? y3 : y2);
            unsigned a2 = f2tf(odd ? z1 : z0);
            unsigned a3 = f2tf(odd ? z3 : z2);
            #pragma unroll
            for (int dt = 0; dt < 4; dt++) {
                unsigned b0 = VsT[(dt * 8 + fr) * 68 + ks * 8 + fc];
                unsigned b1 = VsT[(dt * 8 + fr) * 68 + ks * 8 + fc + 4];
                mma_tf32(o[dt], a0, a1, a2, a3, b0, b1);
            }
        }
        __syncthreads();
        if (more) { STORET(); __syncthreads(); }
    }

    // epilogue
    float inv0 = 1.f / l0, inv1 = 1.f / l1;
    int qr0 = q0 + warp * 16 + fr;
    int qr1 = qr0 + 8;
    #pragma unroll
    for (int dt = 0; dt < 4; dt++) {
        int d = h * HD + dt * 8 + 2 * fc;
        if (qr0 < QN)
            *(float2*)&g_att[(size_t)(b * QN + qr0) * DIM + d] = make_float2(o[dt].x * inv0, o[dt].y * inv0);
        if (qr1 < QN)
            *(float2*)&g_att[(size_t)(b * QN + qr1) * DIM + d] = make_float2(o[dt].z * inv1, o[dt].w * inv1);
    }
}

// ---------------- add + layernorm (256-d rows) ----------------
__global__ void add_ln_kernel(const float* __restrict__ A, const float* __restrict__ B,
                              const float* __restrict__ g, const float* __restrict__ beta,
                              float* __restrict__ out) {
    int row = blockIdx.x, tid = threadIdx.x;
    float x = A[row * DIM + tid] + B[row * DIM + tid];
    __shared__ float red1[8], red2[8];
    float s1 = x, s2 = x * x;
    for (int o = 16; o; o >>= 1) {
        s1 += __shfl_xor_sync(0xffffffffu, s1, o);
        s2 += __shfl_xor_sync(0xffffffffu, s2, o);
    }
    if ((tid & 31) == 0) { red1[tid >> 5] = s1; red2[tid >> 5] = s2; }
    __syncthreads();
    float t1 = 0.f, t2 = 0.f;
    #pragma unroll
    for (int i = 0; i < 8; i++) { t1 += red1[i]; t2 += red2[i]; }
    float mean = t1 * (1.f / DIM);
    float var = t2 * (1.f / DIM) - mean * mean;
    out[row * DIM + tid] = (x - mean) * rsqrtf(var + 1e-5f) * g[tid] + beta[tid];
}

// ---------------- deformable gather (float4, 2 heads per 64-lane group) ----------------
__global__ void deform_kernel(const float* __restrict__ bev, const float* __restrict__ ref) {
    int q = blockIdx.x, n = blockIdx.y;
    int nq = n * QN + q;
    __shared__ int sidx[128];
    __shared__ float swt[128];
    int tid = threadIdx.x;  // 256
    if (tid < 128) {
        int h = tid >> 4, s = tid & 15, p = s >> 2, c = s & 3;
        const float* awl = g_awl + nq * 32 + h * 4;
        float l0 = awl[0], l1 = awl[1], l2 = awl[2], l3 = awl[3];
        float mm = fmaxf(fmaxf(l0, l1), fmaxf(l2, l3));
        float e0 = __expf(l0 - mm), e1 = __expf(l1 - mm);
        float e2 = __expf(l2 - mm), e3 = __expf(l3 - mm);
        float es = 1.f / (e0 + e1 + e2 + e3);
        float awp = (p == 0 ? e0 : p == 1 ? e1 : p == 2 ? e2 : e3) * es;
        const float* off = g_offb + nq * 64 + h * 8;
        float x = ref[nq * 2 + 0] * (float)WBB + off[p * 2 + 0] - 0.5f;
        float y = ref[nq * 2 + 1] * (float)HBB + off[p * 2 + 1] - 0.5f;
        float x0f = floorf(x), y0f = floorf(y);
        float fx = x - x0f, fy = y - y0f;
        int dx = c & 1, dy = c >> 1;
        int xc = (int)x0f + dx, yc = (int)y0f + dy;
        float w = (dx ? fx : 1.f - fx) * (dy ? fy : 1.f - fy);
        bool valid = (xc >= 0) && (xc < WBB) && (yc >= 0) && (yc < HBB);
        float wf = valid ? awp * w : 0.f;
        int xcc = min(max(xc, 0), WBB - 1);
        int ycc = min(max(yc, 0), HBB - 1);
        sidx[tid] = ycc * WBB + xcc;
        swt[tid] = wf;
        float sw = wf;
        #pragma unroll
        for (int o = 1; o < 16; o <<= 1) sw += __shfl_xor_sync(0xffffffffu, sw, o);
        if (s == 0) g_sumw[nq * 8 + h] = sw;
    }
    __syncthreads();
    int sg = tid >> 6;
    int c4 = (tid & 63) << 2;
    const float* bevn = bev + (size_t)n * (HBB * WBB) * DIM;
    #pragma unroll
    for (int hh2 = 0; hh2 < 2; hh2++) {
        int h = sg * 2 + hh2;
        float4 a = make_float4(0.f, 0.f, 0.f, 0.f);
        #pragma unroll
        for (int s = 0; s < 16; s++) {
            float w = swt[h * 16 + s];
            if (w != 0.f) {
                float4 gv = *(const float4*)&bevn[(size_t)sidx[h * 16 + s] * DIM + c4];
                a.x += w * gv.x; a.y += w * gv.y; a.z += w * gv.z; a.w += w * gv.w;
            }
        }
        *(float4*)&g_agg[((size_t)nq * HH + h) * DIM + c4] = a;
    }
}

// ================= per-head projection on tensor cores =================
// 64m x 32n tile, 4 warps stacked in m (16 rows each), K=256.
__global__ void headgemm_kernel(const float* __restrict__ Wval, const float* __restrict__ bval) {
    int h = blockIdx.y;
    int bm = blockIdx.x * 64;
    __shared__ unsigned As[2][64 * ASTR];
    __shared__ unsigned Bs[2][16 * 36];
    int tid = threadIdx.x;          // 128
    int warp = tid >> 5, lane = tid & 31;
    int fr = lane >> 2, fc = lane & 3;
    float4 acc[4];
    #pragma unroll
    for (int i = 0; i < 4; i++) acc[i] = make_float4(0.f, 0.f, 0.f, 0.f);

    int am = tid >> 1;
    int ak = (tid & 1) * 8;
    bool avalid = (bm + am) < NQ;
    const float* Aptr = g_agg + ((size_t)(bm + am) * HH + h) * DIM + ak;
    int bk = tid >> 3;              // 0..15
    int bn4 = (tid & 7) * 4;
    const float* Wptr = Wval + (size_t)bk * DIM + h * HD + bn4;

    float4 xa0, xa1, yb;
    auto LDG = [&](int k0) {
        xa0 = make_float4(0.f, 0.f, 0.f, 0.f); xa1 = xa0;
        if (avalid) { xa0 = *(const float4*)(Aptr + k0); xa1 = *(const float4*)(Aptr + k0 + 4); }
        yb = *(const float4*)(Wptr + (size_t)k0 * DIM);
    };
    auto STS = [&](int buf) {
        uint4 u0 = make_uint4(f2tf(xa0.x), f2tf(xa0.y), f2tf(xa0.z), f2tf(xa0.w));
        uint4 u1 = make_uint4(f2tf(xa1.x), f2tf(xa1.y), f2tf(xa1.z), f2tf(xa1.w));
        *(uint4*)&As[buf][am * ASTR + ak] = u0;
        *(uint4*)&As[buf][am * ASTR + ak + 4] = u1;
        uint4 v = make_uint4(f2tf(yb.x), f2tf(yb.y), f2tf(yb.z), f2tf(yb.w));
        *(uint4*)&Bs[buf][bk * 36 + bn4] = v;
    };

    LDG(0); STS(0);
    __syncthreads();
    int buf = 0;
    for (int k0 = 16;; k0 += 16) {
        bool more = (k0 < DIM);
        if (more) LDG(k0);
        #pragma unroll
        for (int ks = 0; ks < 16; ks += 8) {
            const unsigned* ab = &As[buf][(warp * 16) * ASTR + ks];
            unsigned a0 = ab[fr * ASTR + fc];
            unsigned a1 = ab[(fr + 8) * ASTR + fc];
            unsigned a2 = ab[fr * ASTR + fc + 4];
            unsigned a3 = ab[(fr + 8) * ASTR + fc + 4];
            #pragma unroll
            for (int nt = 0; nt < 4; nt++) {
                unsigned b0 = Bs[buf][(ks + fc) * 36 + nt * 8 + fr];
                unsigned b1 = Bs[buf][(ks + fc + 4) * 36 + nt * 8 + fr];
                mma_tf32(acc[nt], a0, a1, a2, a3, b0, b1);
            }
        }
        if (!more) break;
        buf ^= 1;
        STS(buf);
        __syncthreads();
    }

    int m0 = bm + warp * 16 + fr;
    int m1 = m0 + 8;
    #pragma unroll
    for (int nt = 0; nt < 4; nt++) {
        int c = nt * 8 + 2 * fc;
        float bv0 = bval[h * HD + c], bv1 = bval[h * HD + c + 1];
        if (m0 < NQ) {
            float sw = g_sumw[m0 * HH + h];
            *(float2*)&g_ho[(size_t)m0 * DIM + h * HD + c] =
                make_float2(acc[nt].x + bv0 * sw, acc[nt].y + bv1 * sw);
        }
        if (m1 < NQ) {
            float sw = g_sumw[m1 * HH + h];
            *(float2*)&g_ho[(size_t)m1 * DIM + h * HD + c] =
                make_float2(acc[nt].z + bv0 * sw, acc[nt].w + bv1 * sw);
        }
    }
}

// ---------------- launch ----------------
static float* symaddr(const void* s) {
    void* p = nullptr;
    cudaGetSymbolAddress(&p, s);
    return (float*)p;
}

extern "C" void kernel_launch(void* const* d_in, const int* in_sizes, int n_in,
                              void* d_out, int out_size) {
    const float* queries = (const float*)d_in[0];
    const float* bev     = (const float*)d_in[1];
    const float* refp    = (const float*)d_in[2];
    const float* og      = (const float*)d_in[3];
    const float* mask    = (const float*)d_in[4];
    const float* Wq = (const float*)d_in[5];  const float* bq = (const float*)d_in[6];
    const float* Wk = (const float*)d_in[7];  const float* bk = (const float*)d_in[8];
    const float* Wv = (const float*)d_in[9];  const float* bv = (const float*)d_in[10];
    const float* Wo = (const float*)d_in[11]; const float* bo = (const float*)d_in[12];
    const float* ln1g = (const float*)d_in[13]; const float* ln1b = (const float*)d_in[14];
    const float* Wval = (const float*)d_in[15]; const float* bval = (const float*)d_in[16];
    const float* Woff = (const float*)d_in[17]; const float* boff = (const float*)d_in[18];
    const float* Wattn = (const float*)d_in[19]; const float* battn = (const float*)d_in[20];
    const float* Wdo = (const float*)d_in[21]; const float* bdo = (const float*)d_in[22];
    const float* ln2g = (const float*)d_in[23]; const float* ln2b = (const float*)d_in[24];
    const float* W1 = (const float*)d_in[25]; const float* b1 = (const float*)d_in[26];
    const float* W2 = (const float*)d_in[27]; const float* b2 = (const float*)d_in[28];
    const float* ln3g = (const float*)d_in[29]; const float* ln3b = (const float*)d_in[30];
    float* out = (float*)d_out;

    float* patt = symaddr(g_att);
    float* pout1 = symaddr(g_out1);
    float* pout2 = symaddr(g_out2);
    float* pho  = symaddr(g_ho);
    float* pout3 = symaddr(g_out3);
    float* pout4 = symaddr(g_out4);
    float* pffn = symaddr(g_ffn);
    float* pout5 = symaddr(g_out5);

    // 1. QKV projections with fused q_and_k = queries + og
    qkv_kernel<<<dim3(4, 29, 3), 256>>>(queries, og, Wq, bq, Wk, bk, Wv, bv);
    // 2. flash attention (tf32 tensor cores, q-tile 128)
    flash_kernel<<<dim3(8, NZ), 256>>>(mask);
    // 3. output projection + LN1
    gemm_tf32_kernel<<<dim3(4, 29), 256>>>(patt, Wo, bo, pout1, NQ, DIM, DIM, 0, nullptr);
    add_ln_kernel<<<NQ, 256>>>(queries, pout1, ln1g, ln1b, pout2);
    // 4. deformable attention (projection commuted past sampling; aug fused)
    offattn_kernel<<<dim3(1, 57, 2), 128>>>(og, Woff, boff, Wattn, battn);
    deform_kernel<<<dim3(QN, NB), 256>>>(bev, refp);
    headgemm_kernel<<<dim3(57, HH), 128>>>(Wval, bval);
    gemm_tf32_kernel<<<dim3(4, 29), 256>>>(pho, Wdo, bdo, pout3, NQ, DIM, DIM, 0, mask);
    add_ln_kernel<<<NQ, 256>>>(pout2, pout3, ln2g, ln2b, pout4);
    // 5. FFN + LN3
    gemm_tf32_kernel<<<dim3(8, 29), 256>>>(pout4, W1, b1, pffn, NQ, FFD, DIM, 1, nullptr);
    gemm_tf32_kernel<<<dim3(4, 29), 256>>>(pffn, W2, b2, pout5, NQ, DIM, FFD, 0, nullptr);
    add_ln_kernel<<<NQ, 256>>>(pout4, pout5, ln3g, ln3b, out);
}

// round 9
// speedup vs baseline: 2.9619x; 1.0359x over previous
#include <cuda_runtime.h>
#include <math.h>

#define NB   4
#define QN   900
#define DIM  256
#define HH   8
#define HD   32
#define PP   4
#define HBB  200
#define WBB  200
#define FFD  512
#define NQ   (NB*QN)        // 3600
#define NZ   (NB*HH)        // 32

// ---------------- device scratch (static, allocation-free) ----------------
__device__ float g_qh [NQ*DIM];
__device__ float g_kh [NQ*DIM];
__device__ float g_vh [NQ*DIM];
__device__ float g_att [NQ*DIM];
__device__ float g_out1[NQ*DIM];
__device__ float g_out2[NQ*DIM];
__device__ float g_offawl[NQ*128];             // cols 0..63 offsets, 64..95 attn logits
__device__ float g_woa[DIM*128];
__device__ float g_boa[128];
__device__ float g_agg [(size_t)NQ*HH*DIM];    // ~29.5 MB
__device__ float g_sumw[NQ*HH];
__device__ float g_ho  [NQ*DIM];
__device__ float g_out3[NQ*DIM];
__device__ float g_out4[NQ*DIM];
__device__ float g_ffn [NQ*FFD];
__device__ float g_out5[NQ*DIM];

// ================= tf32 mma primitives =================
__device__ __forceinline__ unsigned f2tf(float x) {
    unsigned r;
    asm("cvt.rna.tf32.f32 %0, %1;" : "=r"(r) : "f"(x));
    return r;
}
__device__ __forceinline__ void mma_tf32(float4& d,
                                         unsigned a0, unsigned a1, unsigned a2, unsigned a3,
                                         unsigned b0, unsigned b1) {
    asm volatile("mma.sync.aligned.m16n8k8.row.col.f32.tf32.tf32.f32 "
                 "{%0,%1,%2,%3}, {%4,%5,%6,%7}, {%8,%9}, {%0,%1,%2,%3};"
                 : "+f"(d.x), "+f"(d.y), "+f"(d.z), "+f"(d.w)
                 : "r"(a0), "r"(a1), "r"(a2), "r"(a3), "r"(b0), "r"(b1));
}

#define ASTR 20
#define BSTR 72

// ================= tf32 GEMM v4: 128x64 tile, 256 threads (8 warps 4x2) ==========
__device__ __forceinline__ void gemm_tf32_128(const float* __restrict__ A,
                                              const float* __restrict__ A2,
                                              const float* __restrict__ W,
                                              const float* __restrict__ bias,
                                              float* __restrict__ C,
                                              int M, int N, int K, int relu,
                                              const float* __restrict__ rowscale,
                                              int bm, int bn) {
    __shared__ unsigned As[2][128 * ASTR];
    __shared__ unsigned Bs[2][16 * BSTR];
    int tid = threadIdx.x;              // 256
    int warp = tid >> 5, lane = tid & 31;
    int wm = (warp & 3) * 32;
    int wn = (warp >> 2) * 32;
    int fr = lane >> 2, fc = lane & 3;
    float4 acc[2][4];
    #pragma unroll
    for (int i = 0; i < 2; i++)
        #pragma unroll
        for (int j = 0; j < 4; j++) acc[i][j] = make_float4(0.f, 0.f, 0.f, 0.f);

    int am = tid >> 1;                  // 0..127
    int ak = (tid & 1) * 8;
    bool avalid = (bm + am) < M;
    const float* Aptr  = A + (size_t)(bm + am) * K + ak;
    const float* A2ptr = A2 ? A2 + (size_t)(bm + am) * K + ak : (const float*)0;
    int bk = tid >> 4;                  // 0..15
    int bnc = (tid & 15) * 4;
    const float* Wptr = W + (size_t)bk * N + bn + bnc;

    float4 xa0, xa1, yb;
    auto LDG = [&](int k0) {
        xa0 = make_float4(0.f, 0.f, 0.f, 0.f); xa1 = xa0;
        if (avalid) {
            xa0 = *(const float4*)(Aptr + k0);
            xa1 = *(const float4*)(Aptr + k0 + 4);
            if (A2ptr) {
                float4 u0 = *(const float4*)(A2ptr + k0);
                float4 u1 = *(const float4*)(A2ptr + k0 + 4);
                xa0.x += u0.x; xa0.y += u0.y; xa0.z += u0.z; xa0.w += u0.w;
                xa1.x += u1.x; xa1.y += u1.y; xa1.z += u1.z; xa1.w += u1.w;
            }
        }
        yb = *(const float4*)(Wptr + (size_t)k0 * N);
    };
    auto STS = [&](int buf) {
        uint4 u0 = make_uint4(f2tf(xa0.x), f2tf(xa0.y), f2tf(xa0.z), f2tf(xa0.w));
        uint4 u1 = make_uint4(f2tf(xa1.x), f2tf(xa1.y), f2tf(xa1.z), f2tf(xa1.w));
        *(uint4*)&As[buf][am * ASTR + ak] = u0;
        *(uint4*)&As[buf][am * ASTR + ak + 4] = u1;
        uint4 v = make_uint4(f2tf(yb.x), f2tf(yb.y), f2tf(yb.z), f2tf(yb.w));
        *(uint4*)&Bs[buf][bk * BSTR + bnc] = v;
    };

    LDG(0); STS(0);
    __syncthreads();
    int buf = 0;
    for (int k0 = 16;; k0 += 16) {
        bool more = (k0 < K);
        if (more) LDG(k0);
        #pragma unroll
        for (int ks = 0; ks < 16; ks += 8) {
            unsigned af[2][4];
            #pragma unroll
            for (int mi = 0; mi < 2; mi++) {
                const unsigned* ab = &As[buf][(wm + mi * 16) * ASTR + ks];
                af[mi][0] = ab[fr * ASTR + fc];
                af[mi][1] = ab[(fr + 8) * ASTR + fc];
                af[mi][2] = ab[fr * ASTR + fc + 4];
                af[mi][3] = ab[(fr + 8) * ASTR + fc + 4];
            }
            unsigned bf[4][2];
            #pragma unroll
            for (int ni = 0; ni < 4; ni++) {
                const unsigned* bb = &Bs[buf][ks * BSTR + wn + ni * 8 + fr];
                bf[ni][0] = bb[fc * BSTR];
                bf[ni][1] = bb[(fc + 4) * BSTR];
            }
            #pragma unroll
            for (int mi = 0; mi < 2; mi++)
                #pragma unroll
                for (int ni = 0; ni < 4; ni++)
                    mma_tf32(acc[mi][ni], af[mi][0], af[mi][1], af[mi][2], af[mi][3],
                             bf[ni][0], bf[ni][1]);
        }
        if (!more) break;
        buf ^= 1;
        STS(buf);
        __syncthreads();
    }

    int c2 = fc * 2;
    #pragma unroll
    for (int ni = 0; ni < 4; ni++) {
        int n = bn + wn + ni * 8 + c2;
        float b0 = 0.f, b1 = 0.f;
        if (bias) { b0 = bias[n]; b1 = bias[n + 1]; }
        #pragma unroll
        for (int mi = 0; mi < 2; mi++) {
            float4 d = acc[mi][ni];
            int m0 = bm + wm + mi * 16 + fr;
            int m1 = m0 + 8;
            if (m0 < M) {
                float rs = rowscale ? rowscale[m0] : 1.f;
                float o0 = d.x + b0, o1 = d.y + b1;
                if (relu) { o0 = fmaxf(o0, 0.f); o1 = fmaxf(o1, 0.f); }
                *(float2*)&C[(size_t)m0 * N + n] = make_float2(o0 * rs, o1 * rs);
            }
            if (m1 < M) {
                float rs = rowscale ? rowscale[m1] : 1.f;
                float o0 = d.z + b0, o1 = d.w + b1;
                if (relu) { o0 = fmaxf(o0, 0.f); o1 = fmaxf(o1, 0.f); }
                *(float2*)&C[(size_t)m1 * N + n] = make_float2(o0 * rs, o1 * rs);
            }
        }
    }
}

__global__ void gemm_tf32_kernel(const float* __restrict__ A, const float* __restrict__ W,
                                 const float* __restrict__ bias, float* __restrict__ C,
                                 int M, int N, int K, int relu,
                                 const float* __restrict__ rowscale) {
    gemm_tf32_128(A, nullptr, W, bias, C, M, N, K, relu, rowscale,
                  blockIdx.y * 128, blockIdx.x * 64);
}

// merged QKV projection with fused residual add
__global__ void qkv_kernel(const float* __restrict__ queries, const float* __restrict__ og,
                           const float* __restrict__ Wq, const float* __restrict__ bq,
                           const float* __restrict__ Wk, const float* __restrict__ bk,
                           const float* __restrict__ Wv, const float* __restrict__ bv) {
    int z = blockIdx.z;
    const float* A2 = (z == 2) ? nullptr : og;
    const float* W = (z == 0) ? Wq : (z == 1) ? Wk : Wv;
    const float* bias = (z == 0) ? bq : (z == 1) ? bk : bv;
    float* C = (z == 0) ? g_qh : (z == 1) ? g_kh : g_vh;
    gemm_tf32_128(queries, A2, W, bias, C, NQ, DIM, DIM, 0, nullptr,
                  blockIdx.y * 128, blockIdx.x * 64);
}

// pack Woff|Wattn -> g_woa (256x128, zero-padded), boff|battn -> g_boa
__global__ void pack_woa_kernel(const float* __restrict__ Woff, const float* __restrict__ boff,
                                const float* __restrict__ Wattn, const float* __restrict__ battn) {
    int i = blockIdx.x * 256 + threadIdx.x;
    if (i < DIM * 128) {
        int r = i >> 7, c = i & 127;
        float v = 0.f;
        if (c < 64) v = Woff[r * 64 + c];
        else if (c < 96) v = Wattn[r * 32 + (c - 64)];
        g_woa[i] = v;
        if (r == 0) {
            float bvv = 0.f;
            if (c < 64) bvv = boff[c];
            else if (c < 96) bvv = battn[c - 64];
            g_boa[c] = bvv;
        }
    }
}

// offsets + attn logits in one tf32 GEMM, aug = out2 + og fused
__global__ void offproj_kernel(const float* __restrict__ og) {
    gemm_tf32_128(g_out2, og, g_woa, g_boa, g_offawl, NQ, 128, DIM, 0, nullptr,
                  blockIdx.y * 128, blockIdx.x * 64);
}

// ================= flash attention on tensor cores (q-tile 128, 256 thr) ==========
__global__ void flash_kernel(const float* __restrict__ mask) {
    int z = blockIdx.y, b = z >> 3, h = z & 7;
    int q0 = blockIdx.x * 128;
    __shared__ float    Qs[128 * 36];
    __shared__ unsigned Ks[64 * 36];    // [key][d] tf32
    __shared__ unsigned VsT[32 * 68];   // [d][key] tf32
    __shared__ float    Ms[64];
    int tid = threadIdx.x;              // 256
    int warp = tid >> 5, lane = tid & 31;
    int fr = lane >> 2, fc = lane & 3;
    const float scale = 0.17677669529663687f;  // 1/sqrt(32)

    {
        int row = tid >> 1, d0 = (tid & 1) * 16;
        int gq = q0 + row;
        float4 v[4];
        #pragma unroll
        for (int i = 0; i < 4; i++) v[i] = make_float4(0.f, 0.f, 0.f, 0.f);
        if (gq < QN) {
            const float* p = &g_qh[(size_t)(b * QN + gq) * DIM + h * HD + d0];
            #pragma unroll
            for (int i = 0; i < 4; i++) v[i] = *(const float4*)(p + i * 4);
        }
        #pragma unroll
        for (int i = 0; i < 4; i++) *(float4*)&Qs[row * 36 + d0 + i * 4] = v[i];
    }
    __syncthreads();

    unsigned aq[4][4];
    {
        int r0 = warp * 16 + fr;
        #pragma unroll
        for (int ks = 0; ks < 4; ks++) {
            aq[ks][0] = f2tf(Qs[r0 * 36 + ks * 8 + fc]);
            aq[ks][1] = f2tf(Qs[(r0 + 8) * 36 + ks * 8 + fc]);
            aq[ks][2] = f2tf(Qs[r0 * 36 + ks * 8 + fc + 4]);
            aq[ks][3] = f2tf(Qs[(r0 + 8) * 36 + ks * 8 + fc + 4]);
        }
    }

    int lk = tid >> 2, ld = (tid & 3) * 8;
    float4 pk0, pk1, pv0, pv1;
    float pm = 0.f;
    auto LOADT = [&](int k0) {
        int gk = k0 + lk;
        pk0 = make_float4(0.f,0.f,0.f,0.f); pk1 = pk0; pv0 = pk0; pv1 = pk0;
        if (gk < QN) {
            const float* kp = &g_kh[(size_t)(b * QN + gk) * DIM + h * HD + ld];
            const float* vp = &g_vh[(size_t)(b * QN + gk) * DIM + h * HD + ld];
            pk0 = *(const float4*)kp; pk1 = *(const float4*)(kp + 4);
            pv0 = *(const float4*)vp; pv1 = *(const float4*)(vp + 4);
        }
        if (tid < 64) pm = (k0 + tid < QN) ? mask[b * QN + k0 + tid] : 0.f;
    };
    auto STORET = [&]() {
        uint4 u0 = make_uint4(f2tf(pk0.x), f2tf(pk0.y), f2tf(pk0.z), f2tf(pk0.w));
        uint4 u1 = make_uint4(f2tf(pk1.x), f2tf(pk1.y), f2tf(pk1.z), f2tf(pk1.w));
        *(uint4*)&Ks[lk * 36 + ld] = u0;
        *(uint4*)&Ks[lk * 36 + ld + 4] = u1;
        VsT[(ld + 0) * 68 + lk] = f2tf(pv0.x);
        VsT[(ld + 1) * 68 + lk] = f2tf(pv0.y);
        VsT[(ld + 2) * 68 + lk] = f2tf(pv0.z);
        VsT[(ld + 3) * 68 + lk] = f2tf(pv0.w);
        VsT[(ld + 4) * 68 + lk] = f2tf(pv1.x);
        VsT[(ld + 5) * 68 + lk] = f2tf(pv1.y);
        VsT[(ld + 6) * 68 + lk] = f2tf(pv1.z);
        VsT[(ld + 7) * 68 + lk] = f2tf(pv1.w);
        if (tid < 64) Ms[tid] = pm;
    };

    float m0 = -3.0e38f, m1 = -3.0e38f, l0 = 0.f, l1 = 0.f;
    float4 o[4];
    #pragma unroll
    for (int i = 0; i < 4; i++) o[i] = make_float4(0.f, 0.f, 0.f, 0.f);

    LOADT(0); STORET(); __syncthreads();
    const int NT = (QN + 63) / 64;  // 15
    for (int t = 0; t < NT; t++) {
        int k0 = t * 64;
        bool more = (t + 1) < NT;
        if (more) LOADT(k0 + 64);

        float4 s[8];
        #pragma unroll
        for (int nt = 0; nt < 8; nt++) s[nt] = make_float4(0.f, 0.f, 0.f, 0.f);
        #pragma unroll
        for (int ks = 0; ks < 4; ks++) {
            #pragma unroll
            for (int nt = 0; nt < 8; nt++) {
                unsigned b0 = Ks[(nt * 8 + fr) * 36 + ks * 8 + fc];
                unsigned b1 = Ks[(nt * 8 + fr) * 36 + ks * 8 + fc + 4];
                mma_tf32(s[nt], aq[ks][0], aq[ks][1], aq[ks][2], aq[ks][3], b0, b1);
            }
        }

        float rm0 = -3.0e38f, rm1 = -3.0e38f;
        #pragma unroll
        for (int nt = 0; nt < 8; nt++) {
            int kx = k0 + nt * 8 + 2 * fc;
            float mx = Ms[nt * 8 + 2 * fc], my = Ms[nt * 8 + 2 * fc + 1];
            float4 v = s[nt];
            v.x = (kx     < QN) ? (mx > 0.f ? v.x * scale : -1e9f) : -1e30f;
            v.y = (kx + 1 < QN) ? (my > 0.f ? v.y * scale : -1e9f) : -1e30f;
            v.z = (kx     < QN) ? (mx > 0.f ? v.z * scale : -1e9f) : -1e30f;
            v.w = (kx + 1 < QN) ? (my > 0.f ? v.w * scale : -1e9f) : -1e30f;
            s[nt] = v;
            rm0 = fmaxf(rm0, fmaxf(v.x, v.y));
            rm1 = fmaxf(rm1, fmaxf(v.z, v.w));
        }
        rm0 = fmaxf(rm0, __shfl_xor_sync(0xffffffffu, rm0, 1));
        rm0 = fmaxf(rm0, __shfl_xor_sync(0xffffffffu, rm0, 2));
        rm1 = fmaxf(rm1, __shfl_xor_sync(0xffffffffu, rm1, 1));
        rm1 = fmaxf(rm1, __shfl_xor_sync(0xffffffffu, rm1, 2));

        float mn0 = fmaxf(m0, rm0), mn1 = fmaxf(m1, rm1);
        float f0 = __expf(m0 - mn0), f1 = __expf(m1 - mn1);
        m0 = mn0; m1 = mn1;
        #pragma unroll
        for (int i = 0; i < 4; i++) { o[i].x *= f0; o[i].y *= f0; o[i].z *= f1; o[i].w *= f1; }

        float rs0 = 0.f, rs1 = 0.f;
        #pragma unroll
        for (int nt = 0; nt < 8; nt++) {
            float4 v = s[nt];
            v.x = __expf(v.x - mn0); v.y = __expf(v.y - mn0);
            v.z = __expf(v.z - mn1); v.w = __expf(v.w - mn1);
            s[nt] = v;
            rs0 += v.x + v.y; rs1 += v.z + v.w;
        }
        rs0 += __shfl_xor_sync(0xffffffffu, rs0, 1);
        rs0 += __shfl_xor_sync(0xffffffffu, rs0, 2);
        rs1 += __shfl_xor_sync(0xffffffffu, rs1, 1);
        rs1 += __shfl_xor_sync(0xffffffffu, rs1, 2);
        l0 = l0 * f0 + rs0;
        l1 = l1 * f1 + rs1;

        int srcA = (lane & ~3) | (fc >> 1);
        int srcB = srcA | 2;
        bool odd = (fc & 1);
        #pragma unroll
        for (int ks = 0; ks < 8; ks++) {
            float4 c = s[ks];
            float y0 = __shfl_sync(0xffffffffu, c.x, srcA);
            float y1 = __shfl_sync(0xffffffffu, c.y, srcA);
            float z0 = __shfl_sync(0xffffffffu, c.x, srcB);
            float z1 = __shfl_sync(0xffffffffu, c.y, srcB);
            float y2 = __shfl_sync(0xffffffffu, c.z, srcA);
            float y3 = __shfl_sync(0xffffffffu, c.w, srcA);
            float z2 = __shfl_sync(0xffffffffu, c.z, srcB);
            float z3 = __shfl_sync(0xffffffffu, c.w, srcB);
            unsigned a0 = f2tf(odd ? y1 : y0);
            unsigned a1 = f2tf(odd ? y3 : y2);
            unsigned a2 = f2tf(odd ? z1 : z0);
            unsigned a3 = f2tf(odd ? z3 : z2);
            #pragma unroll
            for (int dt = 0; dt < 4; dt++) {
                unsigned b0 = VsT[(dt * 8 + fr) * 68 + ks * 8 + fc];
                unsigned b1 = VsT[(dt * 8 + fr) * 68 + ks * 8 + fc + 4];
                mma_tf32(o[dt], a0, a1, a2, a3, b0, b1);
            }
        }
        __syncthreads();
        if (more) { STORET(); __syncthreads(); }
    }

    float inv0 = 1.f / l0, inv1 = 1.f / l1;
    int qr0 = q0 + warp * 16 + fr;
    int qr1 = qr0 + 8;
    #pragma unroll
    for (int dt = 0; dt < 4; dt++) {
        int d = h * HD + dt * 8 + 2 * fc;
        if (qr0 < QN)
            *(float2*)&g_att[(size_t)(b * QN + qr0) * DIM + d] = make_float2(o[dt].x * inv0, o[dt].y * inv0);
        if (qr1 < QN)
            *(float2*)&g_att[(size_t)(b * QN + qr1) * DIM + d] = make_float2(o[dt].z * inv1, o[dt].w * inv1);
    }
}

// ---------------- add + layernorm v2: warp per row, 8 rows/block ----------------
__global__ void add_ln_kernel(const float* __restrict__ A, const float* __restrict__ B,
                              const float* __restrict__ g, const float* __restrict__ beta,
                              float* __restrict__ out) {
    int row = blockIdx.x * 8 + (threadIdx.x >> 5);
    int lane = threadIdx.x & 31;
    int base = row * DIM + lane * 8;
    float4 a0 = *(const float4*)&A[base];
    float4 a1 = *(const float4*)&A[base + 4];
    float4 b0 = *(const float4*)&B[base];
    float4 b1 = *(const float4*)&B[base + 4];
    float x[8] = {a0.x + b0.x, a0.y + b0.y, a0.z + b0.z, a0.w + b0.w,
                  a1.x + b1.x, a1.y + b1.y, a1.z + b1.z, a1.w + b1.w};
    float s1 = 0.f, s2 = 0.f;
    #pragma unroll
    for (int i = 0; i < 8; i++) { s1 += x[i]; s2 += x[i] * x[i]; }
    #pragma unroll
    for (int o = 16; o; o >>= 1) {
        s1 += __shfl_xor_sync(0xffffffffu, s1, o);
        s2 += __shfl_xor_sync(0xffffffffu, s2, o);
    }
    float mean = s1 * (1.f / DIM);
    float var = s2 * (1.f / DIM) - mean * mean;
    float rstd = rsqrtf(var + 1e-5f);
    float4 g0 = *(const float4*)&g[lane * 8];
    float4 g1 = *(const float4*)&g[lane * 8 + 4];
    float4 be0 = *(const float4*)&beta[lane * 8];
    float4 be1 = *(const float4*)&beta[lane * 8 + 4];
    float4 o0, o1;
    o0.x = (x[0] - mean) * rstd * g0.x + be0.x;
    o0.y = (x[1] - mean) * rstd * g0.y + be0.y;
    o0.z = (x[2] - mean) * rstd * g0.z + be0.z;
    o0.w = (x[3] - mean) * rstd * g0.w + be0.w;
    o1.x = (x[4] - mean) * rstd * g1.x + be1.x;
    o1.y = (x[5] - mean) * rstd * g1.y + be1.y;
    o1.z = (x[6] - mean) * rstd * g1.z + be1.z;
    o1.w = (x[7] - mean) * rstd * g1.w + be1.w;
    *(float4*)&out[base] = o0;
    *(float4*)&out[base + 4] = o1;
}

// ---------------- deformable gather with cell dedup ----------------
// All 8 heads x 4 points x 4 corners of one query usually hit only a few
// distinct BEV cells; dedupe and gather each distinct row once.
__global__ void deform_kernel(const float* __restrict__ bev, const float* __restrict__ ref) {
    int q = blockIdx.x, n = blockIdx.y;
    int nq = n * QN + q;
    __shared__ int   sidx[128];
    __shared__ float swt[128];
    __shared__ int   slotof[128];
    __shared__ int   cells[128];
    __shared__ float W8[128][8];
    __shared__ int   cnt;
    int tid = threadIdx.x;  // 256
    if (tid < 128) {
        int h = tid >> 4, s = tid & 15, p = s >> 2, c = s & 3;
        const float* awl = g_offawl + (size_t)nq * 128 + 64 + h * 4;
        float l0 = awl[0], l1 = awl[1], l2 = awl[2], l3 = awl[3];
        float mm = fmaxf(fmaxf(l0, l1), fmaxf(l2, l3));
        float e0 = __expf(l0 - mm), e1 = __expf(l1 - mm);
        float e2 = __expf(l2 - mm), e3 = __expf(l3 - mm);
        float es = 1.f / (e0 + e1 + e2 + e3);
        float awp = (p == 0 ? e0 : p == 1 ? e1 : p == 2 ? e2 : e3) * es;
        const float* off = g_offawl + (size_t)nq * 128 + h * 8;
        float x = ref[nq * 2 + 0] * (float)WBB + off[p * 2 + 0] - 0.5f;
        float y = ref[nq * 2 + 1] * (float)HBB + off[p * 2 + 1] - 0.5f;
        float x0f = floorf(x), y0f = floorf(y);
        float fx = x - x0f, fy = y - y0f;
        int dx = c & 1, dy = c >> 1;
        int xc = (int)x0f + dx, yc = (int)y0f + dy;
        float w = (dx ? fx : 1.f - fx) * (dy ? fy : 1.f - fy);
        bool valid = (xc >= 0) && (xc < WBB) && (yc >= 0) && (yc < HBB);
        float wf = valid ? awp * w : 0.f;
        int xcc = min(max(xc, 0), WBB - 1);
        int ycc = min(max(yc, 0), HBB - 1);
        sidx[tid] = ycc * WBB + xcc;
        swt[tid] = wf;
        float sw = wf;
        #pragma unroll
        for (int o = 1; o < 16; o <<= 1) sw += __shfl_xor_sync(0xffffffffu, sw, o);
        if (s == 0) g_sumw[nq * 8 + h] = sw;
    }
    // zero weight matrix + counter
    #pragma unroll
    for (int i = tid; i < 128 * 8; i += 256) ((float*)W8)[i] = 0.f;
    if (tid == 0) cnt = 0;
    __syncthreads();
    // leader election: first occurrence of each distinct cell index
    int f = 0;
    if (tid < 128) {
        int my = sidx[tid];
        while (sidx[f] != my) f++;
        if (f == tid) {
            int s = atomicAdd(&cnt, 1);
            slotof[tid] = s;
            cells[s] = my;
        }
    }
    __syncthreads();
    if (tid < 128) {
        atomicAdd(&W8[slotof[f]][tid >> 4], swt[tid]);
    }
    __syncthreads();
    int ncell = cnt;

    // gather: each thread covers 4 channels (c4) for 2 heads
    int sg = tid >> 6;
    int c4 = (tid & 63) << 2;
    int h0 = 2 * sg, h1 = h0 + 1;
    const float* bevn = bev + (size_t)n * (HBB * WBB) * DIM;
    float4 a0 = make_float4(0.f, 0.f, 0.f, 0.f), a1 = a0;
    for (int c = 0; c < ncell; c++) {
        float w0 = W8[c][h0], w1 = W8[c][h1];
        if (w0 != 0.f || w1 != 0.f) {
            float4 gv = *(const float4*)&bevn[(size_t)cells[c] * DIM + c4];
            a0.x += w0 * gv.x; a0.y += w0 * gv.y; a0.z += w0 * gv.z; a0.w += w0 * gv.w;
            a1.x += w1 * gv.x; a1.y += w1 * gv.y; a1.z += w1 * gv.z; a1.w += w1 * gv.w;
        }
    }
    *(float4*)&g_agg[((size_t)nq * HH + h0) * DIM + c4] = a0;
    *(float4*)&g_agg[((size_t)nq * HH + h1) * DIM + c4] = a1;
}

// ================= per-head projection on tensor cores =================
__global__ void headgemm_kernel(const float* __restrict__ Wval, const float* __restrict__ bval) {
    int h = blockIdx.y;
    int bm = blockIdx.x * 64;
    __shared__ unsigned As[2][64 * ASTR];
    __shared__ unsigned Bs[2][16 * 36];
    int tid = threadIdx.x;          // 128
    int warp = tid >> 5, lane = tid & 31;
    int fr = lane >> 2, fc = lane & 3;
    float4 acc[4];
    #pragma unroll
    for (int i = 0; i < 4; i++) acc[i] = make_float4(0.f, 0.f, 0.f, 0.f);

    int am = tid >> 1;
    int ak = (tid & 1) * 8;
    bool avalid = (bm + am) < NQ;
    const float* Aptr = g_agg + ((size_t)(bm + am) * HH + h) * DIM + ak;
    int bk = tid >> 3;              // 0..15
    int bn4 = (tid & 7) * 4;
    const float* Wptr = Wval + (size_t)bk * DIM + h * HD + bn4;

    float4 xa0, xa1, yb;
    auto LDG = [&](int k0) {
        xa0 = make_float4(0.f, 0.f, 0.f, 0.f); xa1 = xa0;
        if (avalid) { xa0 = *(const float4*)(Aptr + k0); xa1 = *(const float4*)(Aptr + k0 + 4); }
        yb = *(const float4*)(Wptr + (size_t)k0 * DIM);
    };
    auto STS = [&](int buf) {
        uint4 u0 = make_uint4(f2tf(xa0.x), f2tf(xa0.y), f2tf(xa0.z), f2tf(xa0.w));
        uint4 u1 = make_uint4(f2tf(xa1.x), f2tf(xa1.y), f2tf(xa1.z), f2tf(xa1.w));
        *(uint4*)&As[buf][am * ASTR + ak] = u0;
        *(uint4*)&As[buf][am * ASTR + ak + 4] = u1;
        uint4 v = make_uint4(f2tf(yb.x), f2tf(yb.y), f2tf(yb.z), f2tf(yb.w));
        *(uint4*)&Bs[buf][bk * 36 + bn4] = v;
    };

    LDG(0); STS(0);
    __syncthreads();
    int buf = 0;
    for (int k0 = 16;; k0 += 16) {
        bool more = (k0 < DIM);
        if (more) LDG(k0);
        #pragma unroll
        for (int ks = 0; ks < 16; ks += 8) {
            const unsigned* ab = &As[buf][(warp * 16) * ASTR + ks];
            unsigned a0 = ab[fr * ASTR + fc];
            unsigned a1 = ab[(fr + 8) * ASTR + fc];
            unsigned a2 = ab[fr * ASTR + fc + 4];
            unsigned a3 = ab[(fr + 8) * ASTR + fc + 4];
            #pragma unroll
            for (int nt = 0; nt < 4; nt++) {
                unsigned b0 = Bs[buf][(ks + fc) * 36 + nt * 8 + fr];
                unsigned b1 = Bs[buf][(ks + fc + 4) * 36 + nt * 8 + fr];
                mma_tf32(acc[nt], a0, a1, a2, a3, b0, b1);
            }
        }
        if (!more) break;
        buf ^= 1;
        STS(buf);
        __syncthreads();
    }

    int m0 = bm + warp * 16 + fr;
    int m1 = m0 + 8;
    #pragma unroll
    for (int nt = 0; nt < 4; nt++) {
        int c = nt * 8 + 2 * fc;
        float bv0 = bval[h * HD + c], bv1 = bval[h * HD + c + 1];
        if (m0 < NQ) {
            float sw = g_sumw[m0 * HH + h];
            *(float2*)&g_ho[(size_t)m0 * DIM + h * HD + c] =
                make_float2(acc[nt].x + bv0 * sw, acc[nt].y + bv1 * sw);
        }
        if (m1 < NQ) {
            float sw = g_sumw[m1 * HH + h];
            *(float2*)&g_ho[(size_t)m1 * DIM + h * HD + c] =
                make_float2(acc[nt].z + bv0 * sw, acc[nt].w + bv1 * sw);
        }
    }
}

// ---------------- launch ----------------
static float* symaddr(const void* s) {
    void* p = nullptr;
    cudaGetSymbolAddress(&p, s);
    return (float*)p;
}

extern "C" void kernel_launch(void* const* d_in, const int* in_sizes, int n_in,
                              void* d_out, int out_size) {
    const float* queries = (const float*)d_in[0];
    const float* bev     = (const float*)d_in[1];
    const float* refp    = (const float*)d_in[2];
    const float* og      = (const float*)d_in[3];
    const float* mask    = (const float*)d_in[4];
    const float* Wq = (const float*)d_in[5];  const float* bq = (const float*)d_in[6];
    const float* Wk = (const float*)d_in[7];  const float* bk = (const float*)d_in[8];
    const float* Wv = (const float*)d_in[9];  const float* bv = (const float*)d_in[10];
    const float* Wo = (const float*)d_in[11]; const float* bo = (const float*)d_in[12];
    const float* ln1g = (const float*)d_in[13]; const float* ln1b = (const float*)d_in[14];
    const float* Wval = (const float*)d_in[15]; const float* bval = (const float*)d_in[16];
    const float* Woff = (const float*)d_in[17]; const float* boff = (const float*)d_in[18];
    const float* Wattn = (const float*)d_in[19]; const float* battn = (const float*)d_in[20];
    const float* Wdo = (const float*)d_in[21]; const float* bdo = (const float*)d_in[22];
    const float* ln2g = (const float*)d_in[23]; const float* ln2b = (const float*)d_in[24];
    const float* W1 = (const float*)d_in[25]; const float* b1 = (const float*)d_in[26];
    const float* W2 = (const float*)d_in[27]; const float* b2 = (const float*)d_in[28];
    const float* ln3g = (const float*)d_in[29]; const float* ln3b = (const float*)d_in[30];
    float* out = (float*)d_out;

    float* patt = symaddr(g_att);
    float* pout1 = symaddr(g_out1);
    float* pout2 = symaddr(g_out2);
    float* pho  = symaddr(g_ho);
    float* pout3 = symaddr(g_out3);
    float* pout4 = symaddr(g_out4);
    float* pffn = symaddr(g_ffn);
    float* pout5 = symaddr(g_out5);

    // pack the deform projection weights (independent; runs early)
    pack_woa_kernel<<<128, 256>>>(Woff, boff, Wattn, battn);
    // 1. QKV projections with fused q_and_k = queries + og
    qkv_kernel<<<dim3(4, 29, 3), 256>>>(queries, og, Wq, bq, Wk, bk, Wv, bv);
    // 2. flash attention (tf32 tensor cores)
    flash_kernel<<<dim3(8, NZ), 256>>>(mask);
    // 3. output projection + LN1
    gemm_tf32_kernel<<<dim3(4, 29), 256>>>(patt, Wo, bo, pout1, NQ, DIM, DIM, 0, nullptr);
    add_ln_kernel<<<NQ / 8, 256>>>(queries, pout1, ln1g, ln1b, pout2);
    // 4. deformable attention (offset+logit proj fused w/ aug add; dedup gather)
    offproj_kernel<<<dim3(2, 29), 256>>>(og);
    deform_kernel<<<dim3(QN, NB), 256>>>(bev, refp);
    headgemm_kernel<<<dim3(57, HH), 128>>>(Wval, bval);
    gemm_tf32_kernel<<<dim3(4, 29), 256>>>(pho, Wdo, bdo, pout3, NQ, DIM, DIM, 0, mask);
    add_ln_kernel<<<NQ / 8, 256>>>(pout2, pout3, ln2g, ln2b, pout4);
    // 5. FFN + LN3
    gemm_tf32_kernel<<<dim3(8, 29), 256>>>(pout4, W1, b1, pffn, NQ, FFD, DIM, 1, nullptr);
    gemm_tf32_kernel<<<dim3(4, 29), 256>>>(pffn, W2, b2, pout5, NQ, DIM, FFD, 0, nullptr);
    add_ln_kernel<<<NQ / 8, 256>>>(pout4, pout5, ln3g, ln3b, out);
}